// round 1
// baseline (speedup 1.0000x reference)
#include <cuda_runtime.h>
#include <math.h>

#define BATCH 2
#define SEQ   2048
#define DIM   1024
#define NH    16
#define HD    64
#define NTOK  (BATCH * SEQ)   // 4096

// ---------------- scratch (device globals; no allocation allowed) ----------
__device__ float g_h  [(size_t)NTOK * DIM];        // LN output (reused for ln1/ln2)
__device__ float g_qkv[(size_t)NTOK * 3 * DIM];    // qkv
__device__ float g_y  [(size_t)NTOK * DIM];        // attention output
__device__ float g_x1 [(size_t)NTOK * DIM];        // residual after proj
__device__ float g_act[(size_t)NTOK * 4 * DIM];    // relu(fc) activations

// ---------------- LayerNorm: one block per row of 1024 --------------------
__global__ __launch_bounds__(256) void ln_kernel(
    const float* __restrict__ x, const float* __restrict__ gamma,
    const float* __restrict__ beta, float* __restrict__ out)
{
    int row = blockIdx.x;
    int tid = threadIdx.x;                    // 256 threads, 4 floats each
    const float4* xr = reinterpret_cast<const float4*>(x + (size_t)row * DIM);
    float4 v = xr[tid];
    float s1 = v.x + v.y + v.z + v.w;
    float s2 = v.x * v.x + v.y * v.y + v.z * v.z + v.w * v.w;
    #pragma unroll
    for (int o = 16; o > 0; o >>= 1) {
        s1 += __shfl_xor_sync(0xffffffffu, s1, o);
        s2 += __shfl_xor_sync(0xffffffffu, s2, o);
    }
    __shared__ float sh1[8], sh2[8];
    int w = tid >> 5, l = tid & 31;
    if (l == 0) { sh1[w] = s1; sh2[w] = s2; }
    __syncthreads();
    s1 = 0.f; s2 = 0.f;
    #pragma unroll
    for (int i = 0; i < 8; i++) { s1 += sh1[i]; s2 += sh2[i]; }
    float mu  = s1 * (1.0f / DIM);
    float var = s2 * (1.0f / DIM) - mu * mu;
    float r   = rsqrtf(var + 1e-5f);
    float4 gv = reinterpret_cast<const float4*>(gamma)[tid];
    float4 bv = reinterpret_cast<const float4*>(beta)[tid];
    float4 o;
    o.x = (v.x - mu) * r * gv.x + bv.x;
    o.y = (v.y - mu) * r * gv.y + bv.y;
    o.z = (v.z - mu) * r * gv.z + bv.z;
    o.w = (v.w - mu) * r * gv.w + bv.w;
    reinterpret_cast<float4*>(out + (size_t)row * DIM)[tid] = o;
}

// ---------------- 128x128x16 fp32 tiled GEMM ------------------------------
// C[M,N] = A[M,K] @ B[K,N] + bias  (+ res)  (+ relu)
// M % 128 == 0, N % 128 == 0, K % 16 == 0 (true for all shapes here).
template<bool RELU, bool RES>
__global__ __launch_bounds__(256) void gemm128(
    const float* __restrict__ A, const float* __restrict__ B,
    const float* __restrict__ bias, const float* __restrict__ res,
    float* __restrict__ C, int M, int N, int K)
{
    const int BM = 128, BN = 128, BK = 16;
    __shared__ float As[BK][BM];   // transposed A tile: As[k][m]
    __shared__ float Bs[BK][BN];

    int tid = threadIdx.x;
    int tx = tid & 15, ty = tid >> 4;
    int row0 = blockIdx.y * BM, col0 = blockIdx.x * BN;

    float acc[2][2][4][4];
    #pragma unroll
    for (int a = 0; a < 2; a++)
        #pragma unroll
        for (int b = 0; b < 2; b++)
            #pragma unroll
            for (int i = 0; i < 4; i++)
                #pragma unroll
                for (int j = 0; j < 4; j++) acc[a][b][i][j] = 0.f;

    int arow = tid >> 2;           // 0..63
    int acol = (tid & 3) << 2;     // 0,4,8,12
    int brow = tid >> 5;           // 0..7
    int bcol = (tid & 31) << 2;    // 0..124

    for (int k0 = 0; k0 < K; k0 += BK) {
        #pragma unroll
        for (int r = 0; r < 2; r++) {
            float4 a = *reinterpret_cast<const float4*>(
                A + (size_t)(row0 + arow + r * 64) * K + k0 + acol);
            As[acol + 0][arow + r * 64] = a.x;
            As[acol + 1][arow + r * 64] = a.y;
            As[acol + 2][arow + r * 64] = a.z;
            As[acol + 3][arow + r * 64] = a.w;
        }
        #pragma unroll
        for (int r = 0; r < 2; r++) {
            float4 b = *reinterpret_cast<const float4*>(
                B + (size_t)(k0 + brow + r * 8) * N + col0 + bcol);
            *reinterpret_cast<float4*>(&Bs[brow + r * 8][bcol]) = b;
        }
        __syncthreads();
        #pragma unroll
        for (int kk = 0; kk < BK; kk++) {
            float4 a0 = *reinterpret_cast<const float4*>(&As[kk][ty * 4]);
            float4 a1 = *reinterpret_cast<const float4*>(&As[kk][ty * 4 + 64]);
            float4 b0 = *reinterpret_cast<const float4*>(&Bs[kk][tx * 4]);
            float4 b1 = *reinterpret_cast<const float4*>(&Bs[kk][tx * 4 + 64]);
            float ar[2][4] = {{a0.x, a0.y, a0.z, a0.w}, {a1.x, a1.y, a1.z, a1.w}};
            float br[2][4] = {{b0.x, b0.y, b0.z, b0.w}, {b1.x, b1.y, b1.z, b1.w}};
            #pragma unroll
            for (int rr = 0; rr < 2; rr++)
                #pragma unroll
                for (int i = 0; i < 4; i++)
                    #pragma unroll
                    for (int cc = 0; cc < 2; cc++)
                        #pragma unroll
                        for (int j = 0; j < 4; j++)
                            acc[rr][cc][i][j] += ar[rr][i] * br[cc][j];
        }
        __syncthreads();
    }

    #pragma unroll
    for (int rr = 0; rr < 2; rr++) {
        #pragma unroll
        for (int i = 0; i < 4; i++) {
            int row = row0 + rr * 64 + ty * 4 + i;
            #pragma unroll
            for (int cc = 0; cc < 2; cc++) {
                int col = col0 + cc * 64 + tx * 4;
                float4 bb = *reinterpret_cast<const float4*>(bias + col);
                float4 o;
                o.x = acc[rr][cc][i][0] + bb.x;
                o.y = acc[rr][cc][i][1] + bb.y;
                o.z = acc[rr][cc][i][2] + bb.z;
                o.w = acc[rr][cc][i][3] + bb.w;
                if (RES) {
                    float4 rv = *reinterpret_cast<const float4*>(
                        res + (size_t)row * N + col);
                    o.x += rv.x; o.y += rv.y; o.z += rv.z; o.w += rv.w;
                }
                if (RELU) {
                    o.x = fmaxf(o.x, 0.f); o.y = fmaxf(o.y, 0.f);
                    o.z = fmaxf(o.z, 0.f); o.w = fmaxf(o.w, 0.f);
                }
                *reinterpret_cast<float4*>(C + (size_t)row * N + col) = o;
            }
        }
    }
}

// ---------------- causal flash attention ----------------------------------
// grid: (SEQ/128, NH, BATCH), 128 threads. Each thread owns one query row.
__global__ __launch_bounds__(128) void attn_kernel(
    const float* __restrict__ qkv, float* __restrict__ y)
{
    int qt = blockIdx.x, h = blockIdx.y, b = blockIdx.z;
    int tid = threadIdx.x;
    int q_idx = qt * 128 + tid;

    const float* base = qkv + (size_t)b * SEQ * 3 * DIM;

    float qreg[HD];
    {
        const float4* qr = reinterpret_cast<const float4*>(
            base + (size_t)q_idx * 3 * DIM + h * HD);
        #pragma unroll
        for (int dd = 0; dd < HD / 4; dd++) {
            float4 v = qr[dd];
            qreg[4 * dd + 0] = v.x * 0.125f;   // 1/sqrt(64)
            qreg[4 * dd + 1] = v.y * 0.125f;
            qreg[4 * dd + 2] = v.z * 0.125f;
            qreg[4 * dd + 3] = v.w * 0.125f;
        }
    }

    float m = -INFINITY, l = 0.f;
    float acc[HD];
    #pragma unroll
    for (int d = 0; d < HD; d++) acc[d] = 0.f;

    __shared__ float Ks[64][HD];
    __shared__ float Vs[64][HD];

    int jlast = qt * 128 + 127;           // max key needed by this block
    for (int j0 = 0; j0 <= jlast; j0 += 64) {
        __syncthreads();
        for (int i = tid; i < 64 * HD; i += 128) {
            int jr = i >> 6, d = i & 63;
            size_t roff = (size_t)(j0 + jr) * 3 * DIM + h * HD + d;
            Ks[jr][d] = base[roff + DIM];
            Vs[jr][d] = base[roff + 2 * DIM];
        }
        __syncthreads();

        int jend = q_idx - j0 + 1;        // #valid keys for this thread
        if (jend > 64) jend = 64;
        for (int j = 0; j < jend; j++) {
            const float4* K4 = reinterpret_cast<const float4*>(Ks[j]);
            float s0 = 0.f, s1 = 0.f, s2 = 0.f, s3 = 0.f;
            #pragma unroll
            for (int dd = 0; dd < 16; dd++) {
                float4 kv = K4[dd];
                s0 += qreg[4 * dd + 0] * kv.x;
                s1 += qreg[4 * dd + 1] * kv.y;
                s2 += qreg[4 * dd + 2] * kv.z;
                s3 += qreg[4 * dd + 3] * kv.w;
            }
            float s = (s0 + s1) + (s2 + s3);
            float p;
            if (s > m) {
                float f = __expf(m - s);
                l *= f;
                #pragma unroll
                for (int d = 0; d < HD; d++) acc[d] *= f;
                m = s;
                p = 1.f;
            } else {
                p = __expf(s - m);
            }
            l += p;
            const float4* V4 = reinterpret_cast<const float4*>(Vs[j]);
            #pragma unroll
            for (int dd = 0; dd < 16; dd++) {
                float4 vv = V4[dd];
                acc[4 * dd + 0] += p * vv.x;
                acc[4 * dd + 1] += p * vv.y;
                acc[4 * dd + 2] += p * vv.z;
                acc[4 * dd + 3] += p * vv.w;
            }
        }
    }

    float inv_l = 1.0f / l;
    float4* yo = reinterpret_cast<float4*>(
        y + ((size_t)b * SEQ + q_idx) * DIM + h * HD);
    #pragma unroll
    for (int dd = 0; dd < HD / 4; dd++) {
        float4 o;
        o.x = acc[4 * dd + 0] * inv_l;
        o.y = acc[4 * dd + 1] * inv_l;
        o.z = acc[4 * dd + 2] * inv_l;
        o.w = acc[4 * dd + 3] * inv_l;
        yo[dd] = o;
    }
}

// ---------------- launch ---------------------------------------------------
extern "C" void kernel_launch(void* const* d_in, const int* in_sizes, int n_in,
                              void* d_out, int out_size)
{
    const float* x      = (const float*)d_in[0];
    const float* ln1_g  = (const float*)d_in[1];
    const float* ln1_b  = (const float*)d_in[2];
    const float* ln2_g  = (const float*)d_in[3];
    const float* ln2_b  = (const float*)d_in[4];
    const float* W_qkv  = (const float*)d_in[5];
    const float* b_qkv  = (const float*)d_in[6];
    const float* W_proj = (const float*)d_in[7];
    const float* b_proj = (const float*)d_in[8];
    const float* W_fc   = (const float*)d_in[9];
    const float* b_fc   = (const float*)d_in[10];
    const float* W_out  = (const float*)d_in[11];
    const float* b_out  = (const float*)d_in[12];
    float* out = (float*)d_out;

    float *h, *qkv, *y, *x1, *act;
    cudaGetSymbolAddress((void**)&h,   g_h);
    cudaGetSymbolAddress((void**)&qkv, g_qkv);
    cudaGetSymbolAddress((void**)&y,   g_y);
    cudaGetSymbolAddress((void**)&x1,  g_x1);
    cudaGetSymbolAddress((void**)&act, g_act);

    // 1) h = LN1(x)
    ln_kernel<<<NTOK, 256>>>(x, ln1_g, ln1_b, h);
    // 2) qkv = h @ W_qkv + b_qkv
    gemm128<false, false><<<dim3(3 * DIM / 128, NTOK / 128), 256>>>(
        h, W_qkv, b_qkv, nullptr, qkv, NTOK, 3 * DIM, DIM);
    // 3) y = causal_attention(qkv)
    attn_kernel<<<dim3(SEQ / 128, NH, BATCH), 128>>>(qkv, y);
    // 4) x1 = x + y @ W_proj + b_proj
    gemm128<false, true><<<dim3(DIM / 128, NTOK / 128), 256>>>(
        y, W_proj, b_proj, x, x1, NTOK, DIM, DIM);
    // 5) h = LN2(x1)
    ln_kernel<<<NTOK, 256>>>(x1, ln2_g, ln2_b, h);
    // 6) act = relu(h @ W_fc + b_fc)
    gemm128<true, false><<<dim3(4 * DIM / 128, NTOK / 128), 256>>>(
        h, W_fc, b_fc, nullptr, act, NTOK, 4 * DIM, DIM);
    // 7) out = x1 + act @ W_out + b_out
    gemm128<false, true><<<dim3(DIM / 128, NTOK / 128), 256>>>(
        act, W_out, b_out, x1, out, NTOK, DIM, 4 * DIM);
}

// round 3
// speedup vs baseline: 1.7699x; 1.7699x over previous
#include <cuda_runtime.h>
#include <cuda_bf16.h>
#include <math.h>
#include <stdint.h>

#define BATCH 2
#define SEQ   2048
#define DIM   1024
#define NH    16
#define HD    64
#define NTOK  (BATCH * SEQ)   // 4096

// ---------------- scratch (device globals; no allocation allowed) ----------
__device__ float g_h  [(size_t)NTOK * DIM];
__device__ float g_qkv[(size_t)NTOK * 3 * DIM];
__device__ float g_y  [(size_t)NTOK * DIM];
__device__ float g_x1 [(size_t)NTOK * DIM];
__device__ float g_act[(size_t)NTOK * 4 * DIM];

__device__ __nv_bfloat16 g_ah[(size_t)NTOK * 4 * DIM];
__device__ __nv_bfloat16 g_al[(size_t)NTOK * 4 * DIM];
__device__ __nv_bfloat16 g_bh[(size_t)4 * DIM * DIM];
__device__ __nv_bfloat16 g_bl[(size_t)4 * DIM * DIM];

// ======================= helpers ===========================================
__device__ __forceinline__ uint32_t smem_u32(const void* p) {
    uint32_t a;
    asm("{ .reg .u64 t; cvta.to.shared.u64 t, %1; cvt.u32.u64 %0, t; }"
        : "=r"(a) : "l"(p));
    return a;
}
#define SWZ128(o) ((o) ^ (((o) >> 3) & 0x70))

__device__ __forceinline__ void ldsm_x4(uint32_t* r, uint32_t addr) {
    asm volatile("ldmatrix.sync.aligned.m8n8.x4.shared.b16 {%0,%1,%2,%3}, [%4];"
                 : "=r"(r[0]), "=r"(r[1]), "=r"(r[2]), "=r"(r[3]) : "r"(addr));
}
__device__ __forceinline__ void ldsm_x2(uint32_t* r, uint32_t addr) {
    asm volatile("ldmatrix.sync.aligned.m8n8.x2.shared.b16 {%0,%1}, [%2];"
                 : "=r"(r[0]), "=r"(r[1]) : "r"(addr));
}
__device__ __forceinline__ void mma_bf16(float* c, const uint32_t* a,
                                         const uint32_t* b) {
    asm volatile(
        "mma.sync.aligned.m16n8k16.row.col.f32.bf16.bf16.f32 "
        "{%0,%1,%2,%3}, {%4,%5,%6,%7}, {%8,%9}, {%0,%1,%2,%3};"
        : "+f"(c[0]), "+f"(c[1]), "+f"(c[2]), "+f"(c[3])
        : "r"(a[0]), "r"(a[1]), "r"(a[2]), "r"(a[3]), "r"(b[0]), "r"(b[1]));
}
__device__ __forceinline__ void cp16(uint32_t daddr, const void* saddr) {
    asm volatile("cp.async.cg.shared.global [%0], [%1], 16;"
                 :: "r"(daddr), "l"(saddr));
}

// ---------------- LayerNorm ------------------------------------------------
__global__ __launch_bounds__(256) void ln_kernel(
    const float* __restrict__ x, const float* __restrict__ gamma,
    const float* __restrict__ beta, float* __restrict__ out)
{
    int row = blockIdx.x;
    int tid = threadIdx.x;
    const float4* xr = reinterpret_cast<const float4*>(x + (size_t)row * DIM);
    float4 v = xr[tid];
    float s1 = v.x + v.y + v.z + v.w;
    float s2 = v.x * v.x + v.y * v.y + v.z * v.z + v.w * v.w;
    #pragma unroll
    for (int o = 16; o > 0; o >>= 1) {
        s1 += __shfl_xor_sync(0xffffffffu, s1, o);
        s2 += __shfl_xor_sync(0xffffffffu, s2, o);
    }
    __shared__ float sh1[8], sh2[8];
    int w = tid >> 5, l = tid & 31;
    if (l == 0) { sh1[w] = s1; sh2[w] = s2; }
    __syncthreads();
    s1 = 0.f; s2 = 0.f;
    #pragma unroll
    for (int i = 0; i < 8; i++) { s1 += sh1[i]; s2 += sh2[i]; }
    float mu  = s1 * (1.0f / DIM);
    float var = s2 * (1.0f / DIM) - mu * mu;
    float r   = rsqrtf(var + 1e-5f);
    float4 gv = reinterpret_cast<const float4*>(gamma)[tid];
    float4 bv = reinterpret_cast<const float4*>(beta)[tid];
    float4 o;
    o.x = (v.x - mu) * r * gv.x + bv.x;
    o.y = (v.y - mu) * r * gv.y + bv.y;
    o.z = (v.z - mu) * r * gv.z + bv.z;
    o.w = (v.w - mu) * r * gv.w + bv.w;
    reinterpret_cast<float4*>(out + (size_t)row * DIM)[tid] = o;
}

// ---------------- split fp32 -> bf16 hi/lo (row-major) ---------------------
__global__ __launch_bounds__(256) void split_kernel(
    const float* __restrict__ in, __nv_bfloat16* __restrict__ hi,
    __nv_bfloat16* __restrict__ lo, int n4)
{
    int i = blockIdx.x * 256 + threadIdx.x;
    if (i >= n4) return;
    float4 v = reinterpret_cast<const float4*>(in)[i];
    __nv_bfloat16 h0 = __float2bfloat16(v.x);
    __nv_bfloat16 h1 = __float2bfloat16(v.y);
    __nv_bfloat16 h2 = __float2bfloat16(v.z);
    __nv_bfloat16 h3 = __float2bfloat16(v.w);
    __nv_bfloat16 l0 = __float2bfloat16(v.x - __bfloat162float(h0));
    __nv_bfloat16 l1 = __float2bfloat16(v.y - __bfloat162float(h1));
    __nv_bfloat16 l2 = __float2bfloat16(v.z - __bfloat162float(h2));
    __nv_bfloat16 l3 = __float2bfloat16(v.w - __bfloat162float(h3));
    __nv_bfloat162* hp = reinterpret_cast<__nv_bfloat162*>(hi);
    __nv_bfloat162* lp = reinterpret_cast<__nv_bfloat162*>(lo);
    hp[2 * i + 0] = __nv_bfloat162(h0, h1);
    hp[2 * i + 1] = __nv_bfloat162(h2, h3);
    lp[2 * i + 0] = __nv_bfloat162(l0, l1);
    lp[2 * i + 1] = __nv_bfloat162(l2, l3);
}

// ---------------- split + transpose: in [R,C] fp32 -> out [C,R] bf16 -------
__global__ __launch_bounds__(256) void splitT_kernel(
    const float* __restrict__ in, __nv_bfloat16* __restrict__ hi,
    __nv_bfloat16* __restrict__ lo, int R, int C)
{
    __shared__ float t[32][33];
    int tx = threadIdx.x, ty = threadIdx.y;   // block (32,8)
    int x = blockIdx.x * 32 + tx;
    #pragma unroll
    for (int j = 0; j < 32; j += 8)
        t[ty + j][tx] = in[(size_t)(blockIdx.y * 32 + ty + j) * C + x];
    __syncthreads();
    #pragma unroll
    for (int j = 0; j < 32; j += 8) {
        float v = t[tx][ty + j];
        __nv_bfloat16 h = __float2bfloat16(v);
        __nv_bfloat16 l = __float2bfloat16(v - __bfloat162float(h));
        size_t idx = (size_t)(blockIdx.x * 32 + ty + j) * R + blockIdx.y * 32 + tx;
        hi[idx] = h;
        lo[idx] = l;
    }
}

// ---------------- mma.sync split-bf16 GEMM ---------------------------------
// C[M,N] = A[M,K] @ B[K,N] + bias (+res)(+relu), A/B pre-split to bf16 hi/lo.
// Ah/Al: [M,K] row-major; Bh/Bl: [N,K] row-major (i.e. B^T).
// CTA tile 128x128, BK=64, 8 warps (2 m x 4 n), warp tile 64x32.
#define STAGE_BYTES 65536
#define GEMM_SMEM   (2 * STAGE_BYTES)

template<bool RELU, bool RES>
__global__ __launch_bounds__(256) void gemm_mma(
    const __nv_bfloat16* __restrict__ Ah, const __nv_bfloat16* __restrict__ Al,
    const __nv_bfloat16* __restrict__ Bh, const __nv_bfloat16* __restrict__ Bl,
    const float* __restrict__ bias, const float* __restrict__ res,
    float* __restrict__ C, int M, int N, int K)
{
    extern __shared__ char smem[];
    const int tid = threadIdx.x;
    const int wid = tid >> 5, lane = tid & 31;
    const int m0 = blockIdx.y * 128, n0 = blockIdx.x * 128;
    const int wm = (wid & 1) * 64;     // warp m offset in tile
    const int wn = (wid >> 1) * 32;    // warp n offset in tile

    float acc[4][4][4];
    #pragma unroll
    for (int a = 0; a < 4; a++)
        #pragma unroll
        for (int b = 0; b < 4; b++)
            #pragma unroll
            for (int c = 0; c < 4; c++) acc[a][b][c] = 0.f;

    const __nv_bfloat16* srcs[4] = {
        Ah + (size_t)m0 * K, Al + (size_t)m0 * K,
        Bh + (size_t)n0 * K, Bl + (size_t)n0 * K };

    const int row_l = tid >> 3;       // 0..31 (rows per pass of 32)
    const int c_l   = tid & 7;        // 16B chunk within 128B row

    auto issue_stage = [&](int i) {
        int k0 = i << 6;
        char* st = smem + (size_t)(i & 1) * STAGE_BYTES;
        #pragma unroll
        for (int t = 0; t < 4; t++) {
            char* dst = st + t * 16384;
            const __nv_bfloat16* src = srcs[t] + k0;
            #pragma unroll
            for (int p = 0; p < 4; p++) {
                int row = row_l + p * 32;
                uint32_t doff = SWZ128((uint32_t)(row * 128 + c_l * 16));
                cp16(smem_u32(dst + doff), src + (size_t)row * K + c_l * 8);
            }
        }
        asm volatile("cp.async.commit_group;" ::: "memory");
    };

    const int NC = K >> 6;
    issue_stage(0);
    for (int i = 0; i < NC; i++) {
        if (i + 1 < NC) {
            issue_stage(i + 1);
            asm volatile("cp.async.wait_group 1;" ::: "memory");
        } else {
            asm volatile("cp.async.wait_group 0;" ::: "memory");
        }
        __syncthreads();

        char* st = smem + (size_t)(i & 1) * STAGE_BYTES;
        uint32_t sAh = smem_u32(st);
        uint32_t sAl = sAh + 16384;
        uint32_t sBh = sAh + 32768;
        uint32_t sBl = sAh + 49152;

        #pragma unroll
        for (int ks = 0; ks < 4; ks++) {
            int k16 = ks * 16;
            uint32_t ah[4][4], al[4][4];
            #pragma unroll
            for (int mi = 0; mi < 4; mi++) {
                int row = wm + mi * 16 + (lane & 15);
                int col = k16 + (lane >> 4) * 8;
                uint32_t off = SWZ128((uint32_t)(row * 128 + col * 2));
                ldsm_x4(ah[mi], sAh + off);
                ldsm_x4(al[mi], sAl + off);
            }
            uint32_t bh[4][2], bl[4][2];
            #pragma unroll
            for (int ni = 0; ni < 4; ni++) {
                int row = wn + ni * 8 + (lane & 7);
                int col = k16 + ((lane >> 3) & 1) * 8;
                uint32_t off = SWZ128((uint32_t)(row * 128 + col * 2));
                ldsm_x2(bh[ni], sBh + off);
                ldsm_x2(bl[ni], sBl + off);
            }
            #pragma unroll
            for (int mi = 0; mi < 4; mi++)
                #pragma unroll
                for (int ni = 0; ni < 4; ni++) {
                    mma_bf16(acc[mi][ni], ah[mi], bh[ni]);
                    mma_bf16(acc[mi][ni], ah[mi], bl[ni]);
                    mma_bf16(acc[mi][ni], al[mi], bh[ni]);
                }
        }
        __syncthreads();
    }

    // epilogue: frag (mi,ni): rows m0+wm+mi*16+{lane/4, +8}, cols n0+wn+ni*8+2*(lane%4)
    #pragma unroll
    for (int mi = 0; mi < 4; mi++) {
        #pragma unroll
        for (int h = 0; h < 2; h++) {
            int row = m0 + wm + mi * 16 + (lane >> 2) + h * 8;
            float* crow = C + (size_t)row * N;
            const float* rrow = RES ? res + (size_t)row * N : nullptr;
            #pragma unroll
            for (int ni = 0; ni < 4; ni++) {
                int col = n0 + wn + ni * 8 + (lane & 3) * 2;
                float2 bb = *reinterpret_cast<const float2*>(bias + col);
                float vx = acc[mi][ni][h * 2 + 0] + bb.x;
                float vy = acc[mi][ni][h * 2 + 1] + bb.y;
                if (RES) {
                    float2 rv = *reinterpret_cast<const float2*>(rrow + col);
                    vx += rv.x; vy += rv.y;
                }
                if (RELU) { vx = fmaxf(vx, 0.f); vy = fmaxf(vy, 0.f); }
                *reinterpret_cast<float2*>(crow + col) = make_float2(vx, vy);
            }
        }
    }
}

// ---------------- causal flash attention -----------------------------------
__global__ __launch_bounds__(128) void attn_kernel(
    const float* __restrict__ qkv, float* __restrict__ y)
{
    int qt = blockIdx.x, h = blockIdx.y, b = blockIdx.z;
    int tid = threadIdx.x;
    int q_idx = qt * 128 + tid;

    const float* base = qkv + (size_t)b * SEQ * 3 * DIM;

    float qreg[HD];
    {
        const float4* qr = reinterpret_cast<const float4*>(
            base + (size_t)q_idx * 3 * DIM + h * HD);
        #pragma unroll
        for (int dd = 0; dd < HD / 4; dd++) {
            float4 v = qr[dd];
            qreg[4 * dd + 0] = v.x * 0.125f;
            qreg[4 * dd + 1] = v.y * 0.125f;
            qreg[4 * dd + 2] = v.z * 0.125f;
            qreg[4 * dd + 3] = v.w * 0.125f;
        }
    }

    float m = -INFINITY, l = 0.f;
    float acc[HD];
    #pragma unroll
    for (int d = 0; d < HD; d++) acc[d] = 0.f;

    __shared__ float Ks[64][HD];
    __shared__ float Vs[64][HD];

    int jlast = qt * 128 + 127;
    for (int j0 = 0; j0 <= jlast; j0 += 64) {
        __syncthreads();
        for (int i = tid; i < 64 * HD; i += 128) {
            int jr = i >> 6, d = i & 63;
            size_t roff = (size_t)(j0 + jr) * 3 * DIM + h * HD + d;
            Ks[jr][d] = base[roff + DIM];
            Vs[jr][d] = base[roff + 2 * DIM];
        }
        __syncthreads();

        int jend = q_idx - j0 + 1;
        if (jend > 64) jend = 64;
        for (int j = 0; j < jend; j++) {
            const float4* K4 = reinterpret_cast<const float4*>(Ks[j]);
            float s0 = 0.f, s1 = 0.f, s2 = 0.f, s3 = 0.f;
            #pragma unroll
            for (int dd = 0; dd < 16; dd++) {
                float4 kv = K4[dd];
                s0 += qreg[4 * dd + 0] * kv.x;
                s1 += qreg[4 * dd + 1] * kv.y;
                s2 += qreg[4 * dd + 2] * kv.z;
                s3 += qreg[4 * dd + 3] * kv.w;
            }
            float s = (s0 + s1) + (s2 + s3);
            float p;
            if (s > m) {
                float f = __expf(m - s);
                l *= f;
                #pragma unroll
                for (int d = 0; d < HD; d++) acc[d] *= f;
                m = s;
                p = 1.f;
            } else {
                p = __expf(s - m);
            }
            l += p;
            const float4* V4 = reinterpret_cast<const float4*>(Vs[j]);
            #pragma unroll
            for (int dd = 0; dd < 16; dd++) {
                float4 vv = V4[dd];
                acc[4 * dd + 0] += p * vv.x;
                acc[4 * dd + 1] += p * vv.y;
                acc[4 * dd + 2] += p * vv.z;
                acc[4 * dd + 3] += p * vv.w;
            }
        }
    }

    float inv_l = 1.0f / l;
    float4* yo = reinterpret_cast<float4*>(
        y + ((size_t)b * SEQ + q_idx) * DIM + h * HD);
    #pragma unroll
    for (int dd = 0; dd < HD / 4; dd++) {
        float4 o;
        o.x = acc[4 * dd + 0] * inv_l;
        o.y = acc[4 * dd + 1] * inv_l;
        o.z = acc[4 * dd + 2] * inv_l;
        o.w = acc[4 * dd + 3] * inv_l;
        yo[dd] = o;
    }
}

// ---------------- launch ---------------------------------------------------
extern "C" void kernel_launch(void* const* d_in, const int* in_sizes, int n_in,
                              void* d_out, int out_size)
{
    const float* x      = (const float*)d_in[0];
    const float* ln1_g  = (const float*)d_in[1];
    const float* ln1_b  = (const float*)d_in[2];
    const float* ln2_g  = (const float*)d_in[3];
    const float* ln2_b  = (const float*)d_in[4];
    const float* W_qkv  = (const float*)d_in[5];
    const float* b_qkv  = (const float*)d_in[6];
    const float* W_proj = (const float*)d_in[7];
    const float* b_proj = (const float*)d_in[8];
    const float* W_fc   = (const float*)d_in[9];
    const float* b_fc   = (const float*)d_in[10];
    const float* W_out  = (const float*)d_in[11];
    const float* b_out  = (const float*)d_in[12];
    float* out = (float*)d_out;

    float *h, *qkv, *y, *x1, *act;
    __nv_bfloat16 *ah, *al, *bh, *bl;
    cudaGetSymbolAddress((void**)&h,   g_h);
    cudaGetSymbolAddress((void**)&qkv, g_qkv);
    cudaGetSymbolAddress((void**)&y,   g_y);
    cudaGetSymbolAddress((void**)&x1,  g_x1);
    cudaGetSymbolAddress((void**)&act, g_act);
    cudaGetSymbolAddress((void**)&ah,  g_ah);
    cudaGetSymbolAddress((void**)&al,  g_al);
    cudaGetSymbolAddress((void**)&bh,  g_bh);
    cudaGetSymbolAddress((void**)&bl,  g_bl);

    cudaFuncSetAttribute(gemm_mma<false, false>,
        cudaFuncAttributeMaxDynamicSharedMemorySize, GEMM_SMEM);
    cudaFuncSetAttribute(gemm_mma<false, true>,
        cudaFuncAttributeMaxDynamicSharedMemorySize, GEMM_SMEM);
    cudaFuncSetAttribute(gemm_mma<true, false>,
        cudaFuncAttributeMaxDynamicSharedMemorySize, GEMM_SMEM);

    dim3 tb(32, 8);

    // 1) h = LN1(x)
    ln_kernel<<<NTOK, 256>>>(x, ln1_g, ln1_b, h);

    // 2) qkv = h @ W_qkv + b_qkv
    split_kernel<<<(NTOK * DIM / 4 + 255) / 256, 256>>>(h, ah, al, NTOK * DIM / 4);
    splitT_kernel<<<dim3(3 * DIM / 32, DIM / 32), tb>>>(W_qkv, bh, bl, DIM, 3 * DIM);
    gemm_mma<false, false><<<dim3(3 * DIM / 128, NTOK / 128), 256, GEMM_SMEM>>>(
        ah, al, bh, bl, b_qkv, nullptr, qkv, NTOK, 3 * DIM, DIM);

    // 3) y = causal_attention(qkv)
    attn_kernel<<<dim3(SEQ / 128, NH, BATCH), 128>>>(qkv, y);

    // 4) x1 = x + y @ W_proj + b_proj
    split_kernel<<<(NTOK * DIM / 4 + 255) / 256, 256>>>(y, ah, al, NTOK * DIM / 4);
    splitT_kernel<<<dim3(DIM / 32, DIM / 32), tb>>>(W_proj, bh, bl, DIM, DIM);
    gemm_mma<false, true><<<dim3(DIM / 128, NTOK / 128), 256, GEMM_SMEM>>>(
        ah, al, bh, bl, b_proj, x, x1, NTOK, DIM, DIM);

    // 5) h = LN2(x1)
    ln_kernel<<<NTOK, 256>>>(x1, ln2_g, ln2_b, h);

    // 6) act = relu(h @ W_fc + b_fc)
    split_kernel<<<(NTOK * DIM / 4 + 255) / 256, 256>>>(h, ah, al, NTOK * DIM / 4);
    splitT_kernel<<<dim3(4 * DIM / 32, DIM / 32), tb>>>(W_fc, bh, bl, DIM, 4 * DIM);
    gemm_mma<true, false><<<dim3(4 * DIM / 128, NTOK / 128), 256, GEMM_SMEM>>>(
        ah, al, bh, bl, b_fc, nullptr, act, NTOK, 4 * DIM, DIM);

    // 7) out = x1 + act @ W_out + b_out
    split_kernel<<<(NTOK * 4 * DIM / 4 + 255) / 256, 256>>>(act, ah, al, NTOK * 4 * DIM / 4);
    splitT_kernel<<<dim3(DIM / 32, 4 * DIM / 32), tb>>>(W_out, bh, bl, 4 * DIM, DIM);
    gemm_mma<false, true><<<dim3(DIM / 128, NTOK / 128), 256, GEMM_SMEM>>>(
        ah, al, bh, bl, b_out, x1, out, NTOK, DIM, 4 * DIM);
}

// round 4
// speedup vs baseline: 2.9244x; 1.6523x over previous
#include <cuda_runtime.h>
#include <cuda_bf16.h>
#include <math.h>
#include <stdint.h>

#define BATCH 2
#define SEQ   2048
#define DIM   1024
#define NH    16
#define HD    64
#define NTOK  (BATCH * SEQ)   // 4096

// ---------------- scratch (device globals) ---------------------------------
__device__ float g_qkv[(size_t)NTOK * 3 * DIM];
__device__ float g_x1 [(size_t)NTOK * DIM];

__device__ __nv_bfloat16 g_ah [(size_t)NTOK * DIM];      // LN out hi
__device__ __nv_bfloat16 g_al [(size_t)NTOK * DIM];      // LN out lo
__device__ __nv_bfloat16 g_yh [(size_t)NTOK * DIM];      // attn out hi
__device__ __nv_bfloat16 g_yl [(size_t)NTOK * DIM];      // attn out lo
__device__ __nv_bfloat16 g_a2h[(size_t)NTOK * 4 * DIM];  // relu(fc) hi
__device__ __nv_bfloat16 g_a2l[(size_t)NTOK * 4 * DIM];  // relu(fc) lo
__device__ __nv_bfloat16 g_bh [(size_t)4 * DIM * DIM];   // weight hi (B^T)
__device__ __nv_bfloat16 g_bl [(size_t)4 * DIM * DIM];   // weight lo (B^T)

// ======================= helpers ===========================================
__device__ __forceinline__ uint32_t smem_u32(const void* p) {
    uint32_t a;
    asm("{ .reg .u64 t; cvta.to.shared.u64 t, %1; cvt.u32.u64 %0, t; }"
        : "=r"(a) : "l"(p));
    return a;
}
#define SWZ128(o) ((o) ^ (((o) >> 3) & 0x70))

__device__ __forceinline__ void ldsm_x4(uint32_t* r, uint32_t addr) {
    asm volatile("ldmatrix.sync.aligned.m8n8.x4.shared.b16 {%0,%1,%2,%3}, [%4];"
                 : "=r"(r[0]), "=r"(r[1]), "=r"(r[2]), "=r"(r[3]) : "r"(addr));
}
__device__ __forceinline__ void ldsm_x2(uint32_t* r, uint32_t addr) {
    asm volatile("ldmatrix.sync.aligned.m8n8.x2.shared.b16 {%0,%1}, [%2];"
                 : "=r"(r[0]), "=r"(r[1]) : "r"(addr));
}
__device__ __forceinline__ void ldsm_x2t(uint32_t* r, uint32_t addr) {
    asm volatile("ldmatrix.sync.aligned.m8n8.x2.trans.shared.b16 {%0,%1}, [%2];"
                 : "=r"(r[0]), "=r"(r[1]) : "r"(addr));
}
__device__ __forceinline__ void mma_bf16(float* c, const uint32_t* a,
                                         const uint32_t* b) {
    asm volatile(
        "mma.sync.aligned.m16n8k16.row.col.f32.bf16.bf16.f32 "
        "{%0,%1,%2,%3}, {%4,%5,%6,%7}, {%8,%9}, {%0,%1,%2,%3};"
        : "+f"(c[0]), "+f"(c[1]), "+f"(c[2]), "+f"(c[3])
        : "r"(a[0]), "r"(a[1]), "r"(a[2]), "r"(a[3]), "r"(b[0]), "r"(b[1]));
}
__device__ __forceinline__ void cp16(uint32_t daddr, const void* saddr) {
    asm volatile("cp.async.cg.shared.global [%0], [%1], 16;"
                 :: "r"(daddr), "l"(saddr));
}
__device__ __forceinline__ float ex2(float x) {
    float y;
    asm("ex2.approx.f32 %0, %1;" : "=f"(y) : "f"(x));
    return y;
}
// split (a,b) fp32 pair into packed bf16x2 hi and lo
__device__ __forceinline__ void split2(float a, float b, uint32_t& hi, uint32_t& lo) {
    __nv_bfloat16 ha = __float2bfloat16(a);
    __nv_bfloat16 hb = __float2bfloat16(b);
    __nv_bfloat16 la = __float2bfloat16(a - __bfloat162float(ha));
    __nv_bfloat16 lb = __float2bfloat16(b - __bfloat162float(hb));
    __nv_bfloat162 th(ha, hb), tl(la, lb);
    hi = *reinterpret_cast<uint32_t*>(&th);
    lo = *reinterpret_cast<uint32_t*>(&tl);
}

// ---------------- LayerNorm (writes split bf16 hi/lo directly) -------------
__global__ __launch_bounds__(256) void ln_kernel(
    const float* __restrict__ x, const float* __restrict__ gamma,
    const float* __restrict__ beta,
    __nv_bfloat16* __restrict__ oh, __nv_bfloat16* __restrict__ ol)
{
    int row = blockIdx.x;
    int tid = threadIdx.x;
    const float4* xr = reinterpret_cast<const float4*>(x + (size_t)row * DIM);
    float4 v = xr[tid];
    float s1 = v.x + v.y + v.z + v.w;
    float s2 = v.x * v.x + v.y * v.y + v.z * v.z + v.w * v.w;
    #pragma unroll
    for (int o = 16; o > 0; o >>= 1) {
        s1 += __shfl_xor_sync(0xffffffffu, s1, o);
        s2 += __shfl_xor_sync(0xffffffffu, s2, o);
    }
    __shared__ float sh1[8], sh2[8];
    int w = tid >> 5, l = tid & 31;
    if (l == 0) { sh1[w] = s1; sh2[w] = s2; }
    __syncthreads();
    s1 = 0.f; s2 = 0.f;
    #pragma unroll
    for (int i = 0; i < 8; i++) { s1 += sh1[i]; s2 += sh2[i]; }
    float mu  = s1 * (1.0f / DIM);
    float var = s2 * (1.0f / DIM) - mu * mu;
    float r   = rsqrtf(var + 1e-5f);
    float4 gv = reinterpret_cast<const float4*>(gamma)[tid];
    float4 bv = reinterpret_cast<const float4*>(beta)[tid];
    float ox = (v.x - mu) * r * gv.x + bv.x;
    float oy = (v.y - mu) * r * gv.y + bv.y;
    float oz = (v.z - mu) * r * gv.z + bv.z;
    float ow = (v.w - mu) * r * gv.w + bv.w;
    uint2 hh, ll;
    split2(ox, oy, hh.x, ll.x);
    split2(oz, ow, hh.y, ll.y);
    *reinterpret_cast<uint2*>(oh + (size_t)row * DIM + tid * 4) = hh;
    *reinterpret_cast<uint2*>(ol + (size_t)row * DIM + tid * 4) = ll;
}

// ---------------- split + transpose weights: [R,C] fp32 -> [C,R] bf16 ------
__global__ __launch_bounds__(256) void splitT_kernel(
    const float* __restrict__ in, __nv_bfloat16* __restrict__ hi,
    __nv_bfloat16* __restrict__ lo, int R, int C)
{
    __shared__ float t[32][33];
    int tx = threadIdx.x, ty = threadIdx.y;   // block (32,8)
    int x = blockIdx.x * 32 + tx;
    #pragma unroll
    for (int j = 0; j < 32; j += 8)
        t[ty + j][tx] = in[(size_t)(blockIdx.y * 32 + ty + j) * C + x];
    __syncthreads();
    #pragma unroll
    for (int j = 0; j < 32; j += 8) {
        float v = t[tx][ty + j];
        __nv_bfloat16 h = __float2bfloat16(v);
        __nv_bfloat16 l = __float2bfloat16(v - __bfloat162float(h));
        size_t idx = (size_t)(blockIdx.x * 32 + ty + j) * R + blockIdx.y * 32 + tx;
        hi[idx] = h;
        lo[idx] = l;
    }
}

// ---------------- mma.sync split-bf16 GEMM (3-stage cp.async) --------------
// MODE 0: C = acc + bias            (fp32 out)
// MODE 1: C = acc + bias + res      (fp32 out)
// MODE 2: relu(acc + bias) -> split bf16 Oh/Ol
#define STAGE_BYTES 65536
#define GEMM_SMEM   (3 * STAGE_BYTES)

template<int MODE>
__global__ __launch_bounds__(256) void gemm_mma(
    const __nv_bfloat16* __restrict__ Ah, const __nv_bfloat16* __restrict__ Al,
    const __nv_bfloat16* __restrict__ Bh, const __nv_bfloat16* __restrict__ Bl,
    const float* __restrict__ bias, const float* __restrict__ res,
    float* __restrict__ C, __nv_bfloat16* __restrict__ Oh,
    __nv_bfloat16* __restrict__ Ol, int M, int N, int K)
{
    extern __shared__ char smem[];
    const int tid = threadIdx.x;
    const int wid = tid >> 5, lane = tid & 31;
    const int m0 = blockIdx.y * 128, n0 = blockIdx.x * 128;
    const int wm = (wid & 1) * 64;
    const int wn = (wid >> 1) * 32;

    float acc[4][4][4];
    #pragma unroll
    for (int a = 0; a < 4; a++)
        #pragma unroll
        for (int b = 0; b < 4; b++)
            #pragma unroll
            for (int c = 0; c < 4; c++) acc[a][b][c] = 0.f;

    const __nv_bfloat16* srcs[4] = {
        Ah + (size_t)m0 * K, Al + (size_t)m0 * K,
        Bh + (size_t)n0 * K, Bl + (size_t)n0 * K };

    const int row_l = tid >> 3;
    const int c_l   = tid & 7;

    auto issue_stage = [&](int i) {
        int k0 = i << 6;
        char* st = smem + (size_t)(i % 3) * STAGE_BYTES;
        #pragma unroll
        for (int t = 0; t < 4; t++) {
            char* dst = st + t * 16384;
            const __nv_bfloat16* src = srcs[t] + k0;
            #pragma unroll
            for (int p = 0; p < 4; p++) {
                int row = row_l + p * 32;
                uint32_t doff = SWZ128((uint32_t)(row * 128 + c_l * 16));
                cp16(smem_u32(dst + doff), src + (size_t)row * K + c_l * 8);
            }
        }
        asm volatile("cp.async.commit_group;" ::: "memory");
    };

    const int NC = K >> 6;
    issue_stage(0);
    issue_stage(1);
    for (int i = 0; i < NC; i++) {
        if (i + 2 < NC) {
            asm volatile("cp.async.wait_group 1;" ::: "memory");
        } else {
            asm volatile("cp.async.wait_group 0;" ::: "memory");
        }
        __syncthreads();
        if (i + 2 < NC) issue_stage(i + 2);

        char* st = smem + (size_t)(i % 3) * STAGE_BYTES;
        uint32_t sAh = smem_u32(st);
        uint32_t sAl = sAh + 16384;
        uint32_t sBh = sAh + 32768;
        uint32_t sBl = sAh + 49152;

        #pragma unroll
        for (int ks = 0; ks < 4; ks++) {
            int k16 = ks * 16;
            uint32_t ah[4][4], al[4][4];
            #pragma unroll
            for (int mi = 0; mi < 4; mi++) {
                int row = wm + mi * 16 + (lane & 15);
                int col = k16 + (lane >> 4) * 8;
                uint32_t off = SWZ128((uint32_t)(row * 128 + col * 2));
                ldsm_x4(ah[mi], sAh + off);
                ldsm_x4(al[mi], sAl + off);
            }
            uint32_t bh[4][2], bl[4][2];
            #pragma unroll
            for (int ni = 0; ni < 4; ni++) {
                int row = wn + ni * 8 + (lane & 7);
                int col = k16 + ((lane >> 3) & 1) * 8;
                uint32_t off = SWZ128((uint32_t)(row * 128 + col * 2));
                ldsm_x2(bh[ni], sBh + off);
                ldsm_x2(bl[ni], sBl + off);
            }
            #pragma unroll
            for (int mi = 0; mi < 4; mi++)
                #pragma unroll
                for (int ni = 0; ni < 4; ni++) {
                    mma_bf16(acc[mi][ni], ah[mi], bh[ni]);
                    mma_bf16(acc[mi][ni], ah[mi], bl[ni]);
                    mma_bf16(acc[mi][ni], al[mi], bh[ni]);
                }
        }
        __syncthreads();
    }

    #pragma unroll
    for (int mi = 0; mi < 4; mi++) {
        #pragma unroll
        for (int h = 0; h < 2; h++) {
            int row = m0 + wm + mi * 16 + (lane >> 2) + h * 8;
            #pragma unroll
            for (int ni = 0; ni < 4; ni++) {
                int col = n0 + wn + ni * 8 + (lane & 3) * 2;
                float2 bb = *reinterpret_cast<const float2*>(bias + col);
                float vx = acc[mi][ni][h * 2 + 0] + bb.x;
                float vy = acc[mi][ni][h * 2 + 1] + bb.y;
                if (MODE == 1) {
                    float2 rv = *reinterpret_cast<const float2*>(
                        res + (size_t)row * N + col);
                    vx += rv.x; vy += rv.y;
                }
                if (MODE == 2) {
                    vx = fmaxf(vx, 0.f); vy = fmaxf(vy, 0.f);
                    uint32_t hi, lo;
                    split2(vx, vy, hi, lo);
                    *reinterpret_cast<uint32_t*>(Oh + (size_t)row * N + col) = hi;
                    *reinterpret_cast<uint32_t*>(Ol + (size_t)row * N + col) = lo;
                } else {
                    *reinterpret_cast<float2*>(C + (size_t)row * N + col) =
                        make_float2(vx, vy);
                }
            }
        }
    }
}

// ---------------- tensor-core causal flash attention -----------------------
// grid (SEQ/64, NH, BATCH), 128 threads (4 warps x 16 query rows).
// Split-bf16 on QK (3 terms) and PV (3 terms). Softmax in exp2 domain.
__global__ __launch_bounds__(128) void attn_mma(
    const float* __restrict__ qkv,
    __nv_bfloat16* __restrict__ yh, __nv_bfloat16* __restrict__ yl)
{
    __shared__ __align__(1024) char sm[4 * 8192];  // Kh | Kl | Vh | Vl
    uint32_t sKh = smem_u32(sm);
    uint32_t sKl = sKh + 8192;
    uint32_t sVh = sKh + 16384;
    uint32_t sVl = sKh + 24576;

    int qt = blockIdx.x, h = blockIdx.y, b = blockIdx.z;
    int q0 = qt * 64;
    int tid = threadIdx.x, wid = tid >> 5, lane = tid & 31;
    const float* base = qkv + (size_t)b * SEQ * 3 * DIM;
    const int r = lane >> 2, cb = (lane & 3) * 2;
    const float QSC = 0.125f * 1.44269504089f;   // 1/sqrt(64) * log2(e)

    // Q fragments (A-operand layout), split hi/lo
    uint32_t qh[4][4], ql[4][4];
    #pragma unroll
    for (int ks = 0; ks < 4; ks++) {
        #pragma unroll
        for (int fr = 0; fr < 4; fr++) {
            int row = q0 + wid * 16 + r + (fr & 1) * 8;
            int col = ks * 16 + cb + (fr >> 1) * 8;
            float2 v = *reinterpret_cast<const float2*>(
                base + (size_t)row * 3 * DIM + h * HD + col);
            split2(v.x * QSC, v.y * QSC, qh[ks][fr], ql[ks][fr]);
        }
    }

    float m0 = -1e30f, m1 = -1e30f, l0 = 0.f, l1 = 0.f;
    float o[8][4];
    #pragma unroll
    for (int ni = 0; ni < 8; ni++)
        #pragma unroll
        for (int c = 0; c < 4; c++) o[ni][c] = 0.f;

    for (int kb = 0; kb <= qt; kb++) {
        __syncthreads();
        // load K/V 64x64 fp32 tile, convert+split to bf16 smem (SW128 rows)
        #pragma unroll
        for (int it = 0; it < 8; it++) {
            int idx = it * 128 + tid;
            int row = idx >> 4, c4 = idx & 15;
            const float* g = base + (size_t)(kb * 64 + row) * 3 * DIM + h * HD + c4 * 4;
            float4 kv = *reinterpret_cast<const float4*>(g + DIM);
            float4 vv = *reinterpret_cast<const float4*>(g + 2 * DIM);
            uint32_t off = SWZ128((uint32_t)(row * 128 + c4 * 8));
            uint2 hh, ll;
            split2(kv.x, kv.y, hh.x, ll.x);
            split2(kv.z, kv.w, hh.y, ll.y);
            *reinterpret_cast<uint2*>(sm + (sKh - smem_u32(sm)) + off) = hh;
            *reinterpret_cast<uint2*>(sm + (sKl - smem_u32(sm)) + off) = ll;
            split2(vv.x, vv.y, hh.x, ll.x);
            split2(vv.z, vv.w, hh.y, ll.y);
            *reinterpret_cast<uint2*>(sm + (sVh - smem_u32(sm)) + off) = hh;
            *reinterpret_cast<uint2*>(sm + (sVl - smem_u32(sm)) + off) = ll;
        }
        __syncthreads();

        // S = Q K^T  (3 split terms)
        float s[8][4];
        #pragma unroll
        for (int ni = 0; ni < 8; ni++)
            #pragma unroll
            for (int c = 0; c < 4; c++) s[ni][c] = 0.f;
        #pragma unroll
        for (int ks = 0; ks < 4; ks++) {
            #pragma unroll
            for (int ni = 0; ni < 8; ni++) {
                int krow = ni * 8 + (lane & 7);
                int kcol = ks * 16 + ((lane >> 3) & 1) * 8;
                uint32_t off = SWZ128((uint32_t)(krow * 128 + kcol * 2));
                uint32_t kh2[2], kl2[2];
                ldsm_x2(kh2, sKh + off);
                ldsm_x2(kl2, sKl + off);
                mma_bf16(s[ni], qh[ks], kh2);
                mma_bf16(s[ni], qh[ks], kl2);
                mma_bf16(s[ni], ql[ks], kh2);
            }
        }

        // causal mask (diagonal block only)
        if (kb == qt) {
            int rl0 = wid * 16 + r, rl1 = rl0 + 8;
            #pragma unroll
            for (int ni = 0; ni < 8; ni++) {
                int c0 = ni * 8 + cb;
                if (c0     > rl0) s[ni][0] = -1e30f;
                if (c0 + 1 > rl0) s[ni][1] = -1e30f;
                if (c0     > rl1) s[ni][2] = -1e30f;
                if (c0 + 1 > rl1) s[ni][3] = -1e30f;
            }
        }

        // online softmax (exp2 domain)
        float nm0 = -1e30f, nm1 = -1e30f;
        #pragma unroll
        for (int ni = 0; ni < 8; ni++) {
            nm0 = fmaxf(nm0, fmaxf(s[ni][0], s[ni][1]));
            nm1 = fmaxf(nm1, fmaxf(s[ni][2], s[ni][3]));
        }
        nm0 = fmaxf(nm0, __shfl_xor_sync(0xffffffffu, nm0, 1));
        nm0 = fmaxf(nm0, __shfl_xor_sync(0xffffffffu, nm0, 2));
        nm1 = fmaxf(nm1, __shfl_xor_sync(0xffffffffu, nm1, 1));
        nm1 = fmaxf(nm1, __shfl_xor_sync(0xffffffffu, nm1, 2));
        nm0 = fmaxf(nm0, m0);
        nm1 = fmaxf(nm1, m1);
        float sc0 = ex2(m0 - nm0), sc1 = ex2(m1 - nm1);
        m0 = nm0; m1 = nm1;
        float ls0 = 0.f, ls1 = 0.f;
        #pragma unroll
        for (int ni = 0; ni < 8; ni++) {
            s[ni][0] = ex2(s[ni][0] - nm0);
            s[ni][1] = ex2(s[ni][1] - nm0);
            s[ni][2] = ex2(s[ni][2] - nm1);
            s[ni][3] = ex2(s[ni][3] - nm1);
            ls0 += s[ni][0] + s[ni][1];
            ls1 += s[ni][2] + s[ni][3];
        }
        ls0 += __shfl_xor_sync(0xffffffffu, ls0, 1);
        ls0 += __shfl_xor_sync(0xffffffffu, ls0, 2);
        ls1 += __shfl_xor_sync(0xffffffffu, ls1, 1);
        ls1 += __shfl_xor_sync(0xffffffffu, ls1, 2);
        l0 = l0 * sc0 + ls0;
        l1 = l1 * sc1 + ls1;
        #pragma unroll
        for (int ni = 0; ni < 8; ni++) {
            o[ni][0] *= sc0; o[ni][1] *= sc0;
            o[ni][2] *= sc1; o[ni][3] *= sc1;
        }

        // P fragments (A-operand layout, direct from S accumulator), split
        uint32_t ph[4][4], pl[4][4];
        #pragma unroll
        for (int t = 0; t < 4; t++) {
            split2(s[2 * t][0],     s[2 * t][1],     ph[t][0], pl[t][0]);
            split2(s[2 * t][2],     s[2 * t][3],     ph[t][1], pl[t][1]);
            split2(s[2 * t + 1][0], s[2 * t + 1][1], ph[t][2], pl[t][2]);
            split2(s[2 * t + 1][2], s[2 * t + 1][3], ph[t][3], pl[t][3]);
        }

        // O += P V  (3 split terms); V loaded transposed
        #pragma unroll
        for (int t = 0; t < 4; t++) {
            #pragma unroll
            for (int ni = 0; ni < 8; ni++) {
                int vrow = t * 16 + (lane & 15);
                uint32_t off = SWZ128((uint32_t)(vrow * 128 + ni * 16));
                uint32_t vh2[2], vl2[2];
                ldsm_x2t(vh2, sVh + off);
                ldsm_x2t(vl2, sVl + off);
                mma_bf16(o[ni], ph[t], vh2);
                mma_bf16(o[ni], ph[t], vl2);
                mma_bf16(o[ni], pl[t], vh2);
            }
        }
    }

    // normalize + write split bf16 output
    float il0 = 1.0f / l0, il1 = 1.0f / l1;
    int row0 = b * SEQ + q0 + wid * 16 + r;
    #pragma unroll
    for (int ni = 0; ni < 8; ni++) {
        int col = h * HD + ni * 8 + cb;
        uint32_t hi, lo;
        split2(o[ni][0] * il0, o[ni][1] * il0, hi, lo);
        *reinterpret_cast<uint32_t*>(yh + (size_t)row0 * DIM + col) = hi;
        *reinterpret_cast<uint32_t*>(yl + (size_t)row0 * DIM + col) = lo;
        split2(o[ni][2] * il1, o[ni][3] * il1, hi, lo);
        *reinterpret_cast<uint32_t*>(yh + (size_t)(row0 + 8) * DIM + col) = hi;
        *reinterpret_cast<uint32_t*>(yl + (size_t)(row0 + 8) * DIM + col) = lo;
    }
}

// ---------------- launch ---------------------------------------------------
extern "C" void kernel_launch(void* const* d_in, const int* in_sizes, int n_in,
                              void* d_out, int out_size)
{
    const float* x      = (const float*)d_in[0];
    const float* ln1_g  = (const float*)d_in[1];
    const float* ln1_b  = (const float*)d_in[2];
    const float* ln2_g  = (const float*)d_in[3];
    const float* ln2_b  = (const float*)d_in[4];
    const float* W_qkv  = (const float*)d_in[5];
    const float* b_qkv  = (const float*)d_in[6];
    const float* W_proj = (const float*)d_in[7];
    const float* b_proj = (const float*)d_in[8];
    const float* W_fc   = (const float*)d_in[9];
    const float* b_fc   = (const float*)d_in[10];
    const float* W_out  = (const float*)d_in[11];
    const float* b_out  = (const float*)d_in[12];
    float* out = (float*)d_out;

    float *qkv, *x1;
    __nv_bfloat16 *ah, *al, *yh, *yl, *a2h, *a2l, *bh, *bl;
    cudaGetSymbolAddress((void**)&qkv, g_qkv);
    cudaGetSymbolAddress((void**)&x1,  g_x1);
    cudaGetSymbolAddress((void**)&ah,  g_ah);
    cudaGetSymbolAddress((void**)&al,  g_al);
    cudaGetSymbolAddress((void**)&yh,  g_yh);
    cudaGetSymbolAddress((void**)&yl,  g_yl);
    cudaGetSymbolAddress((void**)&a2h, g_a2h);
    cudaGetSymbolAddress((void**)&a2l, g_a2l);
    cudaGetSymbolAddress((void**)&bh,  g_bh);
    cudaGetSymbolAddress((void**)&bl,  g_bl);

    cudaFuncSetAttribute(gemm_mma<0>,
        cudaFuncAttributeMaxDynamicSharedMemorySize, GEMM_SMEM);
    cudaFuncSetAttribute(gemm_mma<1>,
        cudaFuncAttributeMaxDynamicSharedMemorySize, GEMM_SMEM);
    cudaFuncSetAttribute(gemm_mma<2>,
        cudaFuncAttributeMaxDynamicSharedMemorySize, GEMM_SMEM);

    dim3 tb(32, 8);

    // 1) LN1 -> split bf16
    ln_kernel<<<NTOK, 256>>>(x, ln1_g, ln1_b, ah, al);

    // 2) qkv = LN1 @ W_qkv + b_qkv  (fp32 out)
    splitT_kernel<<<dim3(3 * DIM / 32, DIM / 32), tb>>>(W_qkv, bh, bl, DIM, 3 * DIM);
    gemm_mma<0><<<dim3(3 * DIM / 128, NTOK / 128), 256, GEMM_SMEM>>>(
        ah, al, bh, bl, b_qkv, nullptr, qkv, nullptr, nullptr, NTOK, 3 * DIM, DIM);

    // 3) attention -> split bf16 y
    attn_mma<<<dim3(SEQ / 64, NH, BATCH), 128>>>(qkv, yh, yl);

    // 4) x1 = x + y @ W_proj + b_proj
    splitT_kernel<<<dim3(DIM / 32, DIM / 32), tb>>>(W_proj, bh, bl, DIM, DIM);
    gemm_mma<1><<<dim3(DIM / 128, NTOK / 128), 256, GEMM_SMEM>>>(
        yh, yl, bh, bl, b_proj, x, x1, nullptr, nullptr, NTOK, DIM, DIM);

    // 5) LN2 -> split bf16
    ln_kernel<<<NTOK, 256>>>(x1, ln2_g, ln2_b, ah, al);

    // 6) act = relu(LN2 @ W_fc + b_fc) -> split bf16
    splitT_kernel<<<dim3(4 * DIM / 32, DIM / 32), tb>>>(W_fc, bh, bl, DIM, 4 * DIM);
    gemm_mma<2><<<dim3(4 * DIM / 128, NTOK / 128), 256, GEMM_SMEM>>>(
        ah, al, bh, bl, b_fc, nullptr, nullptr, a2h, a2l, NTOK, 4 * DIM, DIM);

    // 7) out = x1 + act @ W_out + b_out
    splitT_kernel<<<dim3(DIM / 32, 4 * DIM / 32), tb>>>(W_out, bh, bl, 4 * DIM, DIM);
    gemm_mma<1><<<dim3(DIM / 128, NTOK / 128), 256, GEMM_SMEM>>>(
        a2h, a2l, bh, bl, b_out, x1, out, nullptr, nullptr, NTOK, DIM, 4 * DIM);
}

// round 5
// speedup vs baseline: 3.6904x; 1.2619x over previous
#include <cuda_runtime.h>
#include <cuda_bf16.h>
#include <math.h>
#include <stdint.h>

#define BATCH 2
#define SEQ   2048
#define DIM   1024
#define NH    16
#define HD    64
#define NTOK  (BATCH * SEQ)   // 4096

// ---------------- scratch (device globals) ---------------------------------
__device__ float g_h  [(size_t)NTOK * DIM];       // LN out (tf32-rounded)
__device__ float g_qkv[(size_t)NTOK * 3 * DIM];   // qkv fp32
__device__ float g_y  [(size_t)NTOK * DIM];       // attn out (tf32-rounded)
__device__ float g_x1 [(size_t)NTOK * DIM];       // residual
__device__ float g_act[(size_t)NTOK * 4 * DIM];   // relu(fc) (tf32-rounded)
__device__ float g_wT [(size_t)4 * DIM * DIM];    // transposed weight (tf32)

// ======================= helpers ===========================================
__device__ __forceinline__ uint32_t smem_u32(const void* p) {
    uint32_t a;
    asm("{ .reg .u64 t; cvta.to.shared.u64 t, %1; cvt.u32.u64 %0, t; }"
        : "=r"(a) : "l"(p));
    return a;
}
#define SWZ128(o) ((o) ^ (((o) >> 3) & 0x70))

__device__ __forceinline__ float tf32r(float x) {
    uint32_t u;
    asm("cvt.rna.tf32.f32 %0, %1;" : "=r"(u) : "f"(x));
    return __uint_as_float(u);
}
__device__ __forceinline__ void ldsm_x4(uint32_t* r, uint32_t addr) {
    asm volatile("ldmatrix.sync.aligned.m8n8.x4.shared.b16 {%0,%1,%2,%3}, [%4];"
                 : "=r"(r[0]), "=r"(r[1]), "=r"(r[2]), "=r"(r[3]) : "r"(addr));
}
__device__ __forceinline__ void ldsm_x2(uint32_t* r, uint32_t addr) {
    asm volatile("ldmatrix.sync.aligned.m8n8.x2.shared.b16 {%0,%1}, [%2];"
                 : "=r"(r[0]), "=r"(r[1]) : "r"(addr));
}
__device__ __forceinline__ void ldsm_x2t(uint32_t* r, uint32_t addr) {
    asm volatile("ldmatrix.sync.aligned.m8n8.x2.trans.shared.b16 {%0,%1}, [%2];"
                 : "=r"(r[0]), "=r"(r[1]) : "r"(addr));
}
__device__ __forceinline__ void mma_bf16(float* c, const uint32_t* a,
                                         const uint32_t* b) {
    asm volatile(
        "mma.sync.aligned.m16n8k16.row.col.f32.bf16.bf16.f32 "
        "{%0,%1,%2,%3}, {%4,%5,%6,%7}, {%8,%9}, {%0,%1,%2,%3};"
        : "+f"(c[0]), "+f"(c[1]), "+f"(c[2]), "+f"(c[3])
        : "r"(a[0]), "r"(a[1]), "r"(a[2]), "r"(a[3]), "r"(b[0]), "r"(b[1]));
}
__device__ __forceinline__ void mma_tf32(float* c, const uint32_t* a,
                                         const uint32_t* b) {
    asm volatile(
        "mma.sync.aligned.m16n8k8.row.col.f32.tf32.tf32.f32 "
        "{%0,%1,%2,%3}, {%4,%5,%6,%7}, {%8,%9}, {%0,%1,%2,%3};"
        : "+f"(c[0]), "+f"(c[1]), "+f"(c[2]), "+f"(c[3])
        : "r"(a[0]), "r"(a[1]), "r"(a[2]), "r"(a[3]), "r"(b[0]), "r"(b[1]));
}
__device__ __forceinline__ void cp16(uint32_t daddr, const void* saddr) {
    asm volatile("cp.async.cg.shared.global [%0], [%1], 16;"
                 :: "r"(daddr), "l"(saddr));
}
__device__ __forceinline__ float ex2(float x) {
    float y;
    asm("ex2.approx.f32 %0, %1;" : "=f"(y) : "f"(x));
    return y;
}
__device__ __forceinline__ void split2(float a, float b, uint32_t& hi, uint32_t& lo) {
    __nv_bfloat16 ha = __float2bfloat16(a);
    __nv_bfloat16 hb = __float2bfloat16(b);
    __nv_bfloat16 la = __float2bfloat16(a - __bfloat162float(ha));
    __nv_bfloat16 lb = __float2bfloat16(b - __bfloat162float(hb));
    __nv_bfloat162 th(ha, hb), tl(la, lb);
    hi = *reinterpret_cast<uint32_t*>(&th);
    lo = *reinterpret_cast<uint32_t*>(&tl);
}

// ---------------- LayerNorm (tf32-rounded fp32 out) ------------------------
__global__ __launch_bounds__(256) void ln_kernel(
    const float* __restrict__ x, const float* __restrict__ gamma,
    const float* __restrict__ beta, float* __restrict__ out)
{
    int row = blockIdx.x;
    int tid = threadIdx.x;
    const float4* xr = reinterpret_cast<const float4*>(x + (size_t)row * DIM);
    float4 v = xr[tid];
    float s1 = v.x + v.y + v.z + v.w;
    float s2 = v.x * v.x + v.y * v.y + v.z * v.z + v.w * v.w;
    #pragma unroll
    for (int o = 16; o > 0; o >>= 1) {
        s1 += __shfl_xor_sync(0xffffffffu, s1, o);
        s2 += __shfl_xor_sync(0xffffffffu, s2, o);
    }
    __shared__ float sh1[8], sh2[8];
    int w = tid >> 5, l = tid & 31;
    if (l == 0) { sh1[w] = s1; sh2[w] = s2; }
    __syncthreads();
    s1 = 0.f; s2 = 0.f;
    #pragma unroll
    for (int i = 0; i < 8; i++) { s1 += sh1[i]; s2 += sh2[i]; }
    float mu  = s1 * (1.0f / DIM);
    float var = s2 * (1.0f / DIM) - mu * mu;
    float r   = rsqrtf(var + 1e-5f);
    float4 gv = reinterpret_cast<const float4*>(gamma)[tid];
    float4 bv = reinterpret_cast<const float4*>(beta)[tid];
    float4 o;
    o.x = tf32r((v.x - mu) * r * gv.x + bv.x);
    o.y = tf32r((v.y - mu) * r * gv.y + bv.y);
    o.z = tf32r((v.z - mu) * r * gv.z + bv.z);
    o.w = tf32r((v.w - mu) * r * gv.w + bv.w);
    reinterpret_cast<float4*>(out + (size_t)row * DIM)[tid] = o;
}

// ---------------- transpose weights: [R,C] -> [C,R], tf32-rounded ----------
__global__ __launch_bounds__(256) void transT_kernel(
    const float* __restrict__ in, float* __restrict__ out, int R, int C)
{
    __shared__ float t[32][33];
    int tx = threadIdx.x, ty = threadIdx.y;   // block (32,8)
    int x = blockIdx.x * 32 + tx;
    #pragma unroll
    for (int j = 0; j < 32; j += 8)
        t[ty + j][tx] = in[(size_t)(blockIdx.y * 32 + ty + j) * C + x];
    __syncthreads();
    #pragma unroll
    for (int j = 0; j < 32; j += 8) {
        size_t idx = (size_t)(blockIdx.x * 32 + ty + j) * R + blockIdx.y * 32 + tx;
        out[idx] = tf32r(t[tx][ty + j]);
    }
}

// ---------------- TF32 GEMM (3-stage cp.async, 128x128x64) -----------------
// A [M,K] row-major tf32; B [N,K] row-major tf32 (= W^T).
// MODE 0: C = acc + bias; MODE 1: + res; MODE 2: relu -> tf32-rounded.
#define STAGE_BYTES 65536
#define GEMM_SMEM   (3 * STAGE_BYTES)

template<int MODE>
__global__ __launch_bounds__(256) void gemm_tf32(
    const float* __restrict__ A, const float* __restrict__ B,
    const float* __restrict__ bias, const float* __restrict__ res,
    float* __restrict__ C, int M, int N, int K)
{
    extern __shared__ char smem[];
    const uint32_t sbase = smem_u32(smem);
    const int tid = threadIdx.x;
    const int wid = tid >> 5, lane = tid & 31;
    const int m0 = blockIdx.y * 128, n0 = blockIdx.x * 128;
    const int wm = (wid & 1) * 64;
    const int wn = (wid >> 1) * 32;
    const int rl = lane & 7, g = lane >> 3, gb = (lane >> 3) & 1;

    float acc[4][4][4];
    #pragma unroll
    for (int a = 0; a < 4; a++)
        #pragma unroll
        for (int b = 0; b < 4; b++)
            #pragma unroll
            for (int c = 0; c < 4; c++) acc[a][b][c] = 0.f;

    const float* Abase = A + (size_t)m0 * K;
    const float* Bbase = B + (size_t)n0 * K;

    auto issue_stage = [&](int i) {
        int k0 = i << 6;
        uint32_t st = sbase + (uint32_t)(i % 3) * STAGE_BYTES;
        #pragma unroll
        for (int op = 0; op < 2; op++) {
            const float* src = (op ? Bbase : Abase) + k0;
            uint32_t dst = st + op * 32768;
            #pragma unroll
            for (int p = 0; p < 8; p++) {
                int idx = tid + p * 256;            // 0..2047
                int row = idx >> 4, c16 = idx & 15;
                int hh = c16 >> 3, l = c16 & 7;
                cp16(dst + hh * 16384 + SWZ128((uint32_t)(row * 128 + l * 16)),
                     src + (size_t)row * K + c16 * 4);
            }
        }
        asm volatile("cp.async.commit_group;" ::: "memory");
    };

    const int NC = K >> 6;
    issue_stage(0);
    issue_stage(1);
    for (int i = 0; i < NC; i++) {
        if (i + 2 < NC) {
            asm volatile("cp.async.wait_group 1;" ::: "memory");
        } else {
            asm volatile("cp.async.wait_group 0;" ::: "memory");
        }
        __syncthreads();
        if (i + 2 < NC) issue_stage(i + 2);

        uint32_t st = sbase + (uint32_t)(i % 3) * STAGE_BYTES;
        uint32_t sA = st, sB = st + 32768;

        #pragma unroll
        for (int ks = 0; ks < 8; ks++) {
            int hh = ks >> 2;
            int cb = (ks & 3) * 32;                 // byte col base in 128B half
            uint32_t af[4][4];
            #pragma unroll
            for (int mi = 0; mi < 4; mi++) {
                int row  = wm + mi * 16 + rl + (g & 1) * 8;
                int colb = cb + (g >> 1) * 16;
                ldsm_x4(af[mi], sA + hh * 16384 +
                        SWZ128((uint32_t)(row * 128 + colb)));
            }
            uint32_t bf[4][2];
            #pragma unroll
            for (int ni = 0; ni < 4; ni++) {
                int row  = wn + ni * 8 + rl;
                int colb = cb + gb * 16;
                ldsm_x2(bf[ni], sB + hh * 16384 +
                        SWZ128((uint32_t)(row * 128 + colb)));
            }
            #pragma unroll
            for (int mi = 0; mi < 4; mi++)
                #pragma unroll
                for (int ni = 0; ni < 4; ni++)
                    mma_tf32(acc[mi][ni], af[mi], bf[ni]);
        }
    }

    #pragma unroll
    for (int mi = 0; mi < 4; mi++) {
        #pragma unroll
        for (int h = 0; h < 2; h++) {
            int row = m0 + wm + mi * 16 + (lane >> 2) + h * 8;
            #pragma unroll
            for (int ni = 0; ni < 4; ni++) {
                int col = n0 + wn + ni * 8 + (lane & 3) * 2;
                float2 bb = *reinterpret_cast<const float2*>(bias + col);
                float vx = acc[mi][ni][h * 2 + 0] + bb.x;
                float vy = acc[mi][ni][h * 2 + 1] + bb.y;
                if (MODE == 1) {
                    float2 rv = *reinterpret_cast<const float2*>(
                        res + (size_t)row * N + col);
                    vx += rv.x; vy += rv.y;
                }
                if (MODE == 2) {
                    vx = tf32r(fmaxf(vx, 0.f));
                    vy = tf32r(fmaxf(vy, 0.f));
                }
                *reinterpret_cast<float2*>(C + (size_t)row * N + col) =
                    make_float2(vx, vy);
            }
        }
    }
}

// ---------------- tensor-core causal flash attention (bf16 3-term) ---------
__global__ __launch_bounds__(128) void attn_mma(
    const float* __restrict__ qkv, float* __restrict__ y)
{
    __shared__ __align__(1024) char sm[4 * 8192];  // Kh | Kl | Vh | Vl
    uint32_t sKh = smem_u32(sm);
    uint32_t sKl = sKh + 8192;
    uint32_t sVh = sKh + 16384;
    uint32_t sVl = sKh + 24576;

    int qt = blockIdx.x, h = blockIdx.y, b = blockIdx.z;
    int q0 = qt * 64;
    int tid = threadIdx.x, wid = tid >> 5, lane = tid & 31;
    const float* base = qkv + (size_t)b * SEQ * 3 * DIM;
    const int r = lane >> 2, cb = (lane & 3) * 2;
    const float QSC = 0.125f * 1.44269504089f;

    uint32_t qh[4][4], ql[4][4];
    #pragma unroll
    for (int ks = 0; ks < 4; ks++) {
        #pragma unroll
        for (int fr = 0; fr < 4; fr++) {
            int row = q0 + wid * 16 + r + (fr & 1) * 8;
            int col = ks * 16 + cb + (fr >> 1) * 8;
            float2 v = *reinterpret_cast<const float2*>(
                base + (size_t)row * 3 * DIM + h * HD + col);
            split2(v.x * QSC, v.y * QSC, qh[ks][fr], ql[ks][fr]);
        }
    }

    float m0 = -1e30f, m1 = -1e30f, l0 = 0.f, l1 = 0.f;
    float o[8][4];
    #pragma unroll
    for (int ni = 0; ni < 8; ni++)
        #pragma unroll
        for (int c = 0; c < 4; c++) o[ni][c] = 0.f;

    for (int kb = 0; kb <= qt; kb++) {
        __syncthreads();
        #pragma unroll
        for (int it = 0; it < 8; it++) {
            int idx = it * 128 + tid;
            int row = idx >> 4, c4 = idx & 15;
            const float* g = base + (size_t)(kb * 64 + row) * 3 * DIM + h * HD + c4 * 4;
            float4 kv = *reinterpret_cast<const float4*>(g + DIM);
            float4 vv = *reinterpret_cast<const float4*>(g + 2 * DIM);
            uint32_t off = SWZ128((uint32_t)(row * 128 + c4 * 8));
            uint2 hh, ll;
            split2(kv.x, kv.y, hh.x, ll.x);
            split2(kv.z, kv.w, hh.y, ll.y);
            *reinterpret_cast<uint2*>(sm + (sKh - smem_u32(sm)) + off) = hh;
            *reinterpret_cast<uint2*>(sm + (sKl - smem_u32(sm)) + off) = ll;
            split2(vv.x, vv.y, hh.x, ll.x);
            split2(vv.z, vv.w, hh.y, ll.y);
            *reinterpret_cast<uint2*>(sm + (sVh - smem_u32(sm)) + off) = hh;
            *reinterpret_cast<uint2*>(sm + (sVl - smem_u32(sm)) + off) = ll;
        }
        __syncthreads();

        float s[8][4];
        #pragma unroll
        for (int ni = 0; ni < 8; ni++)
            #pragma unroll
            for (int c = 0; c < 4; c++) s[ni][c] = 0.f;
        #pragma unroll
        for (int ks = 0; ks < 4; ks++) {
            #pragma unroll
            for (int ni = 0; ni < 8; ni++) {
                int krow = ni * 8 + (lane & 7);
                int kcol = ks * 16 + ((lane >> 3) & 1) * 8;
                uint32_t off = SWZ128((uint32_t)(krow * 128 + kcol * 2));
                uint32_t kh2[2], kl2[2];
                ldsm_x2(kh2, sKh + off);
                ldsm_x2(kl2, sKl + off);
                mma_bf16(s[ni], qh[ks], kh2);
                mma_bf16(s[ni], qh[ks], kl2);
                mma_bf16(s[ni], ql[ks], kh2);
            }
        }

        if (kb == qt) {
            int rl0 = wid * 16 + r, rl1 = rl0 + 8;
            #pragma unroll
            for (int ni = 0; ni < 8; ni++) {
                int c0 = ni * 8 + cb;
                if (c0     > rl0) s[ni][0] = -1e30f;
                if (c0 + 1 > rl0) s[ni][1] = -1e30f;
                if (c0     > rl1) s[ni][2] = -1e30f;
                if (c0 + 1 > rl1) s[ni][3] = -1e30f;
            }
        }

        float nm0 = -1e30f, nm1 = -1e30f;
        #pragma unroll
        for (int ni = 0; ni < 8; ni++) {
            nm0 = fmaxf(nm0, fmaxf(s[ni][0], s[ni][1]));
            nm1 = fmaxf(nm1, fmaxf(s[ni][2], s[ni][3]));
        }
        nm0 = fmaxf(nm0, __shfl_xor_sync(0xffffffffu, nm0, 1));
        nm0 = fmaxf(nm0, __shfl_xor_sync(0xffffffffu, nm0, 2));
        nm1 = fmaxf(nm1, __shfl_xor_sync(0xffffffffu, nm1, 1));
        nm1 = fmaxf(nm1, __shfl_xor_sync(0xffffffffu, nm1, 2));
        nm0 = fmaxf(nm0, m0);
        nm1 = fmaxf(nm1, m1);
        float sc0 = ex2(m0 - nm0), sc1 = ex2(m1 - nm1);
        m0 = nm0; m1 = nm1;
        float ls0 = 0.f, ls1 = 0.f;
        #pragma unroll
        for (int ni = 0; ni < 8; ni++) {
            s[ni][0] = ex2(s[ni][0] - nm0);
            s[ni][1] = ex2(s[ni][1] - nm0);
            s[ni][2] = ex2(s[ni][2] - nm1);
            s[ni][3] = ex2(s[ni][3] - nm1);
            ls0 += s[ni][0] + s[ni][1];
            ls1 += s[ni][2] + s[ni][3];
        }
        ls0 += __shfl_xor_sync(0xffffffffu, ls0, 1);
        ls0 += __shfl_xor_sync(0xffffffffu, ls0, 2);
        ls1 += __shfl_xor_sync(0xffffffffu, ls1, 1);
        ls1 += __shfl_xor_sync(0xffffffffu, ls1, 2);
        l0 = l0 * sc0 + ls0;
        l1 = l1 * sc1 + ls1;
        #pragma unroll
        for (int ni = 0; ni < 8; ni++) {
            o[ni][0] *= sc0; o[ni][1] *= sc0;
            o[ni][2] *= sc1; o[ni][3] *= sc1;
        }

        uint32_t ph[4][4], pl[4][4];
        #pragma unroll
        for (int t = 0; t < 4; t++) {
            split2(s[2 * t][0],     s[2 * t][1],     ph[t][0], pl[t][0]);
            split2(s[2 * t][2],     s[2 * t][3],     ph[t][1], pl[t][1]);
            split2(s[2 * t + 1][0], s[2 * t + 1][1], ph[t][2], pl[t][2]);
            split2(s[2 * t + 1][2], s[2 * t + 1][3], ph[t][3], pl[t][3]);
        }

        #pragma unroll
        for (int t = 0; t < 4; t++) {
            #pragma unroll
            for (int ni = 0; ni < 8; ni++) {
                int vrow = t * 16 + (lane & 15);
                uint32_t off = SWZ128((uint32_t)(vrow * 128 + ni * 16));
                uint32_t vh2[2], vl2[2];
                ldsm_x2t(vh2, sVh + off);
                ldsm_x2t(vl2, sVl + off);
                mma_bf16(o[ni], ph[t], vh2);
                mma_bf16(o[ni], ph[t], vl2);
                mma_bf16(o[ni], pl[t], vh2);
            }
        }
    }

    float il0 = 1.0f / l0, il1 = 1.0f / l1;
    int row0 = b * SEQ + q0 + wid * 16 + r;
    #pragma unroll
    for (int ni = 0; ni < 8; ni++) {
        int col = h * HD + ni * 8 + cb;
        *reinterpret_cast<float2*>(y + (size_t)row0 * DIM + col) =
            make_float2(tf32r(o[ni][0] * il0), tf32r(o[ni][1] * il0));
        *reinterpret_cast<float2*>(y + (size_t)(row0 + 8) * DIM + col) =
            make_float2(tf32r(o[ni][2] * il1), tf32r(o[ni][3] * il1));
    }
}

// ---------------- launch ---------------------------------------------------
extern "C" void kernel_launch(void* const* d_in, const int* in_sizes, int n_in,
                              void* d_out, int out_size)
{
    const float* x      = (const float*)d_in[0];
    const float* ln1_g  = (const float*)d_in[1];
    const float* ln1_b  = (const float*)d_in[2];
    const float* ln2_g  = (const float*)d_in[3];
    const float* ln2_b  = (const float*)d_in[4];
    const float* W_qkv  = (const float*)d_in[5];
    const float* b_qkv  = (const float*)d_in[6];
    const float* W_proj = (const float*)d_in[7];
    const float* b_proj = (const float*)d_in[8];
    const float* W_fc   = (const float*)d_in[9];
    const float* b_fc   = (const float*)d_in[10];
    const float* W_out  = (const float*)d_in[11];
    const float* b_out  = (const float*)d_in[12];
    float* out = (float*)d_out;

    float *h, *qkv, *y, *x1, *act, *wT;
    cudaGetSymbolAddress((void**)&h,   g_h);
    cudaGetSymbolAddress((void**)&qkv, g_qkv);
    cudaGetSymbolAddress((void**)&y,   g_y);
    cudaGetSymbolAddress((void**)&x1,  g_x1);
    cudaGetSymbolAddress((void**)&act, g_act);
    cudaGetSymbolAddress((void**)&wT,  g_wT);

    cudaFuncSetAttribute(gemm_tf32<0>,
        cudaFuncAttributeMaxDynamicSharedMemorySize, GEMM_SMEM);
    cudaFuncSetAttribute(gemm_tf32<1>,
        cudaFuncAttributeMaxDynamicSharedMemorySize, GEMM_SMEM);
    cudaFuncSetAttribute(gemm_tf32<2>,
        cudaFuncAttributeMaxDynamicSharedMemorySize, GEMM_SMEM);

    dim3 tb(32, 8);

    // 1) LN1 -> h (tf32)
    ln_kernel<<<NTOK, 256>>>(x, ln1_g, ln1_b, h);

    // 2) qkv = h @ W_qkv + b_qkv
    transT_kernel<<<dim3(3 * DIM / 32, DIM / 32), tb>>>(W_qkv, wT, DIM, 3 * DIM);
    gemm_tf32<0><<<dim3(3 * DIM / 128, NTOK / 128), 256, GEMM_SMEM>>>(
        h, wT, b_qkv, nullptr, qkv, NTOK, 3 * DIM, DIM);

    // 3) attention -> y (tf32)
    attn_mma<<<dim3(SEQ / 64, NH, BATCH), 128>>>(qkv, y);

    // 4) x1 = x + y @ W_proj + b_proj
    transT_kernel<<<dim3(DIM / 32, DIM / 32), tb>>>(W_proj, wT, DIM, DIM);
    gemm_tf32<1><<<dim3(DIM / 128, NTOK / 128), 256, GEMM_SMEM>>>(
        y, wT, b_proj, x, x1, NTOK, DIM, DIM);

    // 5) LN2 -> h (tf32)
    ln_kernel<<<NTOK, 256>>>(x1, ln2_g, ln2_b, h);

    // 6) act = relu(h @ W_fc + b_fc) (tf32)
    transT_kernel<<<dim3(4 * DIM / 32, DIM / 32), tb>>>(W_fc, wT, DIM, 4 * DIM);
    gemm_tf32<2><<<dim3(4 * DIM / 128, NTOK / 128), 256, GEMM_SMEM>>>(
        h, wT, b_fc, nullptr, act, NTOK, 4 * DIM, DIM);

    // 7) out = x1 + act @ W_out + b_out
    transT_kernel<<<dim3(DIM / 32, 4 * DIM / 32), tb>>>(W_out, wT, 4 * DIM, DIM);
    gemm_tf32<1><<<dim3(DIM / 128, NTOK / 128), 256, GEMM_SMEM>>>(
        act, wT, b_out, x1, out, NTOK, DIM, 4 * DIM);
}

// round 6
// speedup vs baseline: 6.0716x; 1.6453x over previous
#include <cuda_runtime.h>
#include <cuda_bf16.h>
#include <cuda_fp16.h>
#include <math.h>
#include <stdint.h>

#define BATCH 2
#define SEQ   2048
#define DIM   1024
#define NH    16
#define HD    64
#define NTOK  (BATCH * SEQ)   // 4096

// ---------------- scratch (device globals) ---------------------------------
__device__ float  g_qkv[(size_t)NTOK * 3 * DIM];   // qkv fp32
__device__ float  g_x1 [(size_t)NTOK * DIM];       // residual after proj
__device__ __half g_h  [(size_t)NTOK * DIM];       // LN out fp16
__device__ __half g_y  [(size_t)NTOK * DIM];       // attn out fp16
__device__ __half g_act[(size_t)NTOK * 4 * DIM];   // relu(fc) fp16
__device__ __half g_wT [(size_t)4 * DIM * DIM];    // transposed weight fp16

// ======================= helpers ===========================================
__device__ __forceinline__ uint32_t smem_u32(const void* p) {
    uint32_t a;
    asm("{ .reg .u64 t; cvta.to.shared.u64 t, %1; cvt.u32.u64 %0, t; }"
        : "=r"(a) : "l"(p));
    return a;
}
#define SWZ128(o) ((o) ^ (((o) >> 3) & 0x70))

__device__ __forceinline__ void ldsm_x4(uint32_t* r, uint32_t addr) {
    asm volatile("ldmatrix.sync.aligned.m8n8.x4.shared.b16 {%0,%1,%2,%3}, [%4];"
                 : "=r"(r[0]), "=r"(r[1]), "=r"(r[2]), "=r"(r[3]) : "r"(addr));
}
__device__ __forceinline__ void ldsm_x2(uint32_t* r, uint32_t addr) {
    asm volatile("ldmatrix.sync.aligned.m8n8.x2.shared.b16 {%0,%1}, [%2];"
                 : "=r"(r[0]), "=r"(r[1]) : "r"(addr));
}
__device__ __forceinline__ void ldsm_x2t(uint32_t* r, uint32_t addr) {
    asm volatile("ldmatrix.sync.aligned.m8n8.x2.trans.shared.b16 {%0,%1}, [%2];"
                 : "=r"(r[0]), "=r"(r[1]) : "r"(addr));
}
__device__ __forceinline__ void mma_bf16(float* c, const uint32_t* a,
                                         const uint32_t* b) {
    asm volatile(
        "mma.sync.aligned.m16n8k16.row.col.f32.bf16.bf16.f32 "
        "{%0,%1,%2,%3}, {%4,%5,%6,%7}, {%8,%9}, {%0,%1,%2,%3};"
        : "+f"(c[0]), "+f"(c[1]), "+f"(c[2]), "+f"(c[3])
        : "r"(a[0]), "r"(a[1]), "r"(a[2]), "r"(a[3]), "r"(b[0]), "r"(b[1]));
}
__device__ __forceinline__ void mma_f16(float* c, const uint32_t* a,
                                        const uint32_t* b) {
    asm volatile(
        "mma.sync.aligned.m16n8k16.row.col.f32.f16.f16.f32 "
        "{%0,%1,%2,%3}, {%4,%5,%6,%7}, {%8,%9}, {%0,%1,%2,%3};"
        : "+f"(c[0]), "+f"(c[1]), "+f"(c[2]), "+f"(c[3])
        : "r"(a[0]), "r"(a[1]), "r"(a[2]), "r"(a[3]), "r"(b[0]), "r"(b[1]));
}
__device__ __forceinline__ void cp16(uint32_t daddr, const void* saddr) {
    asm volatile("cp.async.cg.shared.global [%0], [%1], 16;"
                 :: "r"(daddr), "l"(saddr));
}
__device__ __forceinline__ float ex2(float x) {
    float y;
    asm("ex2.approx.f32 %0, %1;" : "=f"(y) : "f"(x));
    return y;
}
__device__ __forceinline__ void split2(float a, float b, uint32_t& hi, uint32_t& lo) {
    __nv_bfloat16 ha = __float2bfloat16(a);
    __nv_bfloat16 hb = __float2bfloat16(b);
    __nv_bfloat16 la = __float2bfloat16(a - __bfloat162float(ha));
    __nv_bfloat16 lb = __float2bfloat16(b - __bfloat162float(hb));
    __nv_bfloat162 th(ha, hb), tl(la, lb);
    hi = *reinterpret_cast<uint32_t*>(&th);
    lo = *reinterpret_cast<uint32_t*>(&tl);
}
__device__ __forceinline__ uint32_t h2u(__half2 v) {
    return *reinterpret_cast<uint32_t*>(&v);
}

// ---------------- LayerNorm (fp16 out) -------------------------------------
__global__ __launch_bounds__(256) void ln_kernel(
    const float* __restrict__ x, const float* __restrict__ gamma,
    const float* __restrict__ beta, __half* __restrict__ out)
{
    int row = blockIdx.x;
    int tid = threadIdx.x;
    const float4* xr = reinterpret_cast<const float4*>(x + (size_t)row * DIM);
    float4 v = xr[tid];
    float s1 = v.x + v.y + v.z + v.w;
    float s2 = v.x * v.x + v.y * v.y + v.z * v.z + v.w * v.w;
    #pragma unroll
    for (int o = 16; o > 0; o >>= 1) {
        s1 += __shfl_xor_sync(0xffffffffu, s1, o);
        s2 += __shfl_xor_sync(0xffffffffu, s2, o);
    }
    __shared__ float sh1[8], sh2[8];
    int w = tid >> 5, l = tid & 31;
    if (l == 0) { sh1[w] = s1; sh2[w] = s2; }
    __syncthreads();
    s1 = 0.f; s2 = 0.f;
    #pragma unroll
    for (int i = 0; i < 8; i++) { s1 += sh1[i]; s2 += sh2[i]; }
    float mu  = s1 * (1.0f / DIM);
    float var = s2 * (1.0f / DIM) - mu * mu;
    float r   = rsqrtf(var + 1e-5f);
    float4 gv = reinterpret_cast<const float4*>(gamma)[tid];
    float4 bv = reinterpret_cast<const float4*>(beta)[tid];
    uint2 u;
    u.x = h2u(__floats2half2_rn((v.x - mu) * r * gv.x + bv.x,
                                (v.y - mu) * r * gv.y + bv.y));
    u.y = h2u(__floats2half2_rn((v.z - mu) * r * gv.z + bv.z,
                                (v.w - mu) * r * gv.w + bv.w));
    *reinterpret_cast<uint2*>(out + (size_t)row * DIM + tid * 4) = u;
}

// ---------------- transpose weights: [R,C] fp32 -> [C,R] fp16 --------------
__global__ __launch_bounds__(256) void transT_kernel(
    const float* __restrict__ in, __half* __restrict__ out, int R, int C)
{
    __shared__ float t[32][33];
    int tx = threadIdx.x, ty = threadIdx.y;   // block (32,8)
    int x = blockIdx.x * 32 + tx;
    #pragma unroll
    for (int j = 0; j < 32; j += 8)
        t[ty + j][tx] = in[(size_t)(blockIdx.y * 32 + ty + j) * C + x];
    __syncthreads();
    #pragma unroll
    for (int j = 0; j < 32; j += 8) {
        size_t idx = (size_t)(blockIdx.x * 32 + ty + j) * R + blockIdx.y * 32 + tx;
        out[idx] = __float2half(t[tx][ty + j]);
    }
}

// ---------------- fp16 GEMM (4-stage cp.async, 128x128x64) -----------------
// A [M,K] fp16 row-major; B [N,K] fp16 row-major (= W^T). fp32 accumulate.
// MODE 0: C = acc + bias; MODE 1: + res; MODE 2: relu -> fp16 Oh.
#define STAGE_BYTES 32768
#define GEMM_STAGES 4
#define GEMM_SMEM   (GEMM_STAGES * STAGE_BYTES)

template<int MODE>
__global__ __launch_bounds__(256) void gemm_f16(
    const __half* __restrict__ A, const __half* __restrict__ B,
    const float* __restrict__ bias, const float* __restrict__ res,
    float* __restrict__ C, __half* __restrict__ Oh, int M, int N, int K)
{
    extern __shared__ char smem[];
    const uint32_t sbase = smem_u32(smem);
    const int tid = threadIdx.x;
    const int wid = tid >> 5, lane = tid & 31;
    const int m0 = blockIdx.y * 128, n0 = blockIdx.x * 128;
    const int wm = (wid & 1) * 64;
    const int wn = (wid >> 1) * 32;

    float acc[4][4][4];
    #pragma unroll
    for (int a = 0; a < 4; a++)
        #pragma unroll
        for (int b = 0; b < 4; b++)
            #pragma unroll
            for (int c = 0; c < 4; c++) acc[a][b][c] = 0.f;

    const __half* Ab = A + (size_t)m0 * K;
    const __half* Bb = B + (size_t)n0 * K;
    const int row_l = tid >> 3, c_l = tid & 7;

    auto issue = [&](int i) {
        int k0 = i << 6;
        uint32_t st = sbase + (uint32_t)(i % GEMM_STAGES) * STAGE_BYTES;
        #pragma unroll
        for (int op = 0; op < 2; op++) {
            const __half* src = (op ? Bb : Ab) + k0;
            uint32_t dst = st + op * 16384;
            #pragma unroll
            for (int p = 0; p < 4; p++) {
                int row = row_l + p * 32;
                cp16(dst + SWZ128((uint32_t)(row * 128 + c_l * 16)),
                     src + (size_t)row * K + c_l * 8);
            }
        }
        asm volatile("cp.async.commit_group;" ::: "memory");
    };

    const int NC = K >> 6;
    issue(0); issue(1); issue(2);
    for (int i = 0; i < NC; i++) {
        int rem = NC - 1 - i;
        if (rem >= 2)      { asm volatile("cp.async.wait_group 2;" ::: "memory"); }
        else if (rem == 1) { asm volatile("cp.async.wait_group 1;" ::: "memory"); }
        else               { asm volatile("cp.async.wait_group 0;" ::: "memory"); }
        __syncthreads();
        if (i + 3 < NC) issue(i + 3);

        uint32_t st = sbase + (uint32_t)(i % GEMM_STAGES) * STAGE_BYTES;
        uint32_t sA = st, sB = st + 16384;

        #pragma unroll
        for (int ks = 0; ks < 4; ks++) {
            uint32_t af[4][4];
            #pragma unroll
            for (int mi = 0; mi < 4; mi++) {
                int row = wm + mi * 16 + (lane & 15);
                int colb = ks * 32 + (lane >> 4) * 16;
                ldsm_x4(af[mi], sA + SWZ128((uint32_t)(row * 128 + colb)));
            }
            uint32_t bf[4][2];
            #pragma unroll
            for (int ni = 0; ni < 4; ni++) {
                int row = wn + ni * 8 + (lane & 7);
                int colb = ks * 32 + ((lane >> 3) & 1) * 16;
                ldsm_x2(bf[ni], sB + SWZ128((uint32_t)(row * 128 + colb)));
            }
            #pragma unroll
            for (int mi = 0; mi < 4; mi++)
                #pragma unroll
                for (int ni = 0; ni < 4; ni++)
                    mma_f16(acc[mi][ni], af[mi], bf[ni]);
        }
    }

    #pragma unroll
    for (int mi = 0; mi < 4; mi++) {
        #pragma unroll
        for (int h = 0; h < 2; h++) {
            int row = m0 + wm + mi * 16 + (lane >> 2) + h * 8;
            #pragma unroll
            for (int ni = 0; ni < 4; ni++) {
                int col = n0 + wn + ni * 8 + (lane & 3) * 2;
                float2 bb = *reinterpret_cast<const float2*>(bias + col);
                float vx = acc[mi][ni][h * 2 + 0] + bb.x;
                float vy = acc[mi][ni][h * 2 + 1] + bb.y;
                if (MODE == 1) {
                    float2 rv = *reinterpret_cast<const float2*>(
                        res + (size_t)row * N + col);
                    vx += rv.x; vy += rv.y;
                }
                if (MODE == 2) {
                    vx = fmaxf(vx, 0.f); vy = fmaxf(vy, 0.f);
                    *reinterpret_cast<uint32_t*>(Oh + (size_t)row * N + col) =
                        h2u(__floats2half2_rn(vx, vy));
                } else {
                    *reinterpret_cast<float2*>(C + (size_t)row * N + col) =
                        make_float2(vx, vy);
                }
            }
        }
    }
}

// ---------------- tensor-core causal flash attention -----------------------
// grid (SEQ/128, NH, BATCH), 256 threads (8 warps x 16 query rows).
// QK: bf16 3-term (accurate logits). PV: fp16 single-term. exp2-domain softmax.
// K/V tiles double-buffered via cp.async (fp32 staging -> convert to smem).
#define ATTN_SMEM (2 * 32768 + 3 * 8192)   // staging x2 | Kh | Kl | Vf

__global__ __launch_bounds__(256) void attn_mma(
    const float* __restrict__ qkv, __half* __restrict__ y)
{
    extern __shared__ char smem[];
    const uint32_t sb  = smem_u32(smem);
    const uint32_t oKh = 65536, oKl = 73728, oVf = 81920;

    int qt = gridDim.x - 1 - blockIdx.x;   // heavy blocks first
    int h = blockIdx.y, b = blockIdx.z;
    int q0 = qt * 128;
    int tid = threadIdx.x, wid = tid >> 5, lane = tid & 31;
    const float* base = qkv + (size_t)b * SEQ * 3 * DIM;
    const int r = lane >> 2, cb = (lane & 3) * 2;
    const float QSC = 0.125f * 1.44269504089f;

    // Q fragments (A-operand layout), split bf16 hi/lo
    uint32_t qh[4][4], ql[4][4];
    #pragma unroll
    for (int ks = 0; ks < 4; ks++) {
        #pragma unroll
        for (int fr = 0; fr < 4; fr++) {
            int row = q0 + wid * 16 + r + (fr & 1) * 8;
            int col = ks * 16 + cb + (fr >> 1) * 8;
            float2 v = *reinterpret_cast<const float2*>(
                base + (size_t)row * 3 * DIM + h * HD + col);
            split2(v.x * QSC, v.y * QSC, qh[ks][fr], ql[ks][fr]);
        }
    }

    auto issueKV = [&](int kb) {
        uint32_t stg = sb + (uint32_t)(kb & 1) * 32768;
        #pragma unroll
        for (int p = 0; p < 8; p++) {
            int idx = p * 256 + tid;
            int op = idx >> 10, rem = idx & 1023;
            int row = rem >> 4, c16 = rem & 15;
            const float* src = base + (size_t)(kb * 64 + row) * 3 * DIM
                             + (op ? 2 * DIM : DIM) + h * HD + c16 * 4;
            cp16(stg + op * 16384 + row * 256 + c16 * 16, src);
        }
        asm volatile("cp.async.commit_group;" ::: "memory");
    };

    float m0 = -1e30f, m1 = -1e30f, l0 = 0.f, l1 = 0.f;
    float o[8][4];
    #pragma unroll
    for (int ni = 0; ni < 8; ni++)
        #pragma unroll
        for (int c = 0; c < 4; c++) o[ni][c] = 0.f;

    const int last = 2 * qt + 1;
    issueKV(0);
    for (int kb = 0; kb <= last; kb++) {
        if (kb < last) {
            issueKV(kb + 1);
            asm volatile("cp.async.wait_group 1;" ::: "memory");
        } else {
            asm volatile("cp.async.wait_group 0;" ::: "memory");
        }
        __syncthreads();   // staging ready + prev MMAs done with split bufs

        // convert staging -> Kh/Kl (bf16 split) + Vf (fp16)
        {
            char* stg = smem + (kb & 1) * 32768;
            #pragma unroll
            for (int p = 0; p < 4; p++) {
                int idx = p * 256 + tid;
                int row = idx >> 4, c4 = idx & 15;
                float4 kv = *reinterpret_cast<float4*>(stg + row * 256 + c4 * 16);
                float4 vv = *reinterpret_cast<float4*>(stg + 16384 + row * 256 + c4 * 16);
                uint32_t off = SWZ128((uint32_t)(row * 128 + c4 * 8));
                uint2 hh, ll;
                split2(kv.x, kv.y, hh.x, ll.x);
                split2(kv.z, kv.w, hh.y, ll.y);
                *reinterpret_cast<uint2*>(smem + oKh + off) = hh;
                *reinterpret_cast<uint2*>(smem + oKl + off) = ll;
                uint2 vf;
                vf.x = h2u(__floats2half2_rn(vv.x, vv.y));
                vf.y = h2u(__floats2half2_rn(vv.z, vv.w));
                *reinterpret_cast<uint2*>(smem + oVf + off) = vf;
            }
        }
        __syncthreads();

        // S = Q K^T (3-term bf16)
        float s[8][4];
        #pragma unroll
        for (int ni = 0; ni < 8; ni++)
            #pragma unroll
            for (int c = 0; c < 4; c++) s[ni][c] = 0.f;
        #pragma unroll
        for (int ks = 0; ks < 4; ks++) {
            #pragma unroll
            for (int ni = 0; ni < 8; ni++) {
                int krow = ni * 8 + (lane & 7);
                int kcolb = ks * 32 + ((lane >> 3) & 1) * 16;
                uint32_t off = SWZ128((uint32_t)(krow * 128 + kcolb));
                uint32_t kh2[2], kl2[2];
                ldsm_x2(kh2, sb + oKh + off);
                ldsm_x2(kl2, sb + oKl + off);
                mma_bf16(s[ni], qh[ks], kh2);
                mma_bf16(s[ni], qh[ks], kl2);
                mma_bf16(s[ni], ql[ks], kh2);
            }
        }

        // causal mask (only tiles that cross the diagonal for this warp)
        if (kb * 64 + 63 > q0 + wid * 16) {
            int rg0 = q0 + wid * 16 + r, rg1 = rg0 + 8;
            int cgb = kb * 64;
            #pragma unroll
            for (int ni = 0; ni < 8; ni++) {
                int c0 = cgb + ni * 8 + cb;
                if (c0     > rg0) s[ni][0] = -1e30f;
                if (c0 + 1 > rg0) s[ni][1] = -1e30f;
                if (c0     > rg1) s[ni][2] = -1e30f;
                if (c0 + 1 > rg1) s[ni][3] = -1e30f;
            }
        }

        // online softmax (exp2 domain)
        float nm0 = -1e30f, nm1 = -1e30f;
        #pragma unroll
        for (int ni = 0; ni < 8; ni++) {
            nm0 = fmaxf(nm0, fmaxf(s[ni][0], s[ni][1]));
            nm1 = fmaxf(nm1, fmaxf(s[ni][2], s[ni][3]));
        }
        nm0 = fmaxf(nm0, __shfl_xor_sync(0xffffffffu, nm0, 1));
        nm0 = fmaxf(nm0, __shfl_xor_sync(0xffffffffu, nm0, 2));
        nm1 = fmaxf(nm1, __shfl_xor_sync(0xffffffffu, nm1, 1));
        nm1 = fmaxf(nm1, __shfl_xor_sync(0xffffffffu, nm1, 2));
        nm0 = fmaxf(nm0, m0);
        nm1 = fmaxf(nm1, m1);
        float sc0 = ex2(m0 - nm0), sc1 = ex2(m1 - nm1);
        m0 = nm0; m1 = nm1;
        float ls0 = 0.f, ls1 = 0.f;
        #pragma unroll
        for (int ni = 0; ni < 8; ni++) {
            s[ni][0] = ex2(s[ni][0] - nm0);
            s[ni][1] = ex2(s[ni][1] - nm0);
            s[ni][2] = ex2(s[ni][2] - nm1);
            s[ni][3] = ex2(s[ni][3] - nm1);
            ls0 += s[ni][0] + s[ni][1];
            ls1 += s[ni][2] + s[ni][3];
        }
        ls0 += __shfl_xor_sync(0xffffffffu, ls0, 1);
        ls0 += __shfl_xor_sync(0xffffffffu, ls0, 2);
        ls1 += __shfl_xor_sync(0xffffffffu, ls1, 1);
        ls1 += __shfl_xor_sync(0xffffffffu, ls1, 2);
        l0 = l0 * sc0 + ls0;
        l1 = l1 * sc1 + ls1;
        #pragma unroll
        for (int ni = 0; ni < 8; ni++) {
            o[ni][0] *= sc0; o[ni][1] *= sc0;
            o[ni][2] *= sc1; o[ni][3] *= sc1;
        }

        // P fragments -> fp16 (A-operand layout direct from S accumulator)
        uint32_t ph[4][4];
        #pragma unroll
        for (int t = 0; t < 4; t++) {
            ph[t][0] = h2u(__floats2half2_rn(s[2 * t][0],     s[2 * t][1]));
            ph[t][1] = h2u(__floats2half2_rn(s[2 * t][2],     s[2 * t][3]));
            ph[t][2] = h2u(__floats2half2_rn(s[2 * t + 1][0], s[2 * t + 1][1]));
            ph[t][3] = h2u(__floats2half2_rn(s[2 * t + 1][2], s[2 * t + 1][3]));
        }

        // O += P V (single-term fp16); V loaded transposed
        #pragma unroll
        for (int t = 0; t < 4; t++) {
            #pragma unroll
            for (int ni = 0; ni < 8; ni++) {
                int vrow = t * 16 + (lane & 15);
                uint32_t off = SWZ128((uint32_t)(vrow * 128 + ni * 16));
                uint32_t vf2[2];
                ldsm_x2t(vf2, sb + oVf + off);
                mma_f16(o[ni], ph[t], vf2);
            }
        }
    }

    // normalize + fp16 output
    float il0 = 1.0f / l0, il1 = 1.0f / l1;
    int row0 = b * SEQ + q0 + wid * 16 + r;
    #pragma unroll
    for (int ni = 0; ni < 8; ni++) {
        int col = h * HD + ni * 8 + cb;
        *reinterpret_cast<uint32_t*>(y + (size_t)row0 * DIM + col) =
            h2u(__floats2half2_rn(o[ni][0] * il0, o[ni][1] * il0));
        *reinterpret_cast<uint32_t*>(y + (size_t)(row0 + 8) * DIM + col) =
            h2u(__floats2half2_rn(o[ni][2] * il1, o[ni][3] * il1));
    }
}

// ---------------- launch ---------------------------------------------------
extern "C" void kernel_launch(void* const* d_in, const int* in_sizes, int n_in,
                              void* d_out, int out_size)
{
    const float* x      = (const float*)d_in[0];
    const float* ln1_g  = (const float*)d_in[1];
    const float* ln1_b  = (const float*)d_in[2];
    const float* ln2_g  = (const float*)d_in[3];
    const float* ln2_b  = (const float*)d_in[4];
    const float* W_qkv  = (const float*)d_in[5];
    const float* b_qkv  = (const float*)d_in[6];
    const float* W_proj = (const float*)d_in[7];
    const float* b_proj = (const float*)d_in[8];
    const float* W_fc   = (const float*)d_in[9];
    const float* b_fc   = (const float*)d_in[10];
    const float* W_out  = (const float*)d_in[11];
    const float* b_out  = (const float*)d_in[12];
    float* out = (float*)d_out;

    float *qkv, *x1;
    __half *h, *y, *act, *wT;
    cudaGetSymbolAddress((void**)&qkv, g_qkv);
    cudaGetSymbolAddress((void**)&x1,  g_x1);
    cudaGetSymbolAddress((void**)&h,   g_h);
    cudaGetSymbolAddress((void**)&y,   g_y);
    cudaGetSymbolAddress((void**)&act, g_act);
    cudaGetSymbolAddress((void**)&wT,  g_wT);

    cudaFuncSetAttribute(gemm_f16<0>,
        cudaFuncAttributeMaxDynamicSharedMemorySize, GEMM_SMEM);
    cudaFuncSetAttribute(gemm_f16<1>,
        cudaFuncAttributeMaxDynamicSharedMemorySize, GEMM_SMEM);
    cudaFuncSetAttribute(gemm_f16<2>,
        cudaFuncAttributeMaxDynamicSharedMemorySize, GEMM_SMEM);
    cudaFuncSetAttribute(attn_mma,
        cudaFuncAttributeMaxDynamicSharedMemorySize, ATTN_SMEM);

    dim3 tb(32, 8);

    // 1) LN1 -> h (fp16)
    ln_kernel<<<NTOK, 256>>>(x, ln1_g, ln1_b, h);

    // 2) qkv = h @ W_qkv + b_qkv (fp32 out)
    transT_kernel<<<dim3(3 * DIM / 32, DIM / 32), tb>>>(W_qkv, wT, DIM, 3 * DIM);
    gemm_f16<0><<<dim3(3 * DIM / 128, NTOK / 128), 256, GEMM_SMEM>>>(
        h, wT, b_qkv, nullptr, qkv, nullptr, NTOK, 3 * DIM, DIM);

    // 3) attention -> y (fp16)
    attn_mma<<<dim3(SEQ / 128, NH, BATCH), 256, ATTN_SMEM>>>(qkv, y);

    // 4) x1 = x + y @ W_proj + b_proj
    transT_kernel<<<dim3(DIM / 32, DIM / 32), tb>>>(W_proj, wT, DIM, DIM);
    gemm_f16<1><<<dim3(DIM / 128, NTOK / 128), 256, GEMM_SMEM>>>(
        y, wT, b_proj, x, x1, nullptr, NTOK, DIM, DIM);

    // 5) LN2 -> h (fp16)
    ln_kernel<<<NTOK, 256>>>(x1, ln2_g, ln2_b, h);

    // 6) act = relu(h @ W_fc + b_fc) (fp16)
    transT_kernel<<<dim3(4 * DIM / 32, DIM / 32), tb>>>(W_fc, wT, DIM, 4 * DIM);
    gemm_f16<2><<<dim3(4 * DIM / 128, NTOK / 128), 256, GEMM_SMEM>>>(
        h, wT, b_fc, nullptr, nullptr, act, NTOK, 4 * DIM, DIM);

    // 7) out = x1 + act @ W_out + b_out
    transT_kernel<<<dim3(DIM / 32, 4 * DIM / 32), tb>>>(W_out, wT, 4 * DIM, DIM);
    gemm_f16<1><<<dim3(DIM / 128, NTOK / 128), 256, GEMM_SMEM>>>(
        act, wT, b_out, x1, out, nullptr, NTOK, DIM, 4 * DIM);
}

// round 8
// speedup vs baseline: 6.7236x; 1.1074x over previous
#include <cuda_runtime.h>
#include <cuda_fp16.h>
#include <math.h>
#include <stdint.h>

#define BATCH 2
#define SEQ   2048
#define DIM   1024
#define NH    16
#define HD    64
#define NTOK  (BATCH * SEQ)   // 4096

// ---------------- scratch (device globals) ---------------------------------
__device__ float  g_x1 [(size_t)NTOK * DIM];       // residual after proj
__device__ __half g_qkv[(size_t)NTOK * 3 * DIM];   // qkv fp16
__device__ __half g_h  [(size_t)NTOK * DIM];       // LN out fp16
__device__ __half g_y  [(size_t)NTOK * DIM];       // attn out fp16
__device__ __half g_act[(size_t)NTOK * 4 * DIM];   // relu(fc) fp16
__device__ __half g_wT [(size_t)4 * DIM * DIM];    // transposed weight fp16

// ======================= helpers ===========================================
__device__ __forceinline__ uint32_t smem_u32(const void* p) {
    uint32_t a;
    asm("{ .reg .u64 t; cvta.to.shared.u64 t, %1; cvt.u32.u64 %0, t; }"
        : "=r"(a) : "l"(p));
    return a;
}
#define SWZ128(o) ((o) ^ (((o) >> 3) & 0x70))

__device__ __forceinline__ void ldsm_x4(uint32_t* r, uint32_t addr) {
    asm volatile("ldmatrix.sync.aligned.m8n8.x4.shared.b16 {%0,%1,%2,%3}, [%4];"
                 : "=r"(r[0]), "=r"(r[1]), "=r"(r[2]), "=r"(r[3]) : "r"(addr));
}
__device__ __forceinline__ void ldsm_x2(uint32_t* r, uint32_t addr) {
    asm volatile("ldmatrix.sync.aligned.m8n8.x2.shared.b16 {%0,%1}, [%2];"
                 : "=r"(r[0]), "=r"(r[1]) : "r"(addr));
}
__device__ __forceinline__ void ldsm_x2t(uint32_t* r, uint32_t addr) {
    asm volatile("ldmatrix.sync.aligned.m8n8.x2.trans.shared.b16 {%0,%1}, [%2];"
                 : "=r"(r[0]), "=r"(r[1]) : "r"(addr));
}
__device__ __forceinline__ void mma_f16(float* c, const uint32_t* a,
                                        const uint32_t* b) {
    asm volatile(
        "mma.sync.aligned.m16n8k16.row.col.f32.f16.f16.f32 "
        "{%0,%1,%2,%3}, {%4,%5,%6,%7}, {%8,%9}, {%0,%1,%2,%3};"
        : "+f"(c[0]), "+f"(c[1]), "+f"(c[2]), "+f"(c[3])
        : "r"(a[0]), "r"(a[1]), "r"(a[2]), "r"(a[3]), "r"(b[0]), "r"(b[1]));
}
__device__ __forceinline__ void cp16(uint32_t daddr, const void* saddr) {
    asm volatile("cp.async.cg.shared.global [%0], [%1], 16;"
                 :: "r"(daddr), "l"(saddr));
}
__device__ __forceinline__ float ex2(float x) {
    float y;
    asm("ex2.approx.f32 %0, %1;" : "=f"(y) : "f"(x));
    return y;
}
__device__ __forceinline__ uint32_t h2u(__half2 v) {
    return *reinterpret_cast<uint32_t*>(&v);
}

// ---------------- LayerNorm (fp16 out) -------------------------------------
__global__ __launch_bounds__(256) void ln_kernel(
    const float* __restrict__ x, const float* __restrict__ gamma,
    const float* __restrict__ beta, __half* __restrict__ out)
{
    int row = blockIdx.x;
    int tid = threadIdx.x;
    const float4* xr = reinterpret_cast<const float4*>(x + (size_t)row * DIM);
    float4 v = xr[tid];
    float s1 = v.x + v.y + v.z + v.w;
    float s2 = v.x * v.x + v.y * v.y + v.z * v.z + v.w * v.w;
    #pragma unroll
    for (int o = 16; o > 0; o >>= 1) {
        s1 += __shfl_xor_sync(0xffffffffu, s1, o);
        s2 += __shfl_xor_sync(0xffffffffu, s2, o);
    }
    __shared__ float sh1[8], sh2[8];
    int w = tid >> 5, l = tid & 31;
    if (l == 0) { sh1[w] = s1; sh2[w] = s2; }
    __syncthreads();
    s1 = 0.f; s2 = 0.f;
    #pragma unroll
    for (int i = 0; i < 8; i++) { s1 += sh1[i]; s2 += sh2[i]; }
    float mu  = s1 * (1.0f / DIM);
    float var = s2 * (1.0f / DIM) - mu * mu;
    float r   = rsqrtf(var + 1e-5f);
    float4 gv = reinterpret_cast<const float4*>(gamma)[tid];
    float4 bv = reinterpret_cast<const float4*>(beta)[tid];
    uint2 u;
    u.x = h2u(__floats2half2_rn((v.x - mu) * r * gv.x + bv.x,
                                (v.y - mu) * r * gv.y + bv.y));
    u.y = h2u(__floats2half2_rn((v.z - mu) * r * gv.z + bv.z,
                                (v.w - mu) * r * gv.w + bv.w));
    *reinterpret_cast<uint2*>(out + (size_t)row * DIM + tid * 4) = u;
}

// ---------------- transpose weights: [R,C] fp32 -> [C,R] fp16 --------------
__global__ __launch_bounds__(256) void transT_kernel(
    const float* __restrict__ in, __half* __restrict__ out, int R, int C)
{
    __shared__ float t[32][33];
    int tx = threadIdx.x, ty = threadIdx.y;   // block (32,8)
    int x = blockIdx.x * 32 + tx;
    #pragma unroll
    for (int j = 0; j < 32; j += 8)
        t[ty + j][tx] = in[(size_t)(blockIdx.y * 32 + ty + j) * C + x];
    __syncthreads();
    #pragma unroll
    for (int j = 0; j < 32; j += 8) {
        size_t idx = (size_t)(blockIdx.x * 32 + ty + j) * R + blockIdx.y * 32 + tx;
        out[idx] = __float2half(t[tx][ty + j]);
    }
}

// ---------------- fp16 GEMM (4-stage cp.async, 128x128x64) -----------------
// A [M,K] fp16 row-major; B [N,K] fp16 row-major (= W^T). fp32 accumulate.
// MODE 0: fp32 C = acc + bias; MODE 1: fp32 C = acc + bias + res;
// MODE 2: fp16 Oh = relu(acc + bias); MODE 3: fp16 Oh = acc + bias.
#define STAGE_BYTES 32768
#define GEMM_STAGES 4
#define GEMM_SMEM   (GEMM_STAGES * STAGE_BYTES)

template<int MODE>
__global__ __launch_bounds__(256) void gemm_f16(
    const __half* __restrict__ A, const __half* __restrict__ B,
    const float* __restrict__ bias, const float* __restrict__ res,
    float* __restrict__ C, __half* __restrict__ Oh, int M, int N, int K)
{
    extern __shared__ char smem[];
    const uint32_t sbase = smem_u32(smem);
    const int tid = threadIdx.x;
    const int wid = tid >> 5, lane = tid & 31;
    const int m0 = blockIdx.y * 128, n0 = blockIdx.x * 128;
    const int wm = (wid & 1) * 64;
    const int wn = (wid >> 1) * 32;

    float acc[4][4][4];
    #pragma unroll
    for (int a = 0; a < 4; a++)
        #pragma unroll
        for (int b = 0; b < 4; b++)
            #pragma unroll
            for (int c = 0; c < 4; c++) acc[a][b][c] = 0.f;

    const __half* Ab = A + (size_t)m0 * K;
    const __half* Bb = B + (size_t)n0 * K;
    const int row_l = tid >> 3, c_l = tid & 7;

    auto issue = [&](int i) {
        int k0 = i << 6;
        uint32_t st = sbase + (uint32_t)(i % GEMM_STAGES) * STAGE_BYTES;
        #pragma unroll
        for (int op = 0; op < 2; op++) {
            const __half* src = (op ? Bb : Ab) + k0;
            uint32_t dst = st + op * 16384;
            #pragma unroll
            for (int p = 0; p < 4; p++) {
                int row = row_l + p * 32;
                cp16(dst + SWZ128((uint32_t)(row * 128 + c_l * 16)),
                     src + (size_t)row * K + c_l * 8);
            }
        }
        asm volatile("cp.async.commit_group;" ::: "memory");
    };

    const int NC = K >> 6;
    issue(0); issue(1); issue(2);
    for (int i = 0; i < NC; i++) {
        int rem = NC - 1 - i;
        if (rem >= 2)      { asm volatile("cp.async.wait_group 2;" ::: "memory"); }
        else if (rem == 1) { asm volatile("cp.async.wait_group 1;" ::: "memory"); }
        else               { asm volatile("cp.async.wait_group 0;" ::: "memory"); }
        __syncthreads();
        if (i + 3 < NC) issue(i + 3);

        uint32_t st = sbase + (uint32_t)(i % GEMM_STAGES) * STAGE_BYTES;
        uint32_t sA = st, sB = st + 16384;

        #pragma unroll
        for (int ks = 0; ks < 4; ks++) {
            uint32_t af[4][4];
            #pragma unroll
            for (int mi = 0; mi < 4; mi++) {
                int row = wm + mi * 16 + (lane & 15);
                int colb = ks * 32 + (lane >> 4) * 16;
                ldsm_x4(af[mi], sA + SWZ128((uint32_t)(row * 128 + colb)));
            }
            uint32_t bf[4][2];
            #pragma unroll
            for (int ni = 0; ni < 4; ni++) {
                int row = wn + ni * 8 + (lane & 7);
                int colb = ks * 32 + ((lane >> 3) & 1) * 16;
                ldsm_x2(bf[ni], sB + SWZ128((uint32_t)(row * 128 + colb)));
            }
            #pragma unroll
            for (int mi = 0; mi < 4; mi++)
                #pragma unroll
                for (int ni = 0; ni < 4; ni++)
                    mma_f16(acc[mi][ni], af[mi], bf[ni]);
        }
    }

    #pragma unroll
    for (int mi = 0; mi < 4; mi++) {
        #pragma unroll
        for (int h = 0; h < 2; h++) {
            int row = m0 + wm + mi * 16 + (lane >> 2) + h * 8;
            #pragma unroll
            for (int ni = 0; ni < 4; ni++) {
                int col = n0 + wn + ni * 8 + (lane & 3) * 2;
                float2 bb = *reinterpret_cast<const float2*>(bias + col);
                float vx = acc[mi][ni][h * 2 + 0] + bb.x;
                float vy = acc[mi][ni][h * 2 + 1] + bb.y;
                if (MODE == 1) {
                    float2 rv = *reinterpret_cast<const float2*>(
                        res + (size_t)row * N + col);
                    vx += rv.x; vy += rv.y;
                }
                if (MODE == 2) { vx = fmaxf(vx, 0.f); vy = fmaxf(vy, 0.f); }
                if (MODE == 2 || MODE == 3) {
                    *reinterpret_cast<uint32_t*>(Oh + (size_t)row * N + col) =
                        h2u(__floats2half2_rn(vx, vy));
                } else {
                    *reinterpret_cast<float2*>(C + (size_t)row * N + col) =
                        make_float2(vx, vy);
                }
            }
        }
    }
}

// ---------------- fp16 tensor-core causal flash attention ------------------
// grid (SEQ/128, NH, BATCH), 256 threads (8 warps x 16 query rows).
// qkv fp16 -> K/V tiles cp.async directly into SW128 smem (no converts).
// Softmax scale applied post-MMA on fp32 logits; exp2 domain.
#define ATTN_SMEM (2 * 16384)   // double-buffered (K 8KB + V 8KB)

__global__ __launch_bounds__(256) void attn_mma(
    const __half* __restrict__ qkv, __half* __restrict__ y)
{
    extern __shared__ char smem[];
    const uint32_t sb = smem_u32(smem);

    int qt = gridDim.x - 1 - blockIdx.x;   // heavy blocks first
    int h = blockIdx.y, b = blockIdx.z;
    int q0 = qt * 128;
    int tid = threadIdx.x, wid = tid >> 5, lane = tid & 31;
    const __half* base = qkv + (size_t)b * SEQ * 3 * DIM;
    const int r = lane >> 2, cb = (lane & 3) * 2;
    const float QSC = 0.125f * 1.44269504089f;   // 1/sqrt(64) * log2(e)

    // Q fragments (fp16 A-operand layout, direct loads)
    uint32_t qf[4][4];
    #pragma unroll
    for (int ks = 0; ks < 4; ks++) {
        #pragma unroll
        for (int fr = 0; fr < 4; fr++) {
            int row = q0 + wid * 16 + r + (fr & 1) * 8;
            int col = ks * 16 + cb + (fr >> 1) * 8;
            qf[ks][fr] = *reinterpret_cast<const uint32_t*>(
                base + (size_t)row * 3 * DIM + h * HD + col);
        }
    }

    auto issueKV = [&](int kb) {
        uint32_t stg = sb + (uint32_t)(kb & 1) * 16384;
        #pragma unroll
        for (int p = 0; p < 4; p++) {
            int idx = p * 256 + tid;              // 0..1023
            int op = idx >> 9, rem = idx & 511;
            int row = rem >> 3, c = rem & 7;
            const __half* src = base + (size_t)(kb * 64 + row) * 3 * DIM
                              + (op ? 2 * DIM : DIM) + h * HD + c * 8;
            cp16(stg + op * 8192 + SWZ128((uint32_t)(row * 128 + c * 16)), src);
        }
        asm volatile("cp.async.commit_group;" ::: "memory");
    };

    float m0 = -1e30f, m1 = -1e30f, l0 = 0.f, l1 = 0.f;
    float o[8][4];
    #pragma unroll
    for (int ni = 0; ni < 8; ni++)
        #pragma unroll
        for (int c = 0; c < 4; c++) o[ni][c] = 0.f;

    const int last = 2 * qt + 1;
    issueKV(0);
    for (int kb = 0; kb <= last; kb++) {
        asm volatile("cp.async.wait_group 0;" ::: "memory");
        __syncthreads();   // buffer kb ready; all warps done with buffer kb-1
        if (kb < last) issueKV(kb + 1);   // overlaps with MMAs below

        uint32_t sK = sb + (uint32_t)(kb & 1) * 16384;
        uint32_t sV = sK + 8192;

        // S = Q K^T (single-term fp16)
        float s[8][4];
        #pragma unroll
        for (int ni = 0; ni < 8; ni++)
            #pragma unroll
            for (int c = 0; c < 4; c++) s[ni][c] = 0.f;
        #pragma unroll
        for (int ks = 0; ks < 4; ks++) {
            #pragma unroll
            for (int ni = 0; ni < 8; ni++) {
                int krow = ni * 8 + (lane & 7);
                int kcolb = ks * 32 + ((lane >> 3) & 1) * 16;
                uint32_t kf2[2];
                ldsm_x2(kf2, sK + SWZ128((uint32_t)(krow * 128 + kcolb)));
                mma_f16(s[ni], qf[ks], kf2);
            }
        }
        #pragma unroll
        for (int ni = 0; ni < 8; ni++) {
            s[ni][0] *= QSC; s[ni][1] *= QSC;
            s[ni][2] *= QSC; s[ni][3] *= QSC;
        }

        // causal mask (tiles crossing the diagonal for this warp)
        if (kb * 64 + 63 > q0 + wid * 16) {
            int rg0 = q0 + wid * 16 + r, rg1 = rg0 + 8;
            int cgb = kb * 64;
            #pragma unroll
            for (int ni = 0; ni < 8; ni++) {
                int c0 = cgb + ni * 8 + cb;
                if (c0     > rg0) s[ni][0] = -1e30f;
                if (c0 + 1 > rg0) s[ni][1] = -1e30f;
                if (c0     > rg1) s[ni][2] = -1e30f;
                if (c0 + 1 > rg1) s[ni][3] = -1e30f;
            }
        }

        // online softmax (exp2 domain)
        float nm0 = -1e30f, nm1 = -1e30f;
        #pragma unroll
        for (int ni = 0; ni < 8; ni++) {
            nm0 = fmaxf(nm0, fmaxf(s[ni][0], s[ni][1]));
            nm1 = fmaxf(nm1, fmaxf(s[ni][2], s[ni][3]));
        }
        nm0 = fmaxf(nm0, __shfl_xor_sync(0xffffffffu, nm0, 1));
        nm0 = fmaxf(nm0, __shfl_xor_sync(0xffffffffu, nm0, 2));
        nm1 = fmaxf(nm1, __shfl_xor_sync(0xffffffffu, nm1, 1));
        nm1 = fmaxf(nm1, __shfl_xor_sync(0xffffffffu, nm1, 2));
        nm0 = fmaxf(nm0, m0);
        nm1 = fmaxf(nm1, m1);
        float sc0 = ex2(m0 - nm0), sc1 = ex2(m1 - nm1);
        m0 = nm0; m1 = nm1;
        float ls0 = 0.f, ls1 = 0.f;
        #pragma unroll
        for (int ni = 0; ni < 8; ni++) {
            s[ni][0] = ex2(s[ni][0] - nm0);
            s[ni][1] = ex2(s[ni][1] - nm0);
            s[ni][2] = ex2(s[ni][2] - nm1);
            s[ni][3] = ex2(s[ni][3] - nm1);
            ls0 += s[ni][0] + s[ni][1];
            ls1 += s[ni][2] + s[ni][3];
        }
        ls0 += __shfl_xor_sync(0xffffffffu, ls0, 1);
        ls0 += __shfl_xor_sync(0xffffffffu, ls0, 2);
        ls1 += __shfl_xor_sync(0xffffffffu, ls1, 1);
        ls1 += __shfl_xor_sync(0xffffffffu, ls1, 2);
        l0 = l0 * sc0 + ls0;
        l1 = l1 * sc1 + ls1;
        #pragma unroll
        for (int ni = 0; ni < 8; ni++) {
            o[ni][0] *= sc0; o[ni][1] *= sc0;
            o[ni][2] *= sc1; o[ni][3] *= sc1;
        }

        // P fragments -> fp16 (A-operand layout direct from S accumulator)
        uint32_t ph[4][4];
        #pragma unroll
        for (int t = 0; t < 4; t++) {
            ph[t][0] = h2u(__floats2half2_rn(s[2 * t][0],     s[2 * t][1]));
            ph[t][1] = h2u(__floats2half2_rn(s[2 * t][2],     s[2 * t][3]));
            ph[t][2] = h2u(__floats2half2_rn(s[2 * t + 1][0], s[2 * t + 1][1]));
            ph[t][3] = h2u(__floats2half2_rn(s[2 * t + 1][2], s[2 * t + 1][3]));
        }

        // O += P V (fp16); V loaded transposed
        #pragma unroll
        for (int t = 0; t < 4; t++) {
            #pragma unroll
            for (int ni = 0; ni < 8; ni++) {
                int vrow = t * 16 + (lane & 15);
                uint32_t vf2[2];
                ldsm_x2t(vf2, sV + SWZ128((uint32_t)(vrow * 128 + ni * 16)));
                mma_f16(o[ni], ph[t], vf2);
            }
        }
    }

    // normalize + fp16 output
    float il0 = 1.0f / l0, il1 = 1.0f / l1;
    int row0 = b * SEQ + q0 + wid * 16 + r;
    #pragma unroll
    for (int ni = 0; ni < 8; ni++) {
        int col = h * HD + ni * 8 + cb;
        *reinterpret_cast<uint32_t*>(y + (size_t)row0 * DIM + col) =
            h2u(__floats2half2_rn(o[ni][0] * il0, o[ni][1] * il0));
        *reinterpret_cast<uint32_t*>(y + (size_t)(row0 + 8) * DIM + col) =
            h2u(__floats2half2_rn(o[ni][2] * il1, o[ni][3] * il1));
    }
}

// ---------------- launch ---------------------------------------------------
extern "C" void kernel_launch(void* const* d_in, const int* in_sizes, int n_in,
                              void* d_out, int out_size)
{
    const float* x      = (const float*)d_in[0];
    const float* ln1_g  = (const float*)d_in[1];
    const float* ln1_b  = (const float*)d_in[2];
    const float* ln2_g  = (const float*)d_in[3];
    const float* ln2_b  = (const float*)d_in[4];
    const float* W_qkv  = (const float*)d_in[5];
    const float* b_qkv  = (const float*)d_in[6];
    const float* W_proj = (const float*)d_in[7];
    const float* b_proj = (const float*)d_in[8];
    const float* W_fc   = (const float*)d_in[9];
    const float* b_fc   = (const float*)d_in[10];
    const float* W_out  = (const float*)d_in[11];
    const float* b_out  = (const float*)d_in[12];
    float* out = (float*)d_out;

    float *x1;
    __half *qkv, *h, *y, *act, *wT;
    cudaGetSymbolAddress((void**)&x1,  g_x1);
    cudaGetSymbolAddress((void**)&qkv, g_qkv);
    cudaGetSymbolAddress((void**)&h,   g_h);
    cudaGetSymbolAddress((void**)&y,   g_y);
    cudaGetSymbolAddress((void**)&act, g_act);
    cudaGetSymbolAddress((void**)&wT,  g_wT);

    cudaFuncSetAttribute(gemm_f16<1>,
        cudaFuncAttributeMaxDynamicSharedMemorySize, GEMM_SMEM);
    cudaFuncSetAttribute(gemm_f16<2>,
        cudaFuncAttributeMaxDynamicSharedMemorySize, GEMM_SMEM);
    cudaFuncSetAttribute(gemm_f16<3>,
        cudaFuncAttributeMaxDynamicSharedMemorySize, GEMM_SMEM);
    cudaFuncSetAttribute(attn_mma,
        cudaFuncAttributeMaxDynamicSharedMemorySize, ATTN_SMEM);

    dim3 tb(32, 8);

    // 1) LN1 -> h (fp16)
    ln_kernel<<<NTOK, 256>>>(x, ln1_g, ln1_b, h);

    // 2) qkv = h @ W_qkv + b_qkv (fp16 out)
    transT_kernel<<<dim3(3 * DIM / 32, DIM / 32), tb>>>(W_qkv, wT, DIM, 3 * DIM);
    gemm_f16<3><<<dim3(3 * DIM / 128, NTOK / 128), 256, GEMM_SMEM>>>(
        h, wT, b_qkv, nullptr, nullptr, qkv, NTOK, 3 * DIM, DIM);

    // 3) attention -> y (fp16)
    attn_mma<<<dim3(SEQ / 128, NH, BATCH), 256, ATTN_SMEM>>>(qkv, y);

    // 4) x1 = x + y @ W_proj + b_proj
    transT_kernel<<<dim3(DIM / 32, DIM / 32), tb>>>(W_proj, wT, DIM, DIM);
    gemm_f16<1><<<dim3(DIM / 128, NTOK / 128), 256, GEMM_SMEM>>>(
        y, wT, b_proj, x, x1, nullptr, NTOK, DIM, DIM);

    // 5) LN2 -> h (fp16)
    ln_kernel<<<NTOK, 256>>>(x1, ln2_g, ln2_b, h);

    // 6) act = relu(h @ W_fc + b_fc) (fp16)
    transT_kernel<<<dim3(4 * DIM / 32, DIM / 32), tb>>>(W_fc, wT, DIM, 4 * DIM);
    gemm_f16<2><<<dim3(4 * DIM / 128, NTOK / 128), 256, GEMM_SMEM>>>(
        h, wT, b_fc, nullptr, nullptr, act, NTOK, 4 * DIM, DIM);

    // 7) out = x1 + act @ W_out + b_out
    transT_kernel<<<dim3(DIM / 32, 4 * DIM / 32), tb>>>(W_out, wT, 4 * DIM, DIM);
    gemm_f16<1><<<dim3(DIM / 128, NTOK / 128), 256, GEMM_SMEM>>>(
        act, wT, b_out, x1, out, nullptr, NTOK, DIM, 4 * DIM);
}

// round 9
// speedup vs baseline: 7.2094x; 1.0723x over previous
#include <cuda_runtime.h>
#include <cuda_fp16.h>
#include <math.h>
#include <stdint.h>

#define BATCH 2
#define SEQ   2048
#define DIM   1024
#define NH    16
#define HD    64
#define NTOK  (BATCH * SEQ)   // 4096

// ---------------- scratch (device globals) ---------------------------------
__device__ float  g_x1 [(size_t)NTOK * DIM];       // residual after proj
__device__ __half g_qkv[(size_t)NTOK * 3 * DIM];   // qkv fp16
__device__ __half g_h  [(size_t)NTOK * DIM];       // LN out fp16
__device__ __half g_y  [(size_t)NTOK * DIM];       // attn out fp16
__device__ __half g_act[(size_t)NTOK * 4 * DIM];   // relu(fc) fp16
__device__ __half g_wT [(size_t)4 * DIM * DIM];    // transposed weight fp16

// ======================= helpers ===========================================
__device__ __forceinline__ uint32_t smem_u32(const void* p) {
    uint32_t a;
    asm("{ .reg .u64 t; cvta.to.shared.u64 t, %1; cvt.u32.u64 %0, t; }"
        : "=r"(a) : "l"(p));
    return a;
}
#define SWZ128(o) ((o) ^ (((o) >> 3) & 0x70))

__device__ __forceinline__ void ldsm_x4(uint32_t* r, uint32_t addr) {
    asm volatile("ldmatrix.sync.aligned.m8n8.x4.shared.b16 {%0,%1,%2,%3}, [%4];"
                 : "=r"(r[0]), "=r"(r[1]), "=r"(r[2]), "=r"(r[3]) : "r"(addr));
}
__device__ __forceinline__ void ldsm_x2(uint32_t* r, uint32_t addr) {
    asm volatile("ldmatrix.sync.aligned.m8n8.x2.shared.b16 {%0,%1}, [%2];"
                 : "=r"(r[0]), "=r"(r[1]) : "r"(addr));
}
__device__ __forceinline__ void ldsm_x2t(uint32_t* r, uint32_t addr) {
    asm volatile("ldmatrix.sync.aligned.m8n8.x2.trans.shared.b16 {%0,%1}, [%2];"
                 : "=r"(r[0]), "=r"(r[1]) : "r"(addr));
}
__device__ __forceinline__ void mma_f16(float* c, const uint32_t* a,
                                        const uint32_t* b) {
    asm volatile(
        "mma.sync.aligned.m16n8k16.row.col.f32.f16.f16.f32 "
        "{%0,%1,%2,%3}, {%4,%5,%6,%7}, {%8,%9}, {%0,%1,%2,%3};"
        : "+f"(c[0]), "+f"(c[1]), "+f"(c[2]), "+f"(c[3])
        : "r"(a[0]), "r"(a[1]), "r"(a[2]), "r"(a[3]), "r"(b[0]), "r"(b[1]));
}
__device__ __forceinline__ void cp16(uint32_t daddr, const void* saddr) {
    asm volatile("cp.async.cg.shared.global [%0], [%1], 16;"
                 :: "r"(daddr), "l"(saddr));
}
__device__ __forceinline__ float ex2(float x) {
    float y;
    asm("ex2.approx.f32 %0, %1;" : "=f"(y) : "f"(x));
    return y;
}
__device__ __forceinline__ uint32_t h2u(__half2 v) {
    return *reinterpret_cast<uint32_t*>(&v);
}

// ---------------- LayerNorm (fp16 out) -------------------------------------
__global__ __launch_bounds__(256) void ln_kernel(
    const float* __restrict__ x, const float* __restrict__ gamma,
    const float* __restrict__ beta, __half* __restrict__ out)
{
    int row = blockIdx.x;
    int tid = threadIdx.x;
    const float4* xr = reinterpret_cast<const float4*>(x + (size_t)row * DIM);
    float4 v = xr[tid];
    float s1 = v.x + v.y + v.z + v.w;
    float s2 = v.x * v.x + v.y * v.y + v.z * v.z + v.w * v.w;
    #pragma unroll
    for (int o = 16; o > 0; o >>= 1) {
        s1 += __shfl_xor_sync(0xffffffffu, s1, o);
        s2 += __shfl_xor_sync(0xffffffffu, s2, o);
    }
    __shared__ float sh1[8], sh2[8];
    int w = tid >> 5, l = tid & 31;
    if (l == 0) { sh1[w] = s1; sh2[w] = s2; }
    __syncthreads();
    s1 = 0.f; s2 = 0.f;
    #pragma unroll
    for (int i = 0; i < 8; i++) { s1 += sh1[i]; s2 += sh2[i]; }
    float mu  = s1 * (1.0f / DIM);
    float var = s2 * (1.0f / DIM) - mu * mu;
    float r   = rsqrtf(var + 1e-5f);
    float4 gv = reinterpret_cast<const float4*>(gamma)[tid];
    float4 bv = reinterpret_cast<const float4*>(beta)[tid];
    uint2 u;
    u.x = h2u(__floats2half2_rn((v.x - mu) * r * gv.x + bv.x,
                                (v.y - mu) * r * gv.y + bv.y));
    u.y = h2u(__floats2half2_rn((v.z - mu) * r * gv.z + bv.z,
                                (v.w - mu) * r * gv.w + bv.w));
    *reinterpret_cast<uint2*>(out + (size_t)row * DIM + tid * 4) = u;
}

// ---------------- transpose weights: [R,C] fp32 -> [C,R] fp16 --------------
__global__ __launch_bounds__(256) void transT_kernel(
    const float* __restrict__ in, __half* __restrict__ out, int R, int C)
{
    __shared__ float t[32][33];
    int tx = threadIdx.x, ty = threadIdx.y;   // block (32,8)
    int x = blockIdx.x * 32 + tx;
    #pragma unroll
    for (int j = 0; j < 32; j += 8)
        t[ty + j][tx] = in[(size_t)(blockIdx.y * 32 + ty + j) * C + x];
    __syncthreads();
    #pragma unroll
    for (int j = 0; j < 32; j += 8) {
        size_t idx = (size_t)(blockIdx.x * 32 + ty + j) * R + blockIdx.y * 32 + tx;
        out[idx] = __float2half(t[tx][ty + j]);
    }
}

// ---------------- fp16 GEMM (3-stage cp.async, 128x128x64, 2 CTA/SM) -------
// A [M,K] fp16 row-major; B [N,K] fp16 row-major (= W^T). fp32 accumulate.
// MODE 0: fp32 C = acc + bias; MODE 1: fp32 C = acc + bias + res;
// MODE 2: fp16 Oh = relu(acc + bias); MODE 3: fp16 Oh = acc + bias.
#define STAGE_BYTES 32768
#define GEMM_STAGES 3
#define GEMM_SMEM   (GEMM_STAGES * STAGE_BYTES)

template<int MODE>
__global__ __launch_bounds__(256, 2) void gemm_f16(
    const __half* __restrict__ A, const __half* __restrict__ B,
    const float* __restrict__ bias, const float* __restrict__ res,
    float* __restrict__ C, __half* __restrict__ Oh, int M, int N, int K)
{
    extern __shared__ char smem[];
    const uint32_t sbase = smem_u32(smem);
    const int tid = threadIdx.x;
    const int wid = tid >> 5, lane = tid & 31;
    const int m0 = blockIdx.y * 128, n0 = blockIdx.x * 128;
    const int wm = (wid & 1) * 64;
    const int wn = (wid >> 1) * 32;

    float acc[4][4][4];
    #pragma unroll
    for (int a = 0; a < 4; a++)
        #pragma unroll
        for (int b = 0; b < 4; b++)
            #pragma unroll
            for (int c = 0; c < 4; c++) acc[a][b][c] = 0.f;

    const __half* Ab = A + (size_t)m0 * K;
    const __half* Bb = B + (size_t)n0 * K;
    const int row_l = tid >> 3, c_l = tid & 7;

    auto issue = [&](int i) {
        int k0 = i << 6;
        uint32_t st = sbase + (uint32_t)(i % GEMM_STAGES) * STAGE_BYTES;
        #pragma unroll
        for (int op = 0; op < 2; op++) {
            const __half* src = (op ? Bb : Ab) + k0;
            uint32_t dst = st + op * 16384;
            #pragma unroll
            for (int p = 0; p < 4; p++) {
                int row = row_l + p * 32;
                cp16(dst + SWZ128((uint32_t)(row * 128 + c_l * 16)),
                     src + (size_t)row * K + c_l * 8);
            }
        }
        asm volatile("cp.async.commit_group;" ::: "memory");
    };

    const int NC = K >> 6;
    issue(0); issue(1);
    for (int i = 0; i < NC; i++) {
        if (i + 1 < NC) { asm volatile("cp.async.wait_group 1;" ::: "memory"); }
        else            { asm volatile("cp.async.wait_group 0;" ::: "memory"); }
        __syncthreads();
        if (i + 2 < NC) issue(i + 2);

        uint32_t st = sbase + (uint32_t)(i % GEMM_STAGES) * STAGE_BYTES;
        uint32_t sA = st, sB = st + 16384;

        #pragma unroll
        for (int ks = 0; ks < 4; ks++) {
            uint32_t af[4][4];
            #pragma unroll
            for (int mi = 0; mi < 4; mi++) {
                int row = wm + mi * 16 + (lane & 15);
                int colb = ks * 32 + (lane >> 4) * 16;
                ldsm_x4(af[mi], sA + SWZ128((uint32_t)(row * 128 + colb)));
            }
            uint32_t bf[4][2];
            #pragma unroll
            for (int ni = 0; ni < 4; ni++) {
                int row = wn + ni * 8 + (lane & 7);
                int colb = ks * 32 + ((lane >> 3) & 1) * 16;
                ldsm_x2(bf[ni], sB + SWZ128((uint32_t)(row * 128 + colb)));
            }
            #pragma unroll
            for (int mi = 0; mi < 4; mi++)
                #pragma unroll
                for (int ni = 0; ni < 4; ni++)
                    mma_f16(acc[mi][ni], af[mi], bf[ni]);
        }
    }

    #pragma unroll
    for (int mi = 0; mi < 4; mi++) {
        #pragma unroll
        for (int h = 0; h < 2; h++) {
            int row = m0 + wm + mi * 16 + (lane >> 2) + h * 8;
            #pragma unroll
            for (int ni = 0; ni < 4; ni++) {
                int col = n0 + wn + ni * 8 + (lane & 3) * 2;
                float2 bb = *reinterpret_cast<const float2*>(bias + col);
                float vx = acc[mi][ni][h * 2 + 0] + bb.x;
                float vy = acc[mi][ni][h * 2 + 1] + bb.y;
                if (MODE == 1) {
                    float2 rv = *reinterpret_cast<const float2*>(
                        res + (size_t)row * N + col);
                    vx += rv.x; vy += rv.y;
                }
                if (MODE == 2) { vx = fmaxf(vx, 0.f); vy = fmaxf(vy, 0.f); }
                if (MODE == 2 || MODE == 3) {
                    *reinterpret_cast<uint32_t*>(Oh + (size_t)row * N + col) =
                        h2u(__floats2half2_rn(vx, vy));
                } else {
                    *reinterpret_cast<float2*>(C + (size_t)row * N + col) =
                        make_float2(vx, vy);
                }
            }
        }
    }
}

// ---------------- fp16 tensor-core causal flash attention ------------------
// grid (SEQ/128, NH, BATCH), 256 threads (8 warps x 16 query rows), 2 CTA/SM.
#define ATTN_SMEM (2 * 16384)   // double-buffered (K 8KB + V 8KB)

__global__ __launch_bounds__(256, 2) void attn_mma(
    const __half* __restrict__ qkv, __half* __restrict__ y)
{
    extern __shared__ char smem[];
    const uint32_t sb = smem_u32(smem);

    int qt = gridDim.x - 1 - blockIdx.x;   // heavy blocks first
    int h = blockIdx.y, b = blockIdx.z;
    int q0 = qt * 128;
    int tid = threadIdx.x, wid = tid >> 5, lane = tid & 31;
    const __half* base = qkv + (size_t)b * SEQ * 3 * DIM;
    const int r = lane >> 2, cb = (lane & 3) * 2;
    const float QSC = 0.125f * 1.44269504089f;   // 1/sqrt(64) * log2(e)

    // Q fragments (fp16 A-operand layout, direct loads)
    uint32_t qf[4][4];
    #pragma unroll
    for (int ks = 0; ks < 4; ks++) {
        #pragma unroll
        for (int fr = 0; fr < 4; fr++) {
            int row = q0 + wid * 16 + r + (fr & 1) * 8;
            int col = ks * 16 + cb + (fr >> 1) * 8;
            qf[ks][fr] = *reinterpret_cast<const uint32_t*>(
                base + (size_t)row * 3 * DIM + h * HD + col);
        }
    }

    auto issueKV = [&](int kb) {
        uint32_t stg = sb + (uint32_t)(kb & 1) * 16384;
        #pragma unroll
        for (int p = 0; p < 4; p++) {
            int idx = p * 256 + tid;              // 0..1023
            int op = idx >> 9, rem = idx & 511;
            int row = rem >> 3, c = rem & 7;
            const __half* src = base + (size_t)(kb * 64 + row) * 3 * DIM
                              + (op ? 2 * DIM : DIM) + h * HD + c * 8;
            cp16(stg + op * 8192 + SWZ128((uint32_t)(row * 128 + c * 16)), src);
        }
        asm volatile("cp.async.commit_group;" ::: "memory");
    };

    float m0 = -1e30f, m1 = -1e30f, l0 = 0.f, l1 = 0.f;
    float o[8][4];
    #pragma unroll
    for (int ni = 0; ni < 8; ni++)
        #pragma unroll
        for (int c = 0; c < 4; c++) o[ni][c] = 0.f;

    const int last = 2 * qt + 1;
    issueKV(0);
    for (int kb = 0; kb <= last; kb++) {
        asm volatile("cp.async.wait_group 0;" ::: "memory");
        __syncthreads();   // buffer kb ready; all warps done with buffer kb-1
        if (kb < last) issueKV(kb + 1);   // overlaps with MMAs below

        uint32_t sK = sb + (uint32_t)(kb & 1) * 16384;
        uint32_t sV = sK + 8192;

        // S = Q K^T (fp16)
        float s[8][4];
        #pragma unroll
        for (int ni = 0; ni < 8; ni++)
            #pragma unroll
            for (int c = 0; c < 4; c++) s[ni][c] = 0.f;
        #pragma unroll
        for (int ks = 0; ks < 4; ks++) {
            #pragma unroll
            for (int ni = 0; ni < 8; ni++) {
                int krow = ni * 8 + (lane & 7);
                int kcolb = ks * 32 + ((lane >> 3) & 1) * 16;
                uint32_t kf2[2];
                ldsm_x2(kf2, sK + SWZ128((uint32_t)(krow * 128 + kcolb)));
                mma_f16(s[ni], qf[ks], kf2);
            }
        }
        #pragma unroll
        for (int ni = 0; ni < 8; ni++) {
            s[ni][0] *= QSC; s[ni][1] *= QSC;
            s[ni][2] *= QSC; s[ni][3] *= QSC;
        }

        // causal mask (tiles crossing the diagonal for this warp)
        if (kb * 64 + 63 > q0 + wid * 16) {
            int rg0 = q0 + wid * 16 + r, rg1 = rg0 + 8;
            int cgb = kb * 64;
            #pragma unroll
            for (int ni = 0; ni < 8; ni++) {
                int c0 = cgb + ni * 8 + cb;
                if (c0     > rg0) s[ni][0] = -1e30f;
                if (c0 + 1 > rg0) s[ni][1] = -1e30f;
                if (c0     > rg1) s[ni][2] = -1e30f;
                if (c0 + 1 > rg1) s[ni][3] = -1e30f;
            }
        }

        // online softmax (exp2 domain)
        float nm0 = -1e30f, nm1 = -1e30f;
        #pragma unroll
        for (int ni = 0; ni < 8; ni++) {
            nm0 = fmaxf(nm0, fmaxf(s[ni][0], s[ni][1]));
            nm1 = fmaxf(nm1, fmaxf(s[ni][2], s[ni][3]));
        }
        nm0 = fmaxf(nm0, __shfl_xor_sync(0xffffffffu, nm0, 1));
        nm0 = fmaxf(nm0, __shfl_xor_sync(0xffffffffu, nm0, 2));
        nm1 = fmaxf(nm1, __shfl_xor_sync(0xffffffffu, nm1, 1));
        nm1 = fmaxf(nm1, __shfl_xor_sync(0xffffffffu, nm1, 2));
        nm0 = fmaxf(nm0, m0);
        nm1 = fmaxf(nm1, m1);
        float sc0 = ex2(m0 - nm0), sc1 = ex2(m1 - nm1);
        m0 = nm0; m1 = nm1;
        float ls0 = 0.f, ls1 = 0.f;
        #pragma unroll
        for (int ni = 0; ni < 8; ni++) {
            s[ni][0] = ex2(s[ni][0] - nm0);
            s[ni][1] = ex2(s[ni][1] - nm0);
            s[ni][2] = ex2(s[ni][2] - nm1);
            s[ni][3] = ex2(s[ni][3] - nm1);
            ls0 += s[ni][0] + s[ni][1];
            ls1 += s[ni][2] + s[ni][3];
        }
        ls0 += __shfl_xor_sync(0xffffffffu, ls0, 1);
        ls0 += __shfl_xor_sync(0xffffffffu, ls0, 2);
        ls1 += __shfl_xor_sync(0xffffffffu, ls1, 1);
        ls1 += __shfl_xor_sync(0xffffffffu, ls1, 2);
        l0 = l0 * sc0 + ls0;
        l1 = l1 * sc1 + ls1;
        #pragma unroll
        for (int ni = 0; ni < 8; ni++) {
            o[ni][0] *= sc0; o[ni][1] *= sc0;
            o[ni][2] *= sc1; o[ni][3] *= sc1;
        }

        // P fragments -> fp16 (A-operand layout direct from S accumulator)
        uint32_t ph[4][4];
        #pragma unroll
        for (int t = 0; t < 4; t++) {
            ph[t][0] = h2u(__floats2half2_rn(s[2 * t][0],     s[2 * t][1]));
            ph[t][1] = h2u(__floats2half2_rn(s[2 * t][2],     s[2 * t][3]));
            ph[t][2] = h2u(__floats2half2_rn(s[2 * t + 1][0], s[2 * t + 1][1]));
            ph[t][3] = h2u(__floats2half2_rn(s[2 * t + 1][2], s[2 * t + 1][3]));
        }

        // O += P V (fp16); V loaded transposed
        #pragma unroll
        for (int t = 0; t < 4; t++) {
            #pragma unroll
            for (int ni = 0; ni < 8; ni++) {
                int vrow = t * 16 + (lane & 15);
                uint32_t vf2[2];
                ldsm_x2t(vf2, sV + SWZ128((uint32_t)(vrow * 128 + ni * 16)));
                mma_f16(o[ni], ph[t], vf2);
            }
        }
    }

    // normalize + fp16 output
    float il0 = 1.0f / l0, il1 = 1.0f / l1;
    int row0 = b * SEQ + q0 + wid * 16 + r;
    #pragma unroll
    for (int ni = 0; ni < 8; ni++) {
        int col = h * HD + ni * 8 + cb;
        *reinterpret_cast<uint32_t*>(y + (size_t)row0 * DIM + col) =
            h2u(__floats2half2_rn(o[ni][0] * il0, o[ni][1] * il0));
        *reinterpret_cast<uint32_t*>(y + (size_t)(row0 + 8) * DIM + col) =
            h2u(__floats2half2_rn(o[ni][2] * il1, o[ni][3] * il1));
    }
}

// ---------------- launch ---------------------------------------------------
extern "C" void kernel_launch(void* const* d_in, const int* in_sizes, int n_in,
                              void* d_out, int out_size)
{
    const float* x      = (const float*)d_in[0];
    const float* ln1_g  = (const float*)d_in[1];
    const float* ln1_b  = (const float*)d_in[2];
    const float* ln2_g  = (const float*)d_in[3];
    const float* ln2_b  = (const float*)d_in[4];
    const float* W_qkv  = (const float*)d_in[5];
    const float* b_qkv  = (const float*)d_in[6];
    const float* W_proj = (const float*)d_in[7];
    const float* b_proj = (const float*)d_in[8];
    const float* W_fc   = (const float*)d_in[9];
    const float* b_fc   = (const float*)d_in[10];
    const float* W_out  = (const float*)d_in[11];
    const float* b_out  = (const float*)d_in[12];
    float* out = (float*)d_out;

    float *x1;
    __half *qkv, *h, *y, *act, *wT;
    cudaGetSymbolAddress((void**)&x1,  g_x1);
    cudaGetSymbolAddress((void**)&qkv, g_qkv);
    cudaGetSymbolAddress((void**)&h,   g_h);
    cudaGetSymbolAddress((void**)&y,   g_y);
    cudaGetSymbolAddress((void**)&act, g_act);
    cudaGetSymbolAddress((void**)&wT,  g_wT);

    cudaFuncSetAttribute(gemm_f16<1>,
        cudaFuncAttributeMaxDynamicSharedMemorySize, GEMM_SMEM);
    cudaFuncSetAttribute(gemm_f16<2>,
        cudaFuncAttributeMaxDynamicSharedMemorySize, GEMM_SMEM);
    cudaFuncSetAttribute(gemm_f16<3>,
        cudaFuncAttributeMaxDynamicSharedMemorySize, GEMM_SMEM);
    cudaFuncSetAttribute(attn_mma,
        cudaFuncAttributeMaxDynamicSharedMemorySize, ATTN_SMEM);

    dim3 tb(32, 8);

    // 1) LN1 -> h (fp16)
    ln_kernel<<<NTOK, 256>>>(x, ln1_g, ln1_b, h);

    // 2) qkv = h @ W_qkv + b_qkv (fp16 out)
    transT_kernel<<<dim3(3 * DIM / 32, DIM / 32), tb>>>(W_qkv, wT, DIM, 3 * DIM);
    gemm_f16<3><<<dim3(3 * DIM / 128, NTOK / 128), 256, GEMM_SMEM>>>(
        h, wT, b_qkv, nullptr, nullptr, qkv, NTOK, 3 * DIM, DIM);

    // 3) attention -> y (fp16)
    attn_mma<<<dim3(SEQ / 128, NH, BATCH), 256, ATTN_SMEM>>>(qkv, y);

    // 4) x1 = x + y @ W_proj + b_proj
    transT_kernel<<<dim3(DIM / 32, DIM / 32), tb>>>(W_proj, wT, DIM, DIM);
    gemm_f16<1><<<dim3(DIM / 128, NTOK / 128), 256, GEMM_SMEM>>>(
        y, wT, b_proj, x, x1, nullptr, NTOK, DIM, DIM);

    // 5) LN2 -> h (fp16)
    ln_kernel<<<NTOK, 256>>>(x1, ln2_g, ln2_b, h);

    // 6) act = relu(h @ W_fc + b_fc) (fp16)
    transT_kernel<<<dim3(4 * DIM / 32, DIM / 32), tb>>>(W_fc, wT, DIM, 4 * DIM);
    gemm_f16<2><<<dim3(4 * DIM / 128, NTOK / 128), 256, GEMM_SMEM>>>(
        h, wT, b_fc, nullptr, nullptr, act, NTOK, 4 * DIM, DIM);

    // 7) out = x1 + act @ W_out + b_out
    transT_kernel<<<dim3(DIM / 32, 4 * DIM / 32), tb>>>(W_out, wT, 4 * DIM, DIM);
    gemm_f16<1><<<dim3(DIM / 128, NTOK / 128), 256, GEMM_SMEM>>>(
        act, wT, b_out, x1, out, nullptr, NTOK, DIM, 4 * DIM);
}

// round 10
// speedup vs baseline: 7.7395x; 1.0735x over previous
#include <cuda_runtime.h>
#include <cuda_fp16.h>
#include <math.h>
#include <stdint.h>

#define BATCH 2
#define SEQ   2048
#define DIM   1024
#define NH    16
#define HD    64
#define NTOK  (BATCH * SEQ)   // 4096

// ---------------- scratch (device globals) ---------------------------------
__device__ float  g_x1 [(size_t)NTOK * DIM];       // residual after proj
__device__ __half g_qkv[(size_t)NTOK * 3 * DIM];   // qkv fp16
__device__ __half g_h  [(size_t)NTOK * DIM];       // LN out fp16
__device__ __half g_y  [(size_t)NTOK * DIM];       // attn out fp16
__device__ __half g_act[(size_t)NTOK * 4 * DIM];   // relu(fc) fp16
__device__ __half g_wT [(size_t)4 * DIM * DIM];    // transposed weight fp16

// ======================= helpers ===========================================
__device__ __forceinline__ uint32_t smem_u32(const void* p) {
    uint32_t a;
    asm("{ .reg .u64 t; cvta.to.shared.u64 t, %1; cvt.u32.u64 %0, t; }"
        : "=r"(a) : "l"(p));
    return a;
}
#define SWZ128(o) ((o) ^ (((o) >> 3) & 0x70))

__device__ __forceinline__ void ldsm_x4(uint32_t* r, uint32_t addr) {
    asm volatile("ldmatrix.sync.aligned.m8n8.x4.shared.b16 {%0,%1,%2,%3}, [%4];"
                 : "=r"(r[0]), "=r"(r[1]), "=r"(r[2]), "=r"(r[3]) : "r"(addr));
}
__device__ __forceinline__ void ldsm_x4t(uint32_t* r, uint32_t addr) {
    asm volatile("ldmatrix.sync.aligned.m8n8.x4.trans.shared.b16 {%0,%1,%2,%3}, [%4];"
                 : "=r"(r[0]), "=r"(r[1]), "=r"(r[2]), "=r"(r[3]) : "r"(addr));
}
__device__ __forceinline__ void mma_f16(float* c, const uint32_t* a,
                                        const uint32_t* b) {
    asm volatile(
        "mma.sync.aligned.m16n8k16.row.col.f32.f16.f16.f32 "
        "{%0,%1,%2,%3}, {%4,%5,%6,%7}, {%8,%9}, {%0,%1,%2,%3};"
        : "+f"(c[0]), "+f"(c[1]), "+f"(c[2]), "+f"(c[3])
        : "r"(a[0]), "r"(a[1]), "r"(a[2]), "r"(a[3]), "r"(b[0]), "r"(b[1]));
}
__device__ __forceinline__ void cp16(uint32_t daddr, const void* saddr) {
    asm volatile("cp.async.cg.shared.global [%0], [%1], 16;"
                 :: "r"(daddr), "l"(saddr));
}
__device__ __forceinline__ float ex2(float x) {
    float y;
    asm("ex2.approx.f32 %0, %1;" : "=f"(y) : "f"(x));
    return y;
}
__device__ __forceinline__ uint32_t h2u(__half2 v) {
    return *reinterpret_cast<uint32_t*>(&v);
}

// ---------------- LayerNorm (fp16 out) -------------------------------------
__global__ __launch_bounds__(256) void ln_kernel(
    const float* __restrict__ x, const float* __restrict__ gamma,
    const float* __restrict__ beta, __half* __restrict__ out)
{
    int row = blockIdx.x;
    int tid = threadIdx.x;
    const float4* xr = reinterpret_cast<const float4*>(x + (size_t)row * DIM);
    float4 v = xr[tid];
    float s1 = v.x + v.y + v.z + v.w;
    float s2 = v.x * v.x + v.y * v.y + v.z * v.z + v.w * v.w;
    #pragma unroll
    for (int o = 16; o > 0; o >>= 1) {
        s1 += __shfl_xor_sync(0xffffffffu, s1, o);
        s2 += __shfl_xor_sync(0xffffffffu, s2, o);
    }
    __shared__ float sh1[8], sh2[8];
    int w = tid >> 5, l = tid & 31;
    if (l == 0) { sh1[w] = s1; sh2[w] = s2; }
    __syncthreads();
    s1 = 0.f; s2 = 0.f;
    #pragma unroll
    for (int i = 0; i < 8; i++) { s1 += sh1[i]; s2 += sh2[i]; }
    float mu  = s1 * (1.0f / DIM);
    float var = s2 * (1.0f / DIM) - mu * mu;
    float r   = rsqrtf(var + 1e-5f);
    float4 gv = reinterpret_cast<const float4*>(gamma)[tid];
    float4 bv = reinterpret_cast<const float4*>(beta)[tid];
    uint2 u;
    u.x = h2u(__floats2half2_rn((v.x - mu) * r * gv.x + bv.x,
                                (v.y - mu) * r * gv.y + bv.y));
    u.y = h2u(__floats2half2_rn((v.z - mu) * r * gv.z + bv.z,
                                (v.w - mu) * r * gv.w + bv.w));
    *reinterpret_cast<uint2*>(out + (size_t)row * DIM + tid * 4) = u;
}

// ---------------- transpose weights: [R,C] fp32 -> [C,R] fp16 --------------
__global__ __launch_bounds__(256) void transT_kernel(
    const float* __restrict__ in, __half* __restrict__ out, int R, int C)
{
    __shared__ float t[32][33];
    int tx = threadIdx.x, ty = threadIdx.y;   // block (32,8)
    int x = blockIdx.x * 32 + tx;
    #pragma unroll
    for (int j = 0; j < 32; j += 8)
        t[ty + j][tx] = in[(size_t)(blockIdx.y * 32 + ty + j) * C + x];
    __syncthreads();
    #pragma unroll
    for (int j = 0; j < 32; j += 8) {
        size_t idx = (size_t)(blockIdx.x * 32 + ty + j) * R + blockIdx.y * 32 + tx;
        out[idx] = __float2half(t[tx][ty + j]);
    }
}

// ---------------- fp16 GEMM (3-stage cp.async, 128x128x64, 2 CTA/SM) -------
// A [M,K] fp16 row-major; B [N,K] fp16 row-major (= W^T). fp32 accumulate.
// MODE 0: fp32 C = acc + bias; MODE 1: fp32 C = acc + bias + res;
// MODE 2: fp16 Oh = relu(acc + bias); MODE 3: fp16 Oh = acc + bias.
#define STAGE_BYTES 32768
#define GEMM_STAGES 3
#define GEMM_SMEM   (GEMM_STAGES * STAGE_BYTES)

template<int MODE>
__global__ __launch_bounds__(256, 2) void gemm_f16(
    const __half* __restrict__ A, const __half* __restrict__ B,
    const float* __restrict__ bias, const float* __restrict__ res,
    float* __restrict__ C, __half* __restrict__ Oh, int M, int N, int K)
{
    extern __shared__ char smem[];
    const uint32_t sbase = smem_u32(smem);
    const int tid = threadIdx.x;
    const int wid = tid >> 5, lane = tid & 31;
    const int m0 = blockIdx.y * 128, n0 = blockIdx.x * 128;
    const int wm = (wid & 1) * 64;
    const int wn = (wid >> 1) * 32;

    float acc[4][4][4];
    #pragma unroll
    for (int a = 0; a < 4; a++)
        #pragma unroll
        for (int b = 0; b < 4; b++)
            #pragma unroll
            for (int c = 0; c < 4; c++) acc[a][b][c] = 0.f;

    const __half* Ab = A + (size_t)m0 * K;
    const __half* Bb = B + (size_t)n0 * K;
    const int row_l = tid >> 3, c_l = tid & 7;

    auto issue = [&](int i) {
        int k0 = i << 6;
        uint32_t st = sbase + (uint32_t)(i % GEMM_STAGES) * STAGE_BYTES;
        #pragma unroll
        for (int op = 0; op < 2; op++) {
            const __half* src = (op ? Bb : Ab) + k0;
            uint32_t dst = st + op * 16384;
            #pragma unroll
            for (int p = 0; p < 4; p++) {
                int row = row_l + p * 32;
                cp16(dst + SWZ128((uint32_t)(row * 128 + c_l * 16)),
                     src + (size_t)row * K + c_l * 8);
            }
        }
        asm volatile("cp.async.commit_group;" ::: "memory");
    };

    const int NC = K >> 6;
    issue(0); issue(1);
    for (int i = 0; i < NC; i++) {
        if (i + 1 < NC) { asm volatile("cp.async.wait_group 1;" ::: "memory"); }
        else            { asm volatile("cp.async.wait_group 0;" ::: "memory"); }
        __syncthreads();
        if (i + 2 < NC) issue(i + 2);

        uint32_t st = sbase + (uint32_t)(i % GEMM_STAGES) * STAGE_BYTES;
        uint32_t sA = st, sB = st + 16384;

        #pragma unroll
        for (int ks = 0; ks < 4; ks++) {
            uint32_t af[4][4];
            #pragma unroll
            for (int mi = 0; mi < 4; mi++) {
                int row = wm + mi * 16 + (lane & 15);
                int colb = ks * 32 + (lane >> 4) * 16;
                ldsm_x4(af[mi], sA + SWZ128((uint32_t)(row * 128 + colb)));
            }
            uint32_t bf[2][4];   // paired: bf[ni2] = frags for ni=2*ni2, 2*ni2+1
            #pragma unroll
            for (int ni2 = 0; ni2 < 2; ni2++) {
                int row = wn + ni2 * 16 + ((lane & 16) >> 1) + (lane & 7);
                int colb = ks * 32 + (lane & 8) * 2;
                ldsm_x4(bf[ni2], sB + SWZ128((uint32_t)(row * 128 + colb)));
            }
            #pragma unroll
            for (int mi = 0; mi < 4; mi++)
                #pragma unroll
                for (int ni2 = 0; ni2 < 2; ni2++) {
                    mma_f16(acc[mi][2 * ni2],     af[mi], bf[ni2]);
                    mma_f16(acc[mi][2 * ni2 + 1], af[mi], bf[ni2] + 2);
                }
        }
    }

    #pragma unroll
    for (int mi = 0; mi < 4; mi++) {
        #pragma unroll
        for (int h = 0; h < 2; h++) {
            int row = m0 + wm + mi * 16 + (lane >> 2) + h * 8;
            #pragma unroll
            for (int ni = 0; ni < 4; ni++) {
                int col = n0 + wn + ni * 8 + (lane & 3) * 2;
                float2 bb = *reinterpret_cast<const float2*>(bias + col);
                float vx = acc[mi][ni][h * 2 + 0] + bb.x;
                float vy = acc[mi][ni][h * 2 + 1] + bb.y;
                if (MODE == 1) {
                    float2 rv = *reinterpret_cast<const float2*>(
                        res + (size_t)row * N + col);
                    vx += rv.x; vy += rv.y;
                }
                if (MODE == 2) { vx = fmaxf(vx, 0.f); vy = fmaxf(vy, 0.f); }
                if (MODE == 2 || MODE == 3) {
                    *reinterpret_cast<uint32_t*>(Oh + (size_t)row * N + col) =
                        h2u(__floats2half2_rn(vx, vy));
                } else {
                    *reinterpret_cast<float2*>(C + (size_t)row * N + col) =
                        make_float2(vx, vy);
                }
            }
        }
    }
}

// ---------------- fp16 tensor-core causal flash attention ------------------
// grid (SEQ/128, NH, BATCH), 256 threads (8 warps x 16 query rows), 2 CTA/SM.
// Softmax scale pre-folded into Q (fp16). Paired ldsm_x4 for K and V frags.
#define ATTN_SMEM (2 * 16384)   // double-buffered (K 8KB + V 8KB)

__global__ __launch_bounds__(256, 2) void attn_mma(
    const __half* __restrict__ qkv, __half* __restrict__ y)
{
    extern __shared__ char smem[];
    const uint32_t sb = smem_u32(smem);

    int qt = gridDim.x - 1 - blockIdx.x;   // heavy blocks first
    int h = blockIdx.y, b = blockIdx.z;
    int q0 = qt * 128;
    int tid = threadIdx.x, wid = tid >> 5, lane = tid & 31;
    const __half* base = qkv + (size_t)b * SEQ * 3 * DIM;
    const int r = lane >> 2, cb = (lane & 3) * 2;
    const __half2 QSC2 = __float2half2_rn(0.1803368801f);  // 0.125*log2(e)

    // Q fragments (fp16 A-operand layout), softmax scale pre-folded
    uint32_t qf[4][4];
    #pragma unroll
    for (int ks = 0; ks < 4; ks++) {
        #pragma unroll
        for (int fr = 0; fr < 4; fr++) {
            int row = q0 + wid * 16 + r + (fr & 1) * 8;
            int col = ks * 16 + cb + (fr >> 1) * 8;
            __half2 v = *reinterpret_cast<const __half2*>(
                base + (size_t)row * 3 * DIM + h * HD + col);
            qf[ks][fr] = h2u(__hmul2(v, QSC2));
        }
    }

    auto issueKV = [&](int kb) {
        uint32_t stg = sb + (uint32_t)(kb & 1) * 16384;
        #pragma unroll
        for (int p = 0; p < 4; p++) {
            int idx = p * 256 + tid;              // 0..1023
            int op = idx >> 9, rem = idx & 511;
            int row = rem >> 3, c = rem & 7;
            const __half* src = base + (size_t)(kb * 64 + row) * 3 * DIM
                              + (op ? 2 * DIM : DIM) + h * HD + c * 8;
            cp16(stg + op * 8192 + SWZ128((uint32_t)(row * 128 + c * 16)), src);
        }
        asm volatile("cp.async.commit_group;" ::: "memory");
    };

    float m0 = -1e30f, m1 = -1e30f, l0 = 0.f, l1 = 0.f;
    float o[8][4];
    #pragma unroll
    for (int ni = 0; ni < 8; ni++)
        #pragma unroll
        for (int c = 0; c < 4; c++) o[ni][c] = 0.f;

    const int last = 2 * qt + 1;
    issueKV(0);
    for (int kb = 0; kb <= last; kb++) {
        asm volatile("cp.async.wait_group 0;" ::: "memory");
        __syncthreads();   // buffer kb ready; all warps done with buffer kb-1
        if (kb < last) issueKV(kb + 1);   // overlaps with MMAs below

        uint32_t sK = sb + (uint32_t)(kb & 1) * 16384;
        uint32_t sV = sK + 8192;

        // S = Q K^T (fp16, scale already in Q -> exp2 domain)
        float s[8][4];
        #pragma unroll
        for (int ni = 0; ni < 8; ni++)
            #pragma unroll
            for (int c = 0; c < 4; c++) s[ni][c] = 0.f;
        #pragma unroll
        for (int ks = 0; ks < 4; ks++) {
            #pragma unroll
            for (int ni2 = 0; ni2 < 4; ni2++) {
                int krow = ni2 * 16 + ((lane & 16) >> 1) + (lane & 7);
                int kcolb = ks * 32 + (lane & 8) * 2;
                uint32_t kf[4];
                ldsm_x4(kf, sK + SWZ128((uint32_t)(krow * 128 + kcolb)));
                mma_f16(s[2 * ni2],     qf[ks], kf);
                mma_f16(s[2 * ni2 + 1], qf[ks], kf + 2);
            }
        }

        // causal mask (tiles crossing the diagonal for this warp)
        if (kb * 64 + 63 > q0 + wid * 16) {
            int rg0 = q0 + wid * 16 + r, rg1 = rg0 + 8;
            int cgb = kb * 64;
            #pragma unroll
            for (int ni = 0; ni < 8; ni++) {
                int c0 = cgb + ni * 8 + cb;
                if (c0     > rg0) s[ni][0] = -1e30f;
                if (c0 + 1 > rg0) s[ni][1] = -1e30f;
                if (c0     > rg1) s[ni][2] = -1e30f;
                if (c0 + 1 > rg1) s[ni][3] = -1e30f;
            }
        }

        // online softmax (exp2 domain)
        float nm0 = -1e30f, nm1 = -1e30f;
        #pragma unroll
        for (int ni = 0; ni < 8; ni++) {
            nm0 = fmaxf(nm0, fmaxf(s[ni][0], s[ni][1]));
            nm1 = fmaxf(nm1, fmaxf(s[ni][2], s[ni][3]));
        }
        nm0 = fmaxf(nm0, __shfl_xor_sync(0xffffffffu, nm0, 1));
        nm0 = fmaxf(nm0, __shfl_xor_sync(0xffffffffu, nm0, 2));
        nm1 = fmaxf(nm1, __shfl_xor_sync(0xffffffffu, nm1, 1));
        nm1 = fmaxf(nm1, __shfl_xor_sync(0xffffffffu, nm1, 2));
        nm0 = fmaxf(nm0, m0);
        nm1 = fmaxf(nm1, m1);
        float sc0 = ex2(m0 - nm0), sc1 = ex2(m1 - nm1);
        m0 = nm0; m1 = nm1;
        float ls0 = 0.f, ls1 = 0.f;
        #pragma unroll
        for (int ni = 0; ni < 8; ni++) {
            s[ni][0] = ex2(s[ni][0] - nm0);
            s[ni][1] = ex2(s[ni][1] - nm0);
            s[ni][2] = ex2(s[ni][2] - nm1);
            s[ni][3] = ex2(s[ni][3] - nm1);
            ls0 += s[ni][0] + s[ni][1];
            ls1 += s[ni][2] + s[ni][3];
        }
        ls0 += __shfl_xor_sync(0xffffffffu, ls0, 1);
        ls0 += __shfl_xor_sync(0xffffffffu, ls0, 2);
        ls1 += __shfl_xor_sync(0xffffffffu, ls1, 1);
        ls1 += __shfl_xor_sync(0xffffffffu, ls1, 2);
        l0 = l0 * sc0 + ls0;
        l1 = l1 * sc1 + ls1;
        #pragma unroll
        for (int ni = 0; ni < 8; ni++) {
            o[ni][0] *= sc0; o[ni][1] *= sc0;
            o[ni][2] *= sc1; o[ni][3] *= sc1;
        }

        // P fragments -> fp16 (A-operand layout direct from S accumulator)
        uint32_t ph[4][4];
        #pragma unroll
        for (int t = 0; t < 4; t++) {
            ph[t][0] = h2u(__floats2half2_rn(s[2 * t][0],     s[2 * t][1]));
            ph[t][1] = h2u(__floats2half2_rn(s[2 * t][2],     s[2 * t][3]));
            ph[t][2] = h2u(__floats2half2_rn(s[2 * t + 1][0], s[2 * t + 1][1]));
            ph[t][3] = h2u(__floats2half2_rn(s[2 * t + 1][2], s[2 * t + 1][3]));
        }

        // O += P V (fp16); V loaded transposed, paired x4
        #pragma unroll
        for (int t = 0; t < 4; t++) {
            #pragma unroll
            for (int ni2 = 0; ni2 < 4; ni2++) {
                int vrow = t * 16 + (lane & 15);
                int vcolb = ni2 * 32 + (lane & 16);
                uint32_t vf[4];
                ldsm_x4t(vf, sV + SWZ128((uint32_t)(vrow * 128 + vcolb)));
                mma_f16(o[2 * ni2],     ph[t], vf);
                mma_f16(o[2 * ni2 + 1], ph[t], vf + 2);
            }
        }
    }

    // normalize + fp16 output
    float il0 = 1.0f / l0, il1 = 1.0f / l1;
    int row0 = b * SEQ + q0 + wid * 16 + r;
    #pragma unroll
    for (int ni = 0; ni < 8; ni++) {
        int col = h * HD + ni * 8 + cb;
        *reinterpret_cast<uint32_t*>(y + (size_t)row0 * DIM + col) =
            h2u(__floats2half2_rn(o[ni][0] * il0, o[ni][1] * il0));
        *reinterpret_cast<uint32_t*>(y + (size_t)(row0 + 8) * DIM + col) =
            h2u(__floats2half2_rn(o[ni][2] * il1, o[ni][3] * il1));
    }
}

// ---------------- launch ---------------------------------------------------
extern "C" void kernel_launch(void* const* d_in, const int* in_sizes, int n_in,
                              void* d_out, int out_size)
{
    const float* x      = (const float*)d_in[0];
    const float* ln1_g  = (const float*)d_in[1];
    const float* ln1_b  = (const float*)d_in[2];
    const float* ln2_g  = (const float*)d_in[3];
    const float* ln2_b  = (const float*)d_in[4];
    const float* W_qkv  = (const float*)d_in[5];
    const float* b_qkv  = (const float*)d_in[6];
    const float* W_proj = (const float*)d_in[7];
    const float* b_proj = (const float*)d_in[8];
    const float* W_fc   = (const float*)d_in[9];
    const float* b_fc   = (const float*)d_in[10];
    const float* W_out  = (const float*)d_in[11];
    const float* b_out  = (const float*)d_in[12];
    float* out = (float*)d_out;

    float *x1;
    __half *qkv, *h, *y, *act, *wT;
    cudaGetSymbolAddress((void**)&x1,  g_x1);
    cudaGetSymbolAddress((void**)&qkv, g_qkv);
    cudaGetSymbolAddress((void**)&h,   g_h);
    cudaGetSymbolAddress((void**)&y,   g_y);
    cudaGetSymbolAddress((void**)&act, g_act);
    cudaGetSymbolAddress((void**)&wT,  g_wT);

    cudaFuncSetAttribute(gemm_f16<1>,
        cudaFuncAttributeMaxDynamicSharedMemorySize, GEMM_SMEM);
    cudaFuncSetAttribute(gemm_f16<2>,
        cudaFuncAttributeMaxDynamicSharedMemorySize, GEMM_SMEM);
    cudaFuncSetAttribute(gemm_f16<3>,
        cudaFuncAttributeMaxDynamicSharedMemorySize, GEMM_SMEM);
    cudaFuncSetAttribute(attn_mma,
        cudaFuncAttributeMaxDynamicSharedMemorySize, ATTN_SMEM);

    dim3 tb(32, 8);

    // 1) LN1 -> h (fp16)
    ln_kernel<<<NTOK, 256>>>(x, ln1_g, ln1_b, h);

    // 2) qkv = h @ W_qkv + b_qkv (fp16 out)
    transT_kernel<<<dim3(3 * DIM / 32, DIM / 32), tb>>>(W_qkv, wT, DIM, 3 * DIM);
    gemm_f16<3><<<dim3(3 * DIM / 128, NTOK / 128), 256, GEMM_SMEM>>>(
        h, wT, b_qkv, nullptr, nullptr, qkv, NTOK, 3 * DIM, DIM);

    // 3) attention -> y (fp16)
    attn_mma<<<dim3(SEQ / 128, NH, BATCH), 256, ATTN_SMEM>>>(qkv, y);

    // 4) x1 = x + y @ W_proj + b_proj
    transT_kernel<<<dim3(DIM / 32, DIM / 32), tb>>>(W_proj, wT, DIM, DIM);
    gemm_f16<1><<<dim3(DIM / 128, NTOK / 128), 256, GEMM_SMEM>>>(
        y, wT, b_proj, x, x1, nullptr, NTOK, DIM, DIM);

    // 5) LN2 -> h (fp16)
    ln_kernel<<<NTOK, 256>>>(x1, ln2_g, ln2_b, h);

    // 6) act = relu(h @ W_fc + b_fc) (fp16)
    transT_kernel<<<dim3(4 * DIM / 32, DIM / 32), tb>>>(W_fc, wT, DIM, 4 * DIM);
    gemm_f16<2><<<dim3(4 * DIM / 128, NTOK / 128), 256, GEMM_SMEM>>>(
        h, wT, b_fc, nullptr, nullptr, act, NTOK, 4 * DIM, DIM);

    // 7) out = x1 + act @ W_out + b_out
    transT_kernel<<<dim3(DIM / 32, 4 * DIM / 32), tb>>>(W_out, wT, 4 * DIM, DIM);
    gemm_f16<1><<<dim3(DIM / 128, NTOK / 128), 256, GEMM_SMEM>>>(
        act, wT, b_out, x1, out, nullptr, NTOK, DIM, 4 * DIM);
}

// round 12
// speedup vs baseline: 7.8200x; 1.0104x over previous
#include <cuda_runtime.h>
#include <cuda_fp16.h>
#include <math.h>
#include <stdint.h>

#define BATCH 2
#define SEQ   2048
#define DIM   1024
#define NH    16
#define HD    64
#define NTOK  (BATCH * SEQ)   // 4096

// ---------------- scratch (device globals) ---------------------------------
__device__ float  g_x1 [(size_t)NTOK * DIM];       // residual after proj
__device__ __half g_qkv[(size_t)NTOK * 3 * DIM];   // qkv fp16
__device__ __half g_h  [(size_t)NTOK * DIM];       // LN out fp16
__device__ __half g_y  [(size_t)NTOK * DIM];       // attn out fp16
__device__ __half g_act[(size_t)NTOK * 4 * DIM];   // relu(fc) fp16
__device__ __half g_wq [(size_t)3 * DIM * DIM];    // W_qkv^T fp16
__device__ __half g_wp [(size_t)DIM * DIM];        // W_proj^T fp16
__device__ __half g_wf [(size_t)4 * DIM * DIM];    // W_fc^T fp16
__device__ __half g_wo [(size_t)4 * DIM * DIM];    // W_out^T fp16

// ======================= helpers ===========================================
__device__ __forceinline__ uint32_t smem_u32(const void* p) {
    uint32_t a;
    asm("{ .reg .u64 t; cvta.to.shared.u64 t, %1; cvt.u32.u64 %0, t; }"
        : "=r"(a) : "l"(p));
    return a;
}
#define SWZ128(o) ((o) ^ (((o) >> 3) & 0x70))

__device__ __forceinline__ void ldsm_x4(uint32_t* r, uint32_t addr) {
    asm volatile("ldmatrix.sync.aligned.m8n8.x4.shared.b16 {%0,%1,%2,%3}, [%4];"
                 : "=r"(r[0]), "=r"(r[1]), "=r"(r[2]), "=r"(r[3]) : "r"(addr));
}
__device__ __forceinline__ void ldsm_x4t(uint32_t* r, uint32_t addr) {
    asm volatile("ldmatrix.sync.aligned.m8n8.x4.trans.shared.b16 {%0,%1,%2,%3}, [%4];"
                 : "=r"(r[0]), "=r"(r[1]), "=r"(r[2]), "=r"(r[3]) : "r"(addr));
}
__device__ __forceinline__ void mma_f16(float* c, const uint32_t* a,
                                        const uint32_t* b) {
    asm volatile(
        "mma.sync.aligned.m16n8k16.row.col.f32.f16.f16.f32 "
        "{%0,%1,%2,%3}, {%4,%5,%6,%7}, {%8,%9}, {%0,%1,%2,%3};"
        : "+f"(c[0]), "+f"(c[1]), "+f"(c[2]), "+f"(c[3])
        : "r"(a[0]), "r"(a[1]), "r"(a[2]), "r"(a[3]), "r"(b[0]), "r"(b[1]));
}
__device__ __forceinline__ void cp16(uint32_t daddr, const void* saddr) {
    asm volatile("cp.async.cg.shared.global [%0], [%1], 16;"
                 :: "r"(daddr), "l"(saddr));
}
__device__ __forceinline__ float ex2(float x) {
    float y;
    asm("ex2.approx.f32 %0, %1;" : "=f"(y) : "f"(x));
    return y;
}
__device__ __forceinline__ uint32_t h2u(__half2 v) {
    return *reinterpret_cast<uint32_t*>(&v);
}

// ---------------- LayerNorm (fp16 out) -------------------------------------
__global__ __launch_bounds__(256) void ln_kernel(
    const float* __restrict__ x, const float* __restrict__ gamma,
    const float* __restrict__ beta, __half* __restrict__ out)
{
    int row = blockIdx.x;
    int tid = threadIdx.x;
    const float4* xr = reinterpret_cast<const float4*>(x + (size_t)row * DIM);
    float4 v = xr[tid];
    float s1 = v.x + v.y + v.z + v.w;
    float s2 = v.x * v.x + v.y * v.y + v.z * v.z + v.w * v.w;
    #pragma unroll
    for (int o = 16; o > 0; o >>= 1) {
        s1 += __shfl_xor_sync(0xffffffffu, s1, o);
        s2 += __shfl_xor_sync(0xffffffffu, s2, o);
    }
    __shared__ float sh1[8], sh2[8];
    int w = tid >> 5, l = tid & 31;
    if (l == 0) { sh1[w] = s1; sh2[w] = s2; }
    __syncthreads();
    s1 = 0.f; s2 = 0.f;
    #pragma unroll
    for (int i = 0; i < 8; i++) { s1 += sh1[i]; s2 += sh2[i]; }
    float mu  = s1 * (1.0f / DIM);
    float var = s2 * (1.0f / DIM) - mu * mu;
    float r   = rsqrtf(var + 1e-5f);
    float4 gv = reinterpret_cast<const float4*>(gamma)[tid];
    float4 bv = reinterpret_cast<const float4*>(beta)[tid];
    uint2 u;
    u.x = h2u(__floats2half2_rn((v.x - mu) * r * gv.x + bv.x,
                                (v.y - mu) * r * gv.y + bv.y));
    u.y = h2u(__floats2half2_rn((v.z - mu) * r * gv.z + bv.z,
                                (v.w - mu) * r * gv.w + bv.w));
    *reinterpret_cast<uint2*>(out + (size_t)row * DIM + tid * 4) = u;
}

// ---------------- fused weight transposes: 4 weights in one launch ---------
// tiles: qkv 96x32=3072 | proj 32x32=1024 | fc 128x32=4096 | out 32x128=4096
__global__ __launch_bounds__(256) void transT_all(
    const float* __restrict__ W0, const float* __restrict__ W1,
    const float* __restrict__ W2, const float* __restrict__ W3,
    __half* __restrict__ O0, __half* __restrict__ O1,
    __half* __restrict__ O2, __half* __restrict__ O3)
{
    int t = blockIdx.x;
    const float* in; __half* out; int R, C;
    if (t < 3072)      { in = W0; out = O0; R = DIM;     C = 3 * DIM; }
    else if (t < 4096) { in = W1; out = O1; R = DIM;     C = DIM;     t -= 3072; }
    else if (t < 8192) { in = W2; out = O2; R = DIM;     C = 4 * DIM; t -= 4096; }
    else               { in = W3; out = O3; R = 4 * DIM; C = DIM;     t -= 8192; }
    int tilesX = C >> 5;
    int bx = t % tilesX, by = t / tilesX;

    __shared__ float tt[32][33];
    int tx = threadIdx.x & 31, ty = threadIdx.x >> 5;   // 256 thr = (32,8)
    int x = bx * 32 + tx;
    #pragma unroll
    for (int j = 0; j < 32; j += 8)
        tt[ty + j][tx] = in[(size_t)(by * 32 + ty + j) * C + x];
    __syncthreads();
    #pragma unroll
    for (int j = 0; j < 32; j += 8) {
        size_t idx = (size_t)(bx * 32 + ty + j) * R + by * 32 + tx;
        out[idx] = __float2half(tt[tx][ty + j]);
    }
}

// ---------------- fp16 GEMM (3-stage cp.async, 128x128x64, 2 CTA/SM) -------
#define STAGE_BYTES 32768
#define GEMM_STAGES 3
#define GEMM_SMEM   (GEMM_STAGES * STAGE_BYTES)

template<int MODE>   // 0: fp32+bias; 1: fp32+bias+res; 2: fp16 relu; 3: fp16
__global__ __launch_bounds__(256, 2) void gemm_f16(
    const __half* __restrict__ A, const __half* __restrict__ B,
    const float* __restrict__ bias, const float* __restrict__ res,
    float* __restrict__ C, __half* __restrict__ Oh, int M, int N, int K)
{
    extern __shared__ char smem[];
    const uint32_t sbase = smem_u32(smem);
    const int tid = threadIdx.x;
    const int wid = tid >> 5, lane = tid & 31;
    const int m0 = blockIdx.y * 128, n0 = blockIdx.x * 128;
    const int wm = (wid & 1) * 64;
    const int wn = (wid >> 1) * 32;

    float acc[4][4][4];
    #pragma unroll
    for (int a = 0; a < 4; a++)
        #pragma unroll
        for (int b = 0; b < 4; b++)
            #pragma unroll
            for (int c = 0; c < 4; c++) acc[a][b][c] = 0.f;

    const __half* Ab = A + (size_t)m0 * K;
    const __half* Bb = B + (size_t)n0 * K;
    const int row_l = tid >> 3, c_l = tid & 7;

    auto issue = [&](int i) {
        int k0 = i << 6;
        uint32_t st = sbase + (uint32_t)(i % GEMM_STAGES) * STAGE_BYTES;
        #pragma unroll
        for (int op = 0; op < 2; op++) {
            const __half* src = (op ? Bb : Ab) + k0;
            uint32_t dst = st + op * 16384;
            #pragma unroll
            for (int p = 0; p < 4; p++) {
                int row = row_l + p * 32;
                cp16(dst + SWZ128((uint32_t)(row * 128 + c_l * 16)),
                     src + (size_t)row * K + c_l * 8);
            }
        }
        asm volatile("cp.async.commit_group;" ::: "memory");
    };

    const int NC = K >> 6;
    issue(0); issue(1);
    for (int i = 0; i < NC; i++) {
        if (i + 1 < NC) { asm volatile("cp.async.wait_group 1;" ::: "memory"); }
        else            { asm volatile("cp.async.wait_group 0;" ::: "memory"); }
        __syncthreads();
        if (i + 2 < NC) issue(i + 2);

        uint32_t st = sbase + (uint32_t)(i % GEMM_STAGES) * STAGE_BYTES;
        uint32_t sA = st, sB = st + 16384;

        #pragma unroll
        for (int ks = 0; ks < 4; ks++) {
            uint32_t af[4][4];
            #pragma unroll
            for (int mi = 0; mi < 4; mi++) {
                int row = wm + mi * 16 + (lane & 15);
                int colb = ks * 32 + (lane >> 4) * 16;
                ldsm_x4(af[mi], sA + SWZ128((uint32_t)(row * 128 + colb)));
            }
            uint32_t bf[2][4];
            #pragma unroll
            for (int ni2 = 0; ni2 < 2; ni2++) {
                int row = wn + ni2 * 16 + ((lane & 16) >> 1) + (lane & 7);
                int colb = ks * 32 + (lane & 8) * 2;
                ldsm_x4(bf[ni2], sB + SWZ128((uint32_t)(row * 128 + colb)));
            }
            #pragma unroll
            for (int mi = 0; mi < 4; mi++)
                #pragma unroll
                for (int ni2 = 0; ni2 < 2; ni2++) {
                    mma_f16(acc[mi][2 * ni2],     af[mi], bf[ni2]);
                    mma_f16(acc[mi][2 * ni2 + 1], af[mi], bf[ni2] + 2);
                }
        }
    }

    #pragma unroll
    for (int mi = 0; mi < 4; mi++) {
        #pragma unroll
        for (int h = 0; h < 2; h++) {
            int row = m0 + wm + mi * 16 + (lane >> 2) + h * 8;
            #pragma unroll
            for (int ni = 0; ni < 4; ni++) {
                int col = n0 + wn + ni * 8 + (lane & 3) * 2;
                float2 bb = *reinterpret_cast<const float2*>(bias + col);
                float vx = acc[mi][ni][h * 2 + 0] + bb.x;
                float vy = acc[mi][ni][h * 2 + 1] + bb.y;
                if (MODE == 1) {
                    float2 rv = *reinterpret_cast<const float2*>(
                        res + (size_t)row * N + col);
                    vx += rv.x; vy += rv.y;
                }
                if (MODE == 2) { vx = fmaxf(vx, 0.f); vy = fmaxf(vy, 0.f); }
                if (MODE == 2 || MODE == 3) {
                    *reinterpret_cast<uint32_t*>(Oh + (size_t)row * N + col) =
                        h2u(__floats2half2_rn(vx, vy));
                } else {
                    *reinterpret_cast<float2*>(C + (size_t)row * N + col) =
                        make_float2(vx, vy);
                }
            }
        }
    }
}

// ---------------- fp16 tensor-core causal flash attention ------------------
// grid (SEQ/128, NH, BATCH), 256 threads (8 warps x 16 query rows), 2 CTA/SM.
// p = exp2 computed in fp16x2 (halves MUFU); row-sum l via ones-column MMA.
#define ATTN_SMEM (2 * 16384)   // double-buffered (K 8KB + V 8KB)

__global__ __launch_bounds__(256, 2) void attn_mma(
    const __half* __restrict__ qkv, __half* __restrict__ y)
{
    extern __shared__ char smem[];
    const uint32_t sb = smem_u32(smem);

    int qt = gridDim.x - 1 - blockIdx.x;   // heavy blocks first
    int h = blockIdx.y, b = blockIdx.z;
    int q0 = qt * 128;
    int tid = threadIdx.x, wid = tid >> 5, lane = tid & 31;
    const __half* base = qkv + (size_t)b * SEQ * 3 * DIM;
    const int r = lane >> 2, cb = (lane & 3) * 2;
    const __half2 QSC2 = __float2half2_rn(0.1803368801f);  // 0.125*log2(e)
    const uint32_t ONES[2] = {0x3C003C00u, 0x3C003C00u};   // half2(1,1) x2

    // Q fragments (fp16 A-operand layout), softmax scale pre-folded
    uint32_t qf[4][4];
    #pragma unroll
    for (int ks = 0; ks < 4; ks++) {
        #pragma unroll
        for (int fr = 0; fr < 4; fr++) {
            int row = q0 + wid * 16 + r + (fr & 1) * 8;
            int col = ks * 16 + cb + (fr >> 1) * 8;
            __half2 v = *reinterpret_cast<const __half2*>(
                base + (size_t)row * 3 * DIM + h * HD + col);
            qf[ks][fr] = h2u(__hmul2(v, QSC2));
        }
    }

    auto issueKV = [&](int kb) {
        uint32_t stg = sb + (uint32_t)(kb & 1) * 16384;
        #pragma unroll
        for (int p = 0; p < 4; p++) {
            int idx = p * 256 + tid;              // 0..1023
            int op = idx >> 9, rem = idx & 511;
            int row = rem >> 3, c = rem & 7;
            const __half* src = base + (size_t)(kb * 64 + row) * 3 * DIM
                              + (op ? 2 * DIM : DIM) + h * HD + c * 8;
            cp16(stg + op * 8192 + SWZ128((uint32_t)(row * 128 + c * 16)), src);
        }
        asm volatile("cp.async.commit_group;" ::: "memory");
    };

    float m0 = -1e30f, m1 = -1e30f;
    float lacc[4] = {0.f, 0.f, 0.f, 0.f};   // ones-column accumulator
    float o[8][4];
    #pragma unroll
    for (int ni = 0; ni < 8; ni++)
        #pragma unroll
        for (int c = 0; c < 4; c++) o[ni][c] = 0.f;

    const int last = 2 * qt + 1;
    issueKV(0);
    for (int kb = 0; kb <= last; kb++) {
        asm volatile("cp.async.wait_group 0;" ::: "memory");
        __syncthreads();
        if (kb < last) issueKV(kb + 1);

        uint32_t sK = sb + (uint32_t)(kb & 1) * 16384;
        uint32_t sV = sK + 8192;

        // S = Q K^T (fp16, scale pre-folded -> exp2 domain)
        float s[8][4];
        #pragma unroll
        for (int ni = 0; ni < 8; ni++)
            #pragma unroll
            for (int c = 0; c < 4; c++) s[ni][c] = 0.f;
        #pragma unroll
        for (int ks = 0; ks < 4; ks++) {
            #pragma unroll
            for (int ni2 = 0; ni2 < 4; ni2++) {
                int krow = ni2 * 16 + ((lane & 16) >> 1) + (lane & 7);
                int kcolb = ks * 32 + (lane & 8) * 2;
                uint32_t kf[4];
                ldsm_x4(kf, sK + SWZ128((uint32_t)(krow * 128 + kcolb)));
                mma_f16(s[2 * ni2],     qf[ks], kf);
                mma_f16(s[2 * ni2 + 1], qf[ks], kf + 2);
            }
        }

        // causal mask (tiles crossing the diagonal for this warp)
        if (kb * 64 + 63 > q0 + wid * 16) {
            int rg0 = q0 + wid * 16 + r, rg1 = rg0 + 8;
            int cgb = kb * 64;
            #pragma unroll
            for (int ni = 0; ni < 8; ni++) {
                int c0 = cgb + ni * 8 + cb;
                if (c0     > rg0) s[ni][0] = -1e30f;
                if (c0 + 1 > rg0) s[ni][1] = -1e30f;
                if (c0     > rg1) s[ni][2] = -1e30f;
                if (c0 + 1 > rg1) s[ni][3] = -1e30f;
            }
        }

        // online softmax: row max update
        float nm0 = -1e30f, nm1 = -1e30f;
        #pragma unroll
        for (int ni = 0; ni < 8; ni++) {
            nm0 = fmaxf(nm0, fmaxf(s[ni][0], s[ni][1]));
            nm1 = fmaxf(nm1, fmaxf(s[ni][2], s[ni][3]));
        }
        nm0 = fmaxf(nm0, __shfl_xor_sync(0xffffffffu, nm0, 1));
        nm0 = fmaxf(nm0, __shfl_xor_sync(0xffffffffu, nm0, 2));
        nm1 = fmaxf(nm1, __shfl_xor_sync(0xffffffffu, nm1, 1));
        nm1 = fmaxf(nm1, __shfl_xor_sync(0xffffffffu, nm1, 2));
        nm0 = fmaxf(nm0, m0);
        nm1 = fmaxf(nm1, m1);
        float sc0 = ex2(m0 - nm0), sc1 = ex2(m1 - nm1);
        m0 = nm0; m1 = nm1;
        #pragma unroll
        for (int ni = 0; ni < 8; ni++) {
            o[ni][0] *= sc0; o[ni][1] *= sc0;
            o[ni][2] *= sc1; o[ni][3] *= sc1;
        }
        lacc[0] *= sc0; lacc[1] *= sc0;
        lacc[2] *= sc1; lacc[3] *= sc1;

        // P = exp2(S - m) computed directly in fp16x2 (A-operand layout)
        uint32_t ph[4][4];
        #pragma unroll
        for (int t = 0; t < 4; t++) {
            ph[t][0] = h2u(h2exp2(__floats2half2_rn(s[2 * t][0] - nm0,
                                                    s[2 * t][1] - nm0)));
            ph[t][1] = h2u(h2exp2(__floats2half2_rn(s[2 * t][2] - nm1,
                                                    s[2 * t][3] - nm1)));
            ph[t][2] = h2u(h2exp2(__floats2half2_rn(s[2 * t + 1][0] - nm0,
                                                    s[2 * t + 1][1] - nm0)));
            ph[t][3] = h2u(h2exp2(__floats2half2_rn(s[2 * t + 1][2] - nm1,
                                                    s[2 * t + 1][3] - nm1)));
        }

        // O += P V ; l += P 1 (ones-column MMA gives row sums in fp32)
        #pragma unroll
        for (int t = 0; t < 4; t++) {
            mma_f16(lacc, ph[t], ONES);
            #pragma unroll
            for (int ni2 = 0; ni2 < 4; ni2++) {
                int vrow = t * 16 + (lane & 15);
                int vcolb = ni2 * 32 + (lane & 16);
                uint32_t vf[4];
                ldsm_x4t(vf, sV + SWZ128((uint32_t)(vrow * 128 + vcolb)));
                mma_f16(o[2 * ni2],     ph[t], vf);
                mma_f16(o[2 * ni2 + 1], ph[t], vf + 2);
            }
        }
    }

    // normalize + fp16 output
    float il0 = 1.0f / lacc[0], il1 = 1.0f / lacc[2];
    int row0 = b * SEQ + q0 + wid * 16 + r;
    #pragma unroll
    for (int ni = 0; ni < 8; ni++) {
        int col = h * HD + ni * 8 + cb;
        *reinterpret_cast<uint32_t*>(y + (size_t)row0 * DIM + col) =
            h2u(__floats2half2_rn(o[ni][0] * il0, o[ni][1] * il0));
        *reinterpret_cast<uint32_t*>(y + (size_t)(row0 + 8) * DIM + col) =
            h2u(__floats2half2_rn(o[ni][2] * il1, o[ni][3] * il1));
    }
}

// ---------------- launch ---------------------------------------------------
extern "C" void kernel_launch(void* const* d_in, const int* in_sizes, int n_in,
                              void* d_out, int out_size)
{
    const float* x      = (const float*)d_in[0];
    const float* ln1_g  = (const float*)d_in[1];
    const float* ln1_b  = (const float*)d_in[2];
    const float* ln2_g  = (const float*)d_in[3];
    const float* ln2_b  = (const float*)d_in[4];
    const float* W_qkv  = (const float*)d_in[5];
    const float* b_qkv  = (const float*)d_in[6];
    const float* W_proj = (const float*)d_in[7];
    const float* b_proj = (const float*)d_in[8];
    const float* W_fc   = (const float*)d_in[9];
    const float* b_fc   = (const float*)d_in[10];
    const float* W_out  = (const float*)d_in[11];
    const float* b_out  = (const float*)d_in[12];
    float* out = (float*)d_out;

    float *x1;
    __half *qkv, *h, *y, *act, *wq, *wp, *wf, *wo;
    cudaGetSymbolAddress((void**)&x1,  g_x1);
    cudaGetSymbolAddress((void**)&qkv, g_qkv);
    cudaGetSymbolAddress((void**)&h,   g_h);
    cudaGetSymbolAddress((void**)&y,   g_y);
    cudaGetSymbolAddress((void**)&act, g_act);
    cudaGetSymbolAddress((void**)&wq,  g_wq);
    cudaGetSymbolAddress((void**)&wp,  g_wp);
    cudaGetSymbolAddress((void**)&wf,  g_wf);
    cudaGetSymbolAddress((void**)&wo,  g_wo);

    cudaFuncSetAttribute(gemm_f16<1>,
        cudaFuncAttributeMaxDynamicSharedMemorySize, GEMM_SMEM);
    cudaFuncSetAttribute(gemm_f16<2>,
        cudaFuncAttributeMaxDynamicSharedMemorySize, GEMM_SMEM);
    cudaFuncSetAttribute(gemm_f16<3>,
        cudaFuncAttributeMaxDynamicSharedMemorySize, GEMM_SMEM);
    cudaFuncSetAttribute(attn_mma,
        cudaFuncAttributeMaxDynamicSharedMemorySize, ATTN_SMEM);

    // 0) all weight transposes in one launch (independent of everything)
    transT_all<<<12288, 256>>>(W_qkv, W_proj, W_fc, W_out, wq, wp, wf, wo);

    // 1) LN1 -> h (fp16)
    ln_kernel<<<NTOK, 256>>>(x, ln1_g, ln1_b, h);

    // 2) qkv = h @ W_qkv + b_qkv (fp16 out)
    gemm_f16<3><<<dim3(3 * DIM / 128, NTOK / 128), 256, GEMM_SMEM>>>(
        h, wq, b_qkv, nullptr, nullptr, qkv, NTOK, 3 * DIM, DIM);

    // 3) attention -> y (fp16)
    attn_mma<<<dim3(SEQ / 128, NH, BATCH), 256, ATTN_SMEM>>>(qkv, y);

    // 4) x1 = x + y @ W_proj + b_proj
    gemm_f16<1><<<dim3(DIM / 128, NTOK / 128), 256, GEMM_SMEM>>>(
        y, wp, b_proj, x, x1, nullptr, NTOK, DIM, DIM);

    // 5) LN2 -> h (fp16)
    ln_kernel<<<NTOK, 256>>>(x1, ln2_g, ln2_b, h);

    // 6) act = relu(h @ W_fc + b_fc) (fp16)
    gemm_f16<2><<<dim3(4 * DIM / 128, NTOK / 128), 256, GEMM_SMEM>>>(
        h, wf, b_fc, nullptr, nullptr, act, NTOK, 4 * DIM, DIM);

    // 7) out = x1 + act @ W_out + b_out
    gemm_f16<1><<<dim3(DIM / 128, NTOK / 128), 256, GEMM_SMEM>>>(
        act, wo, b_out, x1, out, nullptr, NTOK, DIM, 4 * DIM);
}

// round 13
// speedup vs baseline: 7.8581x; 1.0049x over previous
#include <cuda_runtime.h>
#include <cuda_fp16.h>
#include <math.h>
#include <stdint.h>

#define BATCH 2
#define SEQ   2048
#define DIM   1024
#define NH    16
#define HD    64
#define NTOK  (BATCH * SEQ)   // 4096

// ---------------- scratch (device globals) ---------------------------------
__device__ float  g_x1 [(size_t)NTOK * DIM];       // residual after proj
__device__ __half g_qkv[(size_t)NTOK * 3 * DIM];   // qkv fp16
__device__ __half g_h  [(size_t)NTOK * DIM];       // LN out fp16
__device__ __half g_y  [(size_t)NTOK * DIM];       // attn out fp16
__device__ __half g_act[(size_t)NTOK * 4 * DIM];   // relu(fc) fp16
__device__ __half g_wq [(size_t)3 * DIM * DIM];    // W_qkv^T fp16
__device__ __half g_wp [(size_t)DIM * DIM];        // W_proj^T fp16
__device__ __half g_wf [(size_t)4 * DIM * DIM];    // W_fc^T fp16
__device__ __half g_wo [(size_t)4 * DIM * DIM];    // W_out^T fp16

// ======================= helpers ===========================================
__device__ __forceinline__ uint32_t smem_u32(const void* p) {
    uint32_t a;
    asm("{ .reg .u64 t; cvta.to.shared.u64 t, %1; cvt.u32.u64 %0, t; }"
        : "=r"(a) : "l"(p));
    return a;
}
#define SWZ128(o) ((o) ^ (((o) >> 3) & 0x70))

__device__ __forceinline__ void ldsm_x4(uint32_t* r, uint32_t addr) {
    asm volatile("ldmatrix.sync.aligned.m8n8.x4.shared.b16 {%0,%1,%2,%3}, [%4];"
                 : "=r"(r[0]), "=r"(r[1]), "=r"(r[2]), "=r"(r[3]) : "r"(addr));
}
__device__ __forceinline__ void ldsm_x4t(uint32_t* r, uint32_t addr) {
    asm volatile("ldmatrix.sync.aligned.m8n8.x4.trans.shared.b16 {%0,%1,%2,%3}, [%4];"
                 : "=r"(r[0]), "=r"(r[1]), "=r"(r[2]), "=r"(r[3]) : "r"(addr));
}
__device__ __forceinline__ void mma_f16(float* c, const uint32_t* a,
                                        const uint32_t* b) {
    asm volatile(
        "mma.sync.aligned.m16n8k16.row.col.f32.f16.f16.f32 "
        "{%0,%1,%2,%3}, {%4,%5,%6,%7}, {%8,%9}, {%0,%1,%2,%3};"
        : "+f"(c[0]), "+f"(c[1]), "+f"(c[2]), "+f"(c[3])
        : "r"(a[0]), "r"(a[1]), "r"(a[2]), "r"(a[3]), "r"(b[0]), "r"(b[1]));
}
// fp16-accumulator variant (2-reg D) for the QK logits
__device__ __forceinline__ void mma_f16h(uint32_t* c, const uint32_t* a,
                                         const uint32_t* b) {
    asm volatile(
        "mma.sync.aligned.m16n8k16.row.col.f16.f16.f16.f16 "
        "{%0,%1}, {%2,%3,%4,%5}, {%6,%7}, {%0,%1};"
        : "+r"(c[0]), "+r"(c[1])
        : "r"(a[0]), "r"(a[1]), "r"(a[2]), "r"(a[3]), "r"(b[0]), "r"(b[1]));
}
__device__ __forceinline__ void cp16(uint32_t daddr, const void* saddr) {
    asm volatile("cp.async.cg.shared.global [%0], [%1], 16;"
                 :: "r"(daddr), "l"(saddr));
}
__device__ __forceinline__ float ex2(float x) {
    float y;
    asm("ex2.approx.f32 %0, %1;" : "=f"(y) : "f"(x));
    return y;
}
__device__ __forceinline__ uint32_t h2u(__half2 v) {
    return *reinterpret_cast<uint32_t*>(&v);
}
__device__ __forceinline__ __half2 u2h(uint32_t v) {
    return *reinterpret_cast<__half2*>(&v);
}

// ---------------- LayerNorm (fp16 out) -------------------------------------
__global__ __launch_bounds__(256) void ln_kernel(
    const float* __restrict__ x, const float* __restrict__ gamma,
    const float* __restrict__ beta, __half* __restrict__ out)
{
    int row = blockIdx.x;
    int tid = threadIdx.x;
    const float4* xr = reinterpret_cast<const float4*>(x + (size_t)row * DIM);
    float4 v = xr[tid];
    float s1 = v.x + v.y + v.z + v.w;
    float s2 = v.x * v.x + v.y * v.y + v.z * v.z + v.w * v.w;
    #pragma unroll
    for (int o = 16; o > 0; o >>= 1) {
        s1 += __shfl_xor_sync(0xffffffffu, s1, o);
        s2 += __shfl_xor_sync(0xffffffffu, s2, o);
    }
    __shared__ float sh1[8], sh2[8];
    int w = tid >> 5, l = tid & 31;
    if (l == 0) { sh1[w] = s1; sh2[w] = s2; }
    __syncthreads();
    s1 = 0.f; s2 = 0.f;
    #pragma unroll
    for (int i = 0; i < 8; i++) { s1 += sh1[i]; s2 += sh2[i]; }
    float mu  = s1 * (1.0f / DIM);
    float var = s2 * (1.0f / DIM) - mu * mu;
    float r   = rsqrtf(var + 1e-5f);
    float4 gv = reinterpret_cast<const float4*>(gamma)[tid];
    float4 bv = reinterpret_cast<const float4*>(beta)[tid];
    uint2 u;
    u.x = h2u(__floats2half2_rn((v.x - mu) * r * gv.x + bv.x,
                                (v.y - mu) * r * gv.y + bv.y));
    u.y = h2u(__floats2half2_rn((v.z - mu) * r * gv.z + bv.z,
                                (v.w - mu) * r * gv.w + bv.w));
    *reinterpret_cast<uint2*>(out + (size_t)row * DIM + tid * 4) = u;
}

// ---------------- fused weight transposes: 4 weights in one launch ---------
__global__ __launch_bounds__(256) void transT_all(
    const float* __restrict__ W0, const float* __restrict__ W1,
    const float* __restrict__ W2, const float* __restrict__ W3,
    __half* __restrict__ O0, __half* __restrict__ O1,
    __half* __restrict__ O2, __half* __restrict__ O3)
{
    int t = blockIdx.x;
    const float* in; __half* out; int R, C;
    if (t < 3072)      { in = W0; out = O0; R = DIM;     C = 3 * DIM; }
    else if (t < 4096) { in = W1; out = O1; R = DIM;     C = DIM;     t -= 3072; }
    else if (t < 8192) { in = W2; out = O2; R = DIM;     C = 4 * DIM; t -= 4096; }
    else               { in = W3; out = O3; R = 4 * DIM; C = DIM;     t -= 8192; }
    int tilesX = C >> 5;
    int bx = t % tilesX, by = t / tilesX;

    __shared__ float tt[32][33];
    int tx = threadIdx.x & 31, ty = threadIdx.x >> 5;
    int x = bx * 32 + tx;
    #pragma unroll
    for (int j = 0; j < 32; j += 8)
        tt[ty + j][tx] = in[(size_t)(by * 32 + ty + j) * C + x];
    __syncthreads();
    #pragma unroll
    for (int j = 0; j < 32; j += 8) {
        size_t idx = (size_t)(bx * 32 + ty + j) * R + by * 32 + tx;
        out[idx] = __float2half(tt[tx][ty + j]);
    }
}

// ---------------- fp16 GEMM (3-stage cp.async, 128x128x64, 2 CTA/SM) -------
#define STAGE_BYTES 32768
#define GEMM_STAGES 3
#define GEMM_SMEM   (GEMM_STAGES * STAGE_BYTES)

template<int MODE>   // 0: fp32+bias; 1: fp32+bias+res; 2: fp16 relu; 3: fp16
__global__ __launch_bounds__(256, 2) void gemm_f16(
    const __half* __restrict__ A, const __half* __restrict__ B,
    const float* __restrict__ bias, const float* __restrict__ res,
    float* __restrict__ C, __half* __restrict__ Oh, int M, int N, int K)
{
    extern __shared__ char smem[];
    const uint32_t sbase = smem_u32(smem);
    const int tid = threadIdx.x;
    const int wid = tid >> 5, lane = tid & 31;
    const int m0 = blockIdx.y * 128, n0 = blockIdx.x * 128;
    const int wm = (wid & 1) * 64;
    const int wn = (wid >> 1) * 32;

    float acc[4][4][4];
    #pragma unroll
    for (int a = 0; a < 4; a++)
        #pragma unroll
        for (int b = 0; b < 4; b++)
            #pragma unroll
            for (int c = 0; c < 4; c++) acc[a][b][c] = 0.f;

    const __half* Ab = A + (size_t)m0 * K;
    const __half* Bb = B + (size_t)n0 * K;
    const int row_l = tid >> 3, c_l = tid & 7;

    auto issue = [&](int i) {
        int k0 = i << 6;
        uint32_t st = sbase + (uint32_t)(i % GEMM_STAGES) * STAGE_BYTES;
        #pragma unroll
        for (int op = 0; op < 2; op++) {
            const __half* src = (op ? Bb : Ab) + k0;
            uint32_t dst = st + op * 16384;
            #pragma unroll
            for (int p = 0; p < 4; p++) {
                int row = row_l + p * 32;
                cp16(dst + SWZ128((uint32_t)(row * 128 + c_l * 16)),
                     src + (size_t)row * K + c_l * 8);
            }
        }
        asm volatile("cp.async.commit_group;" ::: "memory");
    };

    const int NC = K >> 6;
    issue(0); issue(1);
    for (int i = 0; i < NC; i++) {
        if (i + 1 < NC) { asm volatile("cp.async.wait_group 1;" ::: "memory"); }
        else            { asm volatile("cp.async.wait_group 0;" ::: "memory"); }
        __syncthreads();
        if (i + 2 < NC) issue(i + 2);

        uint32_t st = sbase + (uint32_t)(i % GEMM_STAGES) * STAGE_BYTES;
        uint32_t sA = st, sB = st + 16384;

        #pragma unroll
        for (int ks = 0; ks < 4; ks++) {
            uint32_t af[4][4];
            #pragma unroll
            for (int mi = 0; mi < 4; mi++) {
                int row = wm + mi * 16 + (lane & 15);
                int colb = ks * 32 + (lane >> 4) * 16;
                ldsm_x4(af[mi], sA + SWZ128((uint32_t)(row * 128 + colb)));
            }
            uint32_t bf[2][4];
            #pragma unroll
            for (int ni2 = 0; ni2 < 2; ni2++) {
                int row = wn + ni2 * 16 + ((lane & 16) >> 1) + (lane & 7);
                int colb = ks * 32 + (lane & 8) * 2;
                ldsm_x4(bf[ni2], sB + SWZ128((uint32_t)(row * 128 + colb)));
            }
            #pragma unroll
            for (int mi = 0; mi < 4; mi++)
                #pragma unroll
                for (int ni2 = 0; ni2 < 2; ni2++) {
                    mma_f16(acc[mi][2 * ni2],     af[mi], bf[ni2]);
                    mma_f16(acc[mi][2 * ni2 + 1], af[mi], bf[ni2] + 2);
                }
        }
    }

    #pragma unroll
    for (int mi = 0; mi < 4; mi++) {
        #pragma unroll
        for (int h = 0; h < 2; h++) {
            int row = m0 + wm + mi * 16 + (lane >> 2) + h * 8;
            #pragma unroll
            for (int ni = 0; ni < 4; ni++) {
                int col = n0 + wn + ni * 8 + (lane & 3) * 2;
                float2 bb = *reinterpret_cast<const float2*>(bias + col);
                float vx = acc[mi][ni][h * 2 + 0] + bb.x;
                float vy = acc[mi][ni][h * 2 + 1] + bb.y;
                if (MODE == 1) {
                    float2 rv = *reinterpret_cast<const float2*>(
                        res + (size_t)row * N + col);
                    vx += rv.x; vy += rv.y;
                }
                if (MODE == 2) { vx = fmaxf(vx, 0.f); vy = fmaxf(vy, 0.f); }
                if (MODE == 2 || MODE == 3) {
                    *reinterpret_cast<uint32_t*>(Oh + (size_t)row * N + col) =
                        h2u(__floats2half2_rn(vx, vy));
                } else {
                    *reinterpret_cast<float2*>(C + (size_t)row * N + col) =
                        make_float2(vx, vy);
                }
            }
        }
    }
}

// ---------------- fp16 tensor-core causal flash attention ------------------
// grid (SEQ/128, NH, BATCH), 256 threads (8 warps x 16 query rows), 2 CTA/SM.
// QK logits accumulate in fp16 (S regs ARE the P fragments); softmax is
// half2 SIMD; rescale skipped warp-uniformly when no new row max; fully
// masked diagonal tiles skipped per-warp.
#define ATTN_SMEM (2 * 16384)   // double-buffered (K 8KB + V 8KB)

__global__ __launch_bounds__(256, 2) void attn_mma(
    const __half* __restrict__ qkv, __half* __restrict__ y)
{
    extern __shared__ char smem[];
    const uint32_t sb = smem_u32(smem);

    int qt = gridDim.x - 1 - blockIdx.x;   // heavy blocks first
    int h = blockIdx.y, b = blockIdx.z;
    int q0 = qt * 128;
    int tid = threadIdx.x, wid = tid >> 5, lane = tid & 31;
    const __half* base = qkv + (size_t)b * SEQ * 3 * DIM;
    const int r = lane >> 2, cb = (lane & 3) * 2;
    const __half2 QSC2 = __float2half2_rn(0.1803368801f);  // 0.125*log2(e)
    const uint32_t ONES[2] = {0x3C003C00u, 0x3C003C00u};   // half2(1,1) x2
    const __half NEGINF = __ushort_as_half(0xFC00u);

    // Q fragments (fp16 A-operand layout), softmax scale pre-folded
    uint32_t qf[4][4];
    #pragma unroll
    for (int ks = 0; ks < 4; ks++) {
        #pragma unroll
        for (int fr = 0; fr < 4; fr++) {
            int row = q0 + wid * 16 + r + (fr & 1) * 8;
            int col = ks * 16 + cb + (fr >> 1) * 8;
            __half2 v = *reinterpret_cast<const __half2*>(
                base + (size_t)row * 3 * DIM + h * HD + col);
            qf[ks][fr] = h2u(__hmul2(v, QSC2));
        }
    }

    auto issueKV = [&](int kb) {
        uint32_t stg = sb + (uint32_t)(kb & 1) * 16384;
        #pragma unroll
        for (int p = 0; p < 4; p++) {
            int idx = p * 256 + tid;
            int op = idx >> 9, rem = idx & 511;
            int row = rem >> 3, c = rem & 7;
            const __half* src = base + (size_t)(kb * 64 + row) * 3 * DIM
                              + (op ? 2 * DIM : DIM) + h * HD + c * 8;
            cp16(stg + op * 8192 + SWZ128((uint32_t)(row * 128 + c * 16)), src);
        }
        asm volatile("cp.async.commit_group;" ::: "memory");
    };

    float m0 = -1e30f, m1 = -1e30f;
    float lacc[4] = {0.f, 0.f, 0.f, 0.f};
    float o[8][4];
    #pragma unroll
    for (int ni = 0; ni < 8; ni++)
        #pragma unroll
        for (int c = 0; c < 4; c++) o[ni][c] = 0.f;

    const int last = 2 * qt + 1;
    issueKV(0);
    for (int kb = 0; kb <= last; kb++) {
        asm volatile("cp.async.wait_group 0;" ::: "memory");
        __syncthreads();
        if (kb < last) issueKV(kb + 1);

        // warps whose rows are entirely above this key tile: nothing to do
        bool fullmask = (kb * 64 > q0 + wid * 16 + 15);
        if (!fullmask) {
            uint32_t sK = sb + (uint32_t)(kb & 1) * 16384;
            uint32_t sV = sK + 8192;

            // S = Q K^T, fp16 accumulators (c[0]=row r, c[1]=row r+8)
            uint32_t s16[8][2];
            #pragma unroll
            for (int ni = 0; ni < 8; ni++) { s16[ni][0] = 0; s16[ni][1] = 0; }
            #pragma unroll
            for (int ks = 0; ks < 4; ks++) {
                #pragma unroll
                for (int ni2 = 0; ni2 < 4; ni2++) {
                    int krow = ni2 * 16 + ((lane & 16) >> 1) + (lane & 7);
                    int kcolb = ks * 32 + (lane & 8) * 2;
                    uint32_t kf[4];
                    ldsm_x4(kf, sK + SWZ128((uint32_t)(krow * 128 + kcolb)));
                    mma_f16h(s16[2 * ni2],     qf[ks], kf);
                    mma_f16h(s16[2 * ni2 + 1], qf[ks], kf + 2);
                }
            }

            // causal mask (diagonal-crossing tiles only)
            if (kb * 64 + 63 > q0 + wid * 16) {
                int rg0 = q0 + wid * 16 + r, rg1 = rg0 + 8;
                int cgb = kb * 64;
                #pragma unroll
                for (int ni = 0; ni < 8; ni++) {
                    int c0 = cgb + ni * 8 + cb;
                    __half2 v0 = u2h(s16[ni][0]);
                    __half2 v1 = u2h(s16[ni][1]);
                    if (c0     > rg0) v0.x = NEGINF;
                    if (c0 + 1 > rg0) v0.y = NEGINF;
                    if (c0     > rg1) v1.x = NEGINF;
                    if (c0 + 1 > rg1) v1.y = NEGINF;
                    s16[ni][0] = h2u(v0);
                    s16[ni][1] = h2u(v1);
                }
            }

            // row max via half2 SIMD + quad shuffle
            __half2 mx0 = u2h(s16[0][0]), mx1 = u2h(s16[0][1]);
            #pragma unroll
            for (int ni = 1; ni < 8; ni++) {
                mx0 = __hmax2(mx0, u2h(s16[ni][0]));
                mx1 = __hmax2(mx1, u2h(s16[ni][1]));
            }
            uint32_t x0 = h2u(mx0), x1 = h2u(mx1);
            x0 = h2u(__hmax2(u2h(x0), u2h(__shfl_xor_sync(0xffffffffu, x0, 1))));
            x0 = h2u(__hmax2(u2h(x0), u2h(__shfl_xor_sync(0xffffffffu, x0, 2))));
            x1 = h2u(__hmax2(u2h(x1), u2h(__shfl_xor_sync(0xffffffffu, x1, 1))));
            x1 = h2u(__hmax2(u2h(x1), u2h(__shfl_xor_sync(0xffffffffu, x1, 2))));
            float nm0 = fmaxf(__half2float(u2h(x0).x), __half2float(u2h(x0).y));
            float nm1 = fmaxf(__half2float(u2h(x1).x), __half2float(u2h(x1).y));
            nm0 = fmaxf(nm0, m0);
            nm1 = fmaxf(nm1, m1);

            // rescale only when some lane saw a new max (warp-uniform branch)
            bool changed = !__all_sync(0xffffffffu, (nm0 == m0) & (nm1 == m1));
            if (changed) {
                float sc0 = ex2(m0 - nm0), sc1 = ex2(m1 - nm1);
                #pragma unroll
                for (int ni = 0; ni < 8; ni++) {
                    o[ni][0] *= sc0; o[ni][1] *= sc0;
                    o[ni][2] *= sc1; o[ni][3] *= sc1;
                }
                lacc[0] *= sc0; lacc[2] *= sc1;
            }
            m0 = nm0; m1 = nm1;

            // P = exp2(S - m), pure half2 (regs already in A-fragment layout)
            __half2 nm0h = __float2half2_rn(nm0);
            __half2 nm1h = __float2half2_rn(nm1);
            uint32_t ph[4][4];
            #pragma unroll
            for (int t = 0; t < 4; t++) {
                ph[t][0] = h2u(h2exp2(__hsub2(u2h(s16[2 * t][0]),     nm0h)));
                ph[t][1] = h2u(h2exp2(__hsub2(u2h(s16[2 * t][1]),     nm1h)));
                ph[t][2] = h2u(h2exp2(__hsub2(u2h(s16[2 * t + 1][0]), nm0h)));
                ph[t][3] = h2u(h2exp2(__hsub2(u2h(s16[2 * t + 1][1]), nm1h)));
            }

            // O += P V ; l += P 1
            #pragma unroll
            for (int t = 0; t < 4; t++) {
                mma_f16(lacc, ph[t], ONES);
                #pragma unroll
                for (int ni2 = 0; ni2 < 4; ni2++) {
                    int vrow = t * 16 + (lane & 15);
                    int vcolb = ni2 * 32 + (lane & 16);
                    uint32_t vf[4];
                    ldsm_x4t(vf, sV + SWZ128((uint32_t)(vrow * 128 + vcolb)));
                    mma_f16(o[2 * ni2],     ph[t], vf);
                    mma_f16(o[2 * ni2 + 1], ph[t], vf + 2);
                }
            }
        }
        __syncthreads();   // all warps done with buffer kb before next fill
    }

    // normalize + fp16 output
    float il0 = 1.0f / lacc[0], il1 = 1.0f / lacc[2];
    int row0 = b * SEQ + q0 + wid * 16 + r;
    #pragma unroll
    for (int ni = 0; ni < 8; ni++) {
        int col = h * HD + ni * 8 + cb;
        *reinterpret_cast<uint32_t*>(y + (size_t)row0 * DIM + col) =
            h2u(__floats2half2_rn(o[ni][0] * il0, o[ni][1] * il0));
        *reinterpret_cast<uint32_t*>(y + (size_t)(row0 + 8) * DIM + col) =
            h2u(__floats2half2_rn(o[ni][2] * il1, o[ni][3] * il1));
    }
}

// ---------------- launch ---------------------------------------------------
extern "C" void kernel_launch(void* const* d_in, const int* in_sizes, int n_in,
                              void* d_out, int out_size)
{
    const float* x      = (const float*)d_in[0];
    const float* ln1_g  = (const float*)d_in[1];
    const float* ln1_b  = (const float*)d_in[2];
    const float* ln2_g  = (const float*)d_in[3];
    const float* ln2_b  = (const float*)d_in[4];
    const float* W_qkv  = (const float*)d_in[5];
    const float* b_qkv  = (const float*)d_in[6];
    const float* W_proj = (const float*)d_in[7];
    const float* b_proj = (const float*)d_in[8];
    const float* W_fc   = (const float*)d_in[9];
    const float* b_fc   = (const float*)d_in[10];
    const float* W_out  = (const float*)d_in[11];
    const float* b_out  = (const float*)d_in[12];
    float* out = (float*)d_out;

    float *x1;
    __half *qkv, *h, *y, *act, *wq, *wp, *wf, *wo;
    cudaGetSymbolAddress((void**)&x1,  g_x1);
    cudaGetSymbolAddress((void**)&qkv, g_qkv);
    cudaGetSymbolAddress((void**)&h,   g_h);
    cudaGetSymbolAddress((void**)&y,   g_y);
    cudaGetSymbolAddress((void**)&act, g_act);
    cudaGetSymbolAddress((void**)&wq,  g_wq);
    cudaGetSymbolAddress((void**)&wp,  g_wp);
    cudaGetSymbolAddress((void**)&wf,  g_wf);
    cudaGetSymbolAddress((void**)&wo,  g_wo);

    cudaFuncSetAttribute(gemm_f16<1>,
        cudaFuncAttributeMaxDynamicSharedMemorySize, GEMM_SMEM);
    cudaFuncSetAttribute(gemm_f16<2>,
        cudaFuncAttributeMaxDynamicSharedMemorySize, GEMM_SMEM);
    cudaFuncSetAttribute(gemm_f16<3>,
        cudaFuncAttributeMaxDynamicSharedMemorySize, GEMM_SMEM);
    cudaFuncSetAttribute(attn_mma,
        cudaFuncAttributeMaxDynamicSharedMemorySize, ATTN_SMEM);

    // 0) all weight transposes in one launch
    transT_all<<<12288, 256>>>(W_qkv, W_proj, W_fc, W_out, wq, wp, wf, wo);

    // 1) LN1 -> h (fp16)
    ln_kernel<<<NTOK, 256>>>(x, ln1_g, ln1_b, h);

    // 2) qkv = h @ W_qkv + b_qkv (fp16 out)
    gemm_f16<3><<<dim3(3 * DIM / 128, NTOK / 128), 256, GEMM_SMEM>>>(
        h, wq, b_qkv, nullptr, nullptr, qkv, NTOK, 3 * DIM, DIM);

    // 3) attention -> y (fp16)
    attn_mma<<<dim3(SEQ / 128, NH, BATCH), 256, ATTN_SMEM>>>(qkv, y);

    // 4) x1 = x + y @ W_proj + b_proj
    gemm_f16<1><<<dim3(DIM / 128, NTOK / 128), 256, GEMM_SMEM>>>(
        y, wp, b_proj, x, x1, nullptr, NTOK, DIM, DIM);

    // 5) LN2 -> h (fp16)
    ln_kernel<<<NTOK, 256>>>(x1, ln2_g, ln2_b, h);

    // 6) act = relu(h @ W_fc + b_fc) (fp16)
    gemm_f16<2><<<dim3(4 * DIM / 128, NTOK / 128), 256, GEMM_SMEM>>>(
        h, wf, b_fc, nullptr, nullptr, act, NTOK, 4 * DIM, DIM);

    // 7) out = x1 + act @ W_out + b_out
    gemm_f16<1><<<dim3(DIM / 128, NTOK / 128), 256, GEMM_SMEM>>>(
        act, wo, b_out, x1, out, nullptr, NTOK, DIM, 4 * DIM);
}

// round 14
// speedup vs baseline: 7.8941x; 1.0046x over previous
#include <cuda_runtime.h>
#include <cuda_fp16.h>
#include <math.h>
#include <stdint.h>

#define BATCH 2
#define SEQ   2048
#define DIM   1024
#define NH    16
#define HD    64
#define NTOK  (BATCH * SEQ)   // 4096

// ---------------- scratch (device globals) ---------------------------------
__device__ float  g_x1 [(size_t)NTOK * DIM];       // residual after proj
__device__ __half g_qkv[(size_t)NTOK * 3 * DIM];   // qkv fp16
__device__ __half g_h  [(size_t)NTOK * DIM];       // LN out fp16
__device__ __half g_y  [(size_t)NTOK * DIM];       // attn out fp16
__device__ __half g_act[(size_t)NTOK * 4 * DIM];   // relu(fc) fp16
__device__ __half g_wq [(size_t)3 * DIM * DIM];    // W_qkv^T fp16
__device__ __half g_wp [(size_t)DIM * DIM];        // W_proj^T fp16
__device__ __half g_wf [(size_t)4 * DIM * DIM];    // W_fc^T fp16
__device__ __half g_wo [(size_t)4 * DIM * DIM];    // W_out^T fp16

// ======================= helpers ===========================================
__device__ __forceinline__ uint32_t smem_u32(const void* p) {
    uint32_t a;
    asm("{ .reg .u64 t; cvta.to.shared.u64 t, %1; cvt.u32.u64 %0, t; }"
        : "=r"(a) : "l"(p));
    return a;
}
#define SWZ128(o) ((o) ^ (((o) >> 3) & 0x70))

__device__ __forceinline__ void ldsm_x4(uint32_t* r, uint32_t addr) {
    asm volatile("ldmatrix.sync.aligned.m8n8.x4.shared.b16 {%0,%1,%2,%3}, [%4];"
                 : "=r"(r[0]), "=r"(r[1]), "=r"(r[2]), "=r"(r[3]) : "r"(addr));
}
__device__ __forceinline__ void ldsm_x4t(uint32_t* r, uint32_t addr) {
    asm volatile("ldmatrix.sync.aligned.m8n8.x4.trans.shared.b16 {%0,%1,%2,%3}, [%4];"
                 : "=r"(r[0]), "=r"(r[1]), "=r"(r[2]), "=r"(r[3]) : "r"(addr));
}
__device__ __forceinline__ void mma_f16(float* c, const uint32_t* a,
                                        const uint32_t* b) {
    asm volatile(
        "mma.sync.aligned.m16n8k16.row.col.f32.f16.f16.f32 "
        "{%0,%1,%2,%3}, {%4,%5,%6,%7}, {%8,%9}, {%0,%1,%2,%3};"
        : "+f"(c[0]), "+f"(c[1]), "+f"(c[2]), "+f"(c[3])
        : "r"(a[0]), "r"(a[1]), "r"(a[2]), "r"(a[3]), "r"(b[0]), "r"(b[1]));
}
// fp16-accumulator variant (2-reg D) for the QK logits
__device__ __forceinline__ void mma_f16h(uint32_t* c, const uint32_t* a,
                                         const uint32_t* b) {
    asm volatile(
        "mma.sync.aligned.m16n8k16.row.col.f16.f16.f16.f16 "
        "{%0,%1}, {%2,%3,%4,%5}, {%6,%7}, {%0,%1};"
        : "+r"(c[0]), "+r"(c[1])
        : "r"(a[0]), "r"(a[1]), "r"(a[2]), "r"(a[3]), "r"(b[0]), "r"(b[1]));
}
__device__ __forceinline__ void cp16(uint32_t daddr, const void* saddr) {
    asm volatile("cp.async.cg.shared.global [%0], [%1], 16;"
                 :: "r"(daddr), "l"(saddr));
}
__device__ __forceinline__ float ex2(float x) {
    float y;
    asm("ex2.approx.f32 %0, %1;" : "=f"(y) : "f"(x));
    return y;
}
__device__ __forceinline__ uint32_t h2u(__half2 v) {
    return *reinterpret_cast<uint32_t*>(&v);
}
__device__ __forceinline__ __half2 u2h(uint32_t v) {
    return *reinterpret_cast<__half2*>(&v);
}

// ---------------- LayerNorm (fp16 out) -------------------------------------
__global__ __launch_bounds__(256) void ln_kernel(
    const float* __restrict__ x, const float* __restrict__ gamma,
    const float* __restrict__ beta, __half* __restrict__ out)
{
    int row = blockIdx.x;
    int tid = threadIdx.x;
    const float4* xr = reinterpret_cast<const float4*>(x + (size_t)row * DIM);
    float4 v = xr[tid];
    float s1 = v.x + v.y + v.z + v.w;
    float s2 = v.x * v.x + v.y * v.y + v.z * v.z + v.w * v.w;
    #pragma unroll
    for (int o = 16; o > 0; o >>= 1) {
        s1 += __shfl_xor_sync(0xffffffffu, s1, o);
        s2 += __shfl_xor_sync(0xffffffffu, s2, o);
    }
    __shared__ float sh1[8], sh2[8];
    int w = tid >> 5, l = tid & 31;
    if (l == 0) { sh1[w] = s1; sh2[w] = s2; }
    __syncthreads();
    s1 = 0.f; s2 = 0.f;
    #pragma unroll
    for (int i = 0; i < 8; i++) { s1 += sh1[i]; s2 += sh2[i]; }
    float mu  = s1 * (1.0f / DIM);
    float var = s2 * (1.0f / DIM) - mu * mu;
    float r   = rsqrtf(var + 1e-5f);
    float4 gv = reinterpret_cast<const float4*>(gamma)[tid];
    float4 bv = reinterpret_cast<const float4*>(beta)[tid];
    uint2 u;
    u.x = h2u(__floats2half2_rn((v.x - mu) * r * gv.x + bv.x,
                                (v.y - mu) * r * gv.y + bv.y));
    u.y = h2u(__floats2half2_rn((v.z - mu) * r * gv.z + bv.z,
                                (v.w - mu) * r * gv.w + bv.w));
    *reinterpret_cast<uint2*>(out + (size_t)row * DIM + tid * 4) = u;
}

// ---------------- fused weight transposes: 4 weights in one launch ---------
__global__ __launch_bounds__(256) void transT_all(
    const float* __restrict__ W0, const float* __restrict__ W1,
    const float* __restrict__ W2, const float* __restrict__ W3,
    __half* __restrict__ O0, __half* __restrict__ O1,
    __half* __restrict__ O2, __half* __restrict__ O3)
{
    int t = blockIdx.x;
    const float* in; __half* out; int R, C;
    if (t < 3072)      { in = W0; out = O0; R = DIM;     C = 3 * DIM; }
    else if (t < 4096) { in = W1; out = O1; R = DIM;     C = DIM;     t -= 3072; }
    else if (t < 8192) { in = W2; out = O2; R = DIM;     C = 4 * DIM; t -= 4096; }
    else               { in = W3; out = O3; R = 4 * DIM; C = DIM;     t -= 8192; }
    int tilesX = C >> 5;
    int bx = t % tilesX, by = t / tilesX;

    __shared__ float tt[32][33];
    int tx = threadIdx.x & 31, ty = threadIdx.x >> 5;
    int x = bx * 32 + tx;
    #pragma unroll
    for (int j = 0; j < 32; j += 8)
        tt[ty + j][tx] = in[(size_t)(by * 32 + ty + j) * C + x];
    __syncthreads();
    #pragma unroll
    for (int j = 0; j < 32; j += 8) {
        size_t idx = (size_t)(bx * 32 + ty + j) * R + by * 32 + tx;
        out[idx] = __float2half(tt[tx][ty + j]);
    }
}

// ---------------- fp16 GEMM (3-stage cp.async, 128x128x64, 2 CTA/SM) -------
#define STAGE_BYTES 32768
#define GEMM_STAGES 3
#define GEMM_SMEM   (GEMM_STAGES * STAGE_BYTES)

template<int MODE>   // 0: fp32+bias; 1: fp32+bias+res; 2: fp16 relu; 3: fp16
__global__ __launch_bounds__(256, 2) void gemm_f16(
    const __half* __restrict__ A, const __half* __restrict__ B,
    const float* __restrict__ bias, const float* __restrict__ res,
    float* __restrict__ C, __half* __restrict__ Oh, int M, int N, int K)
{
    extern __shared__ char smem[];
    const uint32_t sbase = smem_u32(smem);
    const int tid = threadIdx.x;
    const int wid = tid >> 5, lane = tid & 31;
    const int m0 = blockIdx.y * 128, n0 = blockIdx.x * 128;
    const int wm = (wid & 1) * 64;
    const int wn = (wid >> 1) * 32;

    float acc[4][4][4];
    #pragma unroll
    for (int a = 0; a < 4; a++)
        #pragma unroll
        for (int b = 0; b < 4; b++)
            #pragma unroll
            for (int c = 0; c < 4; c++) acc[a][b][c] = 0.f;

    const __half* Ab = A + (size_t)m0 * K;
    const __half* Bb = B + (size_t)n0 * K;
    const int row_l = tid >> 3, c_l = tid & 7;

    auto issue = [&](int i) {
        int k0 = i << 6;
        uint32_t st = sbase + (uint32_t)(i % GEMM_STAGES) * STAGE_BYTES;
        #pragma unroll
        for (int op = 0; op < 2; op++) {
            const __half* src = (op ? Bb : Ab) + k0;
            uint32_t dst = st + op * 16384;
            #pragma unroll
            for (int p = 0; p < 4; p++) {
                int row = row_l + p * 32;
                cp16(dst + SWZ128((uint32_t)(row * 128 + c_l * 16)),
                     src + (size_t)row * K + c_l * 8);
            }
        }
        asm volatile("cp.async.commit_group;" ::: "memory");
    };

    const int NC = K >> 6;
    issue(0); issue(1);
    for (int i = 0; i < NC; i++) {
        if (i + 1 < NC) { asm volatile("cp.async.wait_group 1;" ::: "memory"); }
        else            { asm volatile("cp.async.wait_group 0;" ::: "memory"); }
        __syncthreads();
        if (i + 2 < NC) issue(i + 2);

        uint32_t st = sbase + (uint32_t)(i % GEMM_STAGES) * STAGE_BYTES;
        uint32_t sA = st, sB = st + 16384;

        #pragma unroll
        for (int ks = 0; ks < 4; ks++) {
            uint32_t af[4][4];
            #pragma unroll
            for (int mi = 0; mi < 4; mi++) {
                int row = wm + mi * 16 + (lane & 15);
                int colb = ks * 32 + (lane >> 4) * 16;
                ldsm_x4(af[mi], sA + SWZ128((uint32_t)(row * 128 + colb)));
            }
            uint32_t bf[2][4];
            #pragma unroll
            for (int ni2 = 0; ni2 < 2; ni2++) {
                int row = wn + ni2 * 16 + ((lane & 16) >> 1) + (lane & 7);
                int colb = ks * 32 + (lane & 8) * 2;
                ldsm_x4(bf[ni2], sB + SWZ128((uint32_t)(row * 128 + colb)));
            }
            #pragma unroll
            for (int mi = 0; mi < 4; mi++)
                #pragma unroll
                for (int ni2 = 0; ni2 < 2; ni2++) {
                    mma_f16(acc[mi][2 * ni2],     af[mi], bf[ni2]);
                    mma_f16(acc[mi][2 * ni2 + 1], af[mi], bf[ni2] + 2);
                }
        }
    }

    #pragma unroll
    for (int mi = 0; mi < 4; mi++) {
        #pragma unroll
        for (int h = 0; h < 2; h++) {
            int row = m0 + wm + mi * 16 + (lane >> 2) + h * 8;
            #pragma unroll
            for (int ni = 0; ni < 4; ni++) {
                int col = n0 + wn + ni * 8 + (lane & 3) * 2;
                float2 bb = *reinterpret_cast<const float2*>(bias + col);
                float vx = acc[mi][ni][h * 2 + 0] + bb.x;
                float vy = acc[mi][ni][h * 2 + 1] + bb.y;
                if (MODE == 1) {
                    float2 rv = *reinterpret_cast<const float2*>(
                        res + (size_t)row * N + col);
                    vx += rv.x; vy += rv.y;
                }
                if (MODE == 2) { vx = fmaxf(vx, 0.f); vy = fmaxf(vy, 0.f); }
                if (MODE == 2 || MODE == 3) {
                    *reinterpret_cast<uint32_t*>(Oh + (size_t)row * N + col) =
                        h2u(__floats2half2_rn(vx, vy));
                } else {
                    *reinterpret_cast<float2*>(C + (size_t)row * N + col) =
                        make_float2(vx, vy);
                }
            }
        }
    }
}

// ---------------- fp16 tensor-core causal flash attention ------------------
// grid (SEQ/128, NH, BATCH), 256 threads (8 warps x 16 query rows), 2 CTA/SM.
// 3-stage KV ring -> ONE __syncthreads per tile: the fill of stage kb+2
// lands in ring slot (kb-1)%3, which all warps finished consuming before
// passing the barrier for tile kb.
#define ATTN_STAGES 3
#define ATTN_SMEM (ATTN_STAGES * 16384)

__global__ __launch_bounds__(256, 2) void attn_mma(
    const __half* __restrict__ qkv, __half* __restrict__ y)
{
    extern __shared__ char smem[];
    const uint32_t sb = smem_u32(smem);

    int qt = gridDim.x - 1 - blockIdx.x;   // heavy blocks first
    int h = blockIdx.y, b = blockIdx.z;
    int q0 = qt * 128;
    int tid = threadIdx.x, wid = tid >> 5, lane = tid & 31;
    const __half* base = qkv + (size_t)b * SEQ * 3 * DIM;
    const int r = lane >> 2, cb = (lane & 3) * 2;
    const __half2 QSC2 = __float2half2_rn(0.1803368801f);  // 0.125*log2(e)
    const uint32_t ONES[2] = {0x3C003C00u, 0x3C003C00u};   // half2(1,1) x2
    const __half NEGINF = __ushort_as_half(0xFC00u);

    // Q fragments (fp16 A-operand layout), softmax scale pre-folded
    uint32_t qf[4][4];
    #pragma unroll
    for (int ks = 0; ks < 4; ks++) {
        #pragma unroll
        for (int fr = 0; fr < 4; fr++) {
            int row = q0 + wid * 16 + r + (fr & 1) * 8;
            int col = ks * 16 + cb + (fr >> 1) * 8;
            __half2 v = *reinterpret_cast<const __half2*>(
                base + (size_t)row * 3 * DIM + h * HD + col);
            qf[ks][fr] = h2u(__hmul2(v, QSC2));
        }
    }

    auto issueKV = [&](int kb) {
        uint32_t stg = sb + (uint32_t)(kb % ATTN_STAGES) * 16384;
        #pragma unroll
        for (int p = 0; p < 4; p++) {
            int idx = p * 256 + tid;
            int op = idx >> 9, rem = idx & 511;
            int row = rem >> 3, c = rem & 7;
            const __half* src = base + (size_t)(kb * 64 + row) * 3 * DIM
                              + (op ? 2 * DIM : DIM) + h * HD + c * 8;
            cp16(stg + op * 8192 + SWZ128((uint32_t)(row * 128 + c * 16)), src);
        }
        asm volatile("cp.async.commit_group;" ::: "memory");
    };

    float m0 = -1e30f, m1 = -1e30f;
    float lacc[4] = {0.f, 0.f, 0.f, 0.f};
    float o[8][4];
    #pragma unroll
    for (int ni = 0; ni < 8; ni++)
        #pragma unroll
        for (int c = 0; c < 4; c++) o[ni][c] = 0.f;

    const int last = 2 * qt + 1;
    issueKV(0);
    if (last >= 1) issueKV(1);
    for (int kb = 0; kb <= last; kb++) {
        if (kb < last) { asm volatile("cp.async.wait_group 1;" ::: "memory"); }
        else           { asm volatile("cp.async.wait_group 0;" ::: "memory"); }
        __syncthreads();   // fill(kb) visible; all warps done with tile kb-1
        if (kb + 2 <= last) issueKV(kb + 2);   // slot (kb-1)%3: safe

        // warps whose rows are entirely above this key tile: nothing to do
        bool fullmask = (kb * 64 > q0 + wid * 16 + 15);
        if (!fullmask) {
            uint32_t sK = sb + (uint32_t)(kb % ATTN_STAGES) * 16384;
            uint32_t sV = sK + 8192;

            // S = Q K^T, fp16 accumulators (c[0]=row r, c[1]=row r+8)
            uint32_t s16[8][2];
            #pragma unroll
            for (int ni = 0; ni < 8; ni++) { s16[ni][0] = 0; s16[ni][1] = 0; }
            #pragma unroll
            for (int ks = 0; ks < 4; ks++) {
                #pragma unroll
                for (int ni2 = 0; ni2 < 4; ni2++) {
                    int krow = ni2 * 16 + ((lane & 16) >> 1) + (lane & 7);
                    int kcolb = ks * 32 + (lane & 8) * 2;
                    uint32_t kf[4];
                    ldsm_x4(kf, sK + SWZ128((uint32_t)(krow * 128 + kcolb)));
                    mma_f16h(s16[2 * ni2],     qf[ks], kf);
                    mma_f16h(s16[2 * ni2 + 1], qf[ks], kf + 2);
                }
            }

            // causal mask (diagonal-crossing tiles only)
            if (kb * 64 + 63 > q0 + wid * 16) {
                int rg0 = q0 + wid * 16 + r, rg1 = rg0 + 8;
                int cgb = kb * 64;
                #pragma unroll
                for (int ni = 0; ni < 8; ni++) {
                    int c0 = cgb + ni * 8 + cb;
                    __half2 v0 = u2h(s16[ni][0]);
                    __half2 v1 = u2h(s16[ni][1]);
                    if (c0     > rg0) v0.x = NEGINF;
                    if (c0 + 1 > rg0) v0.y = NEGINF;
                    if (c0     > rg1) v1.x = NEGINF;
                    if (c0 + 1 > rg1) v1.y = NEGINF;
                    s16[ni][0] = h2u(v0);
                    s16[ni][1] = h2u(v1);
                }
            }

            // row max via half2 SIMD + quad shuffle
            __half2 mx0 = u2h(s16[0][0]), mx1 = u2h(s16[0][1]);
            #pragma unroll
            for (int ni = 1; ni < 8; ni++) {
                mx0 = __hmax2(mx0, u2h(s16[ni][0]));
                mx1 = __hmax2(mx1, u2h(s16[ni][1]));
            }
            uint32_t x0 = h2u(mx0), x1 = h2u(mx1);
            x0 = h2u(__hmax2(u2h(x0), u2h(__shfl_xor_sync(0xffffffffu, x0, 1))));
            x0 = h2u(__hmax2(u2h(x0), u2h(__shfl_xor_sync(0xffffffffu, x0, 2))));
            x1 = h2u(__hmax2(u2h(x1), u2h(__shfl_xor_sync(0xffffffffu, x1, 1))));
            x1 = h2u(__hmax2(u2h(x1), u2h(__shfl_xor_sync(0xffffffffu, x1, 2))));
            float nm0 = fmaxf(__half2float(u2h(x0).x), __half2float(u2h(x0).y));
            float nm1 = fmaxf(__half2float(u2h(x1).x), __half2float(u2h(x1).y));
            nm0 = fmaxf(nm0, m0);
            nm1 = fmaxf(nm1, m1);

            // rescale only when some lane saw a new max (warp-uniform branch)
            bool changed = !__all_sync(0xffffffffu, (nm0 == m0) & (nm1 == m1));
            if (changed) {
                float sc0 = ex2(m0 - nm0), sc1 = ex2(m1 - nm1);
                #pragma unroll
                for (int ni = 0; ni < 8; ni++) {
                    o[ni][0] *= sc0; o[ni][1] *= sc0;
                    o[ni][2] *= sc1; o[ni][3] *= sc1;
                }
                lacc[0] *= sc0; lacc[2] *= sc1;
            }
            m0 = nm0; m1 = nm1;

            // P = exp2(S - m), pure half2 (regs already in A-fragment layout)
            __half2 nm0h = __float2half2_rn(nm0);
            __half2 nm1h = __float2half2_rn(nm1);
            uint32_t ph[4][4];
            #pragma unroll
            for (int t = 0; t < 4; t++) {
                ph[t][0] = h2u(h2exp2(__hsub2(u2h(s16[2 * t][0]),     nm0h)));
                ph[t][1] = h2u(h2exp2(__hsub2(u2h(s16[2 * t][1]),     nm1h)));
                ph[t][2] = h2u(h2exp2(__hsub2(u2h(s16[2 * t + 1][0]), nm0h)));
                ph[t][3] = h2u(h2exp2(__hsub2(u2h(s16[2 * t + 1][1]), nm1h)));
            }

            // O += P V ; l += P 1
            #pragma unroll
            for (int t = 0; t < 4; t++) {
                mma_f16(lacc, ph[t], ONES);
                #pragma unroll
                for (int ni2 = 0; ni2 < 4; ni2++) {
                    int vrow = t * 16 + (lane & 15);
                    int vcolb = ni2 * 32 + (lane & 16);
                    uint32_t vf[4];
                    ldsm_x4t(vf, sV + SWZ128((uint32_t)(vrow * 128 + vcolb)));
                    mma_f16(o[2 * ni2],     ph[t], vf);
                    mma_f16(o[2 * ni2 + 1], ph[t], vf + 2);
                }
            }
        }
    }

    // normalize + fp16 output
    float il0 = 1.0f / lacc[0], il1 = 1.0f / lacc[2];
    int row0 = b * SEQ + q0 + wid * 16 + r;
    #pragma unroll
    for (int ni = 0; ni < 8; ni++) {
        int col = h * HD + ni * 8 + cb;
        *reinterpret_cast<uint32_t*>(y + (size_t)row0 * DIM + col) =
            h2u(__floats2half2_rn(o[ni][0] * il0, o[ni][1] * il0));
        *reinterpret_cast<uint32_t*>(y + (size_t)(row0 + 8) * DIM + col) =
            h2u(__floats2half2_rn(o[ni][2] * il1, o[ni][3] * il1));
    }
}

// ---------------- launch ---------------------------------------------------
extern "C" void kernel_launch(void* const* d_in, const int* in_sizes, int n_in,
                              void* d_out, int out_size)
{
    const float* x      = (const float*)d_in[0];
    const float* ln1_g  = (const float*)d_in[1];
    const float* ln1_b  = (const float*)d_in[2];
    const float* ln2_g  = (const float*)d_in[3];
    const float* ln2_b  = (const float*)d_in[4];
    const float* W_qkv  = (const float*)d_in[5];
    const float* b_qkv  = (const float*)d_in[6];
    const float* W_proj = (const float*)d_in[7];
    const float* b_proj = (const float*)d_in[8];
    const float* W_fc   = (const float*)d_in[9];
    const float* b_fc   = (const float*)d_in[10];
    const float* W_out  = (const float*)d_in[11];
    const float* b_out  = (const float*)d_in[12];
    float* out = (float*)d_out;

    float *x1;
    __half *qkv, *h, *y, *act, *wq, *wp, *wf, *wo;
    cudaGetSymbolAddress((void**)&x1,  g_x1);
    cudaGetSymbolAddress((void**)&qkv, g_qkv);
    cudaGetSymbolAddress((void**)&h,   g_h);
    cudaGetSymbolAddress((void**)&y,   g_y);
    cudaGetSymbolAddress((void**)&act, g_act);
    cudaGetSymbolAddress((void**)&wq,  g_wq);
    cudaGetSymbolAddress((void**)&wp,  g_wp);
    cudaGetSymbolAddress((void**)&wf,  g_wf);
    cudaGetSymbolAddress((void**)&wo,  g_wo);

    cudaFuncSetAttribute(gemm_f16<1>,
        cudaFuncAttributeMaxDynamicSharedMemorySize, GEMM_SMEM);
    cudaFuncSetAttribute(gemm_f16<2>,
        cudaFuncAttributeMaxDynamicSharedMemorySize, GEMM_SMEM);
    cudaFuncSetAttribute(gemm_f16<3>,
        cudaFuncAttributeMaxDynamicSharedMemorySize, GEMM_SMEM);
    cudaFuncSetAttribute(attn_mma,
        cudaFuncAttributeMaxDynamicSharedMemorySize, ATTN_SMEM);

    // 0) all weight transposes in one launch
    transT_all<<<12288, 256>>>(W_qkv, W_proj, W_fc, W_out, wq, wp, wf, wo);

    // 1) LN1 -> h (fp16)
    ln_kernel<<<NTOK, 256>>>(x, ln1_g, ln1_b, h);

    // 2) qkv = h @ W_qkv + b_qkv (fp16 out)
    gemm_f16<3><<<dim3(3 * DIM / 128, NTOK / 128), 256, GEMM_SMEM>>>(
        h, wq, b_qkv, nullptr, nullptr, qkv, NTOK, 3 * DIM, DIM);

    // 3) attention -> y (fp16)
    attn_mma<<<dim3(SEQ / 128, NH, BATCH), 256, ATTN_SMEM>>>(qkv, y);

    // 4) x1 = x + y @ W_proj + b_proj
    gemm_f16<1><<<dim3(DIM / 128, NTOK / 128), 256, GEMM_SMEM>>>(
        y, wp, b_proj, x, x1, nullptr, NTOK, DIM, DIM);

    // 5) LN2 -> h (fp16)
    ln_kernel<<<NTOK, 256>>>(x1, ln2_g, ln2_b, h);

    // 6) act = relu(h @ W_fc + b_fc) (fp16)
    gemm_f16<2><<<dim3(4 * DIM / 128, NTOK / 128), 256, GEMM_SMEM>>>(
        h, wf, b_fc, nullptr, nullptr, act, NTOK, 4 * DIM, DIM);

    // 7) out = x1 + act @ W_out + b_out
    gemm_f16<1><<<dim3(DIM / 128, NTOK / 128), 256, GEMM_SMEM>>>(
        act, wo, b_out, x1, out, nullptr, NTOK, DIM, 4 * DIM);
}

// round 15
// speedup vs baseline: 8.2200x; 1.0413x over previous
#include <cuda_runtime.h>
#include <cuda_fp16.h>
#include <math.h>
#include <stdint.h>

#define BATCH 2
#define SEQ   2048
#define DIM   1024
#define NH    16
#define HD    64
#define NTOK  (BATCH * SEQ)   // 4096

// ---------------- scratch (device globals) ---------------------------------
__device__ float  g_x1 [(size_t)NTOK * DIM];       // residual after proj
__device__ __half g_qkv[(size_t)NTOK * 3 * DIM];   // qkv fp16
__device__ __half g_h  [(size_t)NTOK * DIM];       // LN out fp16
__device__ __half g_y  [(size_t)NTOK * DIM];       // attn out fp16
__device__ __half g_act[(size_t)NTOK * 4 * DIM];   // relu(fc) fp16
__device__ __half g_wq [(size_t)3 * DIM * DIM];    // W_qkv^T fp16
__device__ __half g_wp [(size_t)DIM * DIM];        // W_proj^T fp16
__device__ __half g_wf [(size_t)4 * DIM * DIM];    // W_fc^T fp16
__device__ __half g_wo [(size_t)4 * DIM * DIM];    // W_out^T fp16

// ======================= helpers ===========================================
__device__ __forceinline__ uint32_t smem_u32(const void* p) {
    uint32_t a;
    asm("{ .reg .u64 t; cvta.to.shared.u64 t, %1; cvt.u32.u64 %0, t; }"
        : "=r"(a) : "l"(p));
    return a;
}
#define SWZ128(o) ((o) ^ (((o) >> 3) & 0x70))

__device__ __forceinline__ void ldsm_x4(uint32_t* r, uint32_t addr) {
    asm volatile("ldmatrix.sync.aligned.m8n8.x4.shared.b16 {%0,%1,%2,%3}, [%4];"
                 : "=r"(r[0]), "=r"(r[1]), "=r"(r[2]), "=r"(r[3]) : "r"(addr));
}
__device__ __forceinline__ void ldsm_x4t(uint32_t* r, uint32_t addr) {
    asm volatile("ldmatrix.sync.aligned.m8n8.x4.trans.shared.b16 {%0,%1,%2,%3}, [%4];"
                 : "=r"(r[0]), "=r"(r[1]), "=r"(r[2]), "=r"(r[3]) : "r"(addr));
}
__device__ __forceinline__ void mma_f16(float* c, const uint32_t* a,
                                        const uint32_t* b) {
    asm volatile(
        "mma.sync.aligned.m16n8k16.row.col.f32.f16.f16.f32 "
        "{%0,%1,%2,%3}, {%4,%5,%6,%7}, {%8,%9}, {%0,%1,%2,%3};"
        : "+f"(c[0]), "+f"(c[1]), "+f"(c[2]), "+f"(c[3])
        : "r"(a[0]), "r"(a[1]), "r"(a[2]), "r"(a[3]), "r"(b[0]), "r"(b[1]));
}
// fp16-accumulator variant (2-reg D) for the QK logits
__device__ __forceinline__ void mma_f16h(uint32_t* c, const uint32_t* a,
                                         const uint32_t* b) {
    asm volatile(
        "mma.sync.aligned.m16n8k16.row.col.f16.f16.f16.f16 "
        "{%0,%1}, {%2,%3,%4,%5}, {%6,%7}, {%0,%1};"
        : "+r"(c[0]), "+r"(c[1])
        : "r"(a[0]), "r"(a[1]), "r"(a[2]), "r"(a[3]), "r"(b[0]), "r"(b[1]));
}
__device__ __forceinline__ void cp16(uint32_t daddr, const void* saddr) {
    asm volatile("cp.async.cg.shared.global [%0], [%1], 16;"
                 :: "r"(daddr), "l"(saddr));
}
__device__ __forceinline__ float ex2(float x) {
    float y;
    asm("ex2.approx.f32 %0, %1;" : "=f"(y) : "f"(x));
    return y;
}
__device__ __forceinline__ uint32_t h2u(__half2 v) {
    return *reinterpret_cast<uint32_t*>(&v);
}
__device__ __forceinline__ __half2 u2h(uint32_t v) {
    return *reinterpret_cast<__half2*>(&v);
}

// ---------------- LayerNorm body (fp16 out) --------------------------------
__device__ __forceinline__ void ln_body(
    const float* __restrict__ x, const float* __restrict__ gamma,
    const float* __restrict__ beta, __half* __restrict__ out, int row)
{
    int tid = threadIdx.x;
    const float4* xr = reinterpret_cast<const float4*>(x + (size_t)row * DIM);
    float4 v = xr[tid];
    float s1 = v.x + v.y + v.z + v.w;
    float s2 = v.x * v.x + v.y * v.y + v.z * v.z + v.w * v.w;
    #pragma unroll
    for (int o = 16; o > 0; o >>= 1) {
        s1 += __shfl_xor_sync(0xffffffffu, s1, o);
        s2 += __shfl_xor_sync(0xffffffffu, s2, o);
    }
    __shared__ float sh1[8], sh2[8];
    int w = tid >> 5, l = tid & 31;
    if (l == 0) { sh1[w] = s1; sh2[w] = s2; }
    __syncthreads();
    s1 = 0.f; s2 = 0.f;
    #pragma unroll
    for (int i = 0; i < 8; i++) { s1 += sh1[i]; s2 += sh2[i]; }
    float mu  = s1 * (1.0f / DIM);
    float var = s2 * (1.0f / DIM) - mu * mu;
    float r   = rsqrtf(var + 1e-5f);
    float4 gv = reinterpret_cast<const float4*>(gamma)[tid];
    float4 bv = reinterpret_cast<const float4*>(beta)[tid];
    uint2 u;
    u.x = h2u(__floats2half2_rn((v.x - mu) * r * gv.x + bv.x,
                                (v.y - mu) * r * gv.y + bv.y));
    u.y = h2u(__floats2half2_rn((v.z - mu) * r * gv.z + bv.z,
                                (v.w - mu) * r * gv.w + bv.w));
    *reinterpret_cast<uint2*>(out + (size_t)row * DIM + tid * 4) = u;
}

__global__ __launch_bounds__(256) void ln_kernel(
    const float* __restrict__ x, const float* __restrict__ gamma,
    const float* __restrict__ beta, __half* __restrict__ out)
{
    ln_body(x, gamma, beta, out, blockIdx.x);
}

// ---------------- prep: 4 weight transposes + LN1, one launch --------------
// blocks [0,12288): transpose tiles; [12288, 12288+NTOK): LN1 rows.
__global__ __launch_bounds__(256) void prep_kernel(
    const float* __restrict__ W0, const float* __restrict__ W1,
    const float* __restrict__ W2, const float* __restrict__ W3,
    __half* __restrict__ O0, __half* __restrict__ O1,
    __half* __restrict__ O2, __half* __restrict__ O3,
    const float* __restrict__ x, const float* __restrict__ ln1_g,
    const float* __restrict__ ln1_b, __half* __restrict__ h)
{
    int t = blockIdx.x;
    if (t >= 12288) {
        ln_body(x, ln1_g, ln1_b, h, t - 12288);
        return;
    }
    const float* in; __half* out; int R, C;
    if (t < 3072)      { in = W0; out = O0; R = DIM;     C = 3 * DIM; }
    else if (t < 4096) { in = W1; out = O1; R = DIM;     C = DIM;     t -= 3072; }
    else if (t < 8192) { in = W2; out = O2; R = DIM;     C = 4 * DIM; t -= 4096; }
    else               { in = W3; out = O3; R = 4 * DIM; C = DIM;     t -= 8192; }
    int tilesX = C >> 5;
    int bx = t % tilesX, by = t / tilesX;

    __shared__ float tt[32][33];
    int tx = threadIdx.x & 31, ty = threadIdx.x >> 5;
    int x0 = bx * 32 + tx;
    #pragma unroll
    for (int j = 0; j < 32; j += 8)
        tt[ty + j][tx] = in[(size_t)(by * 32 + ty + j) * C + x0];
    __syncthreads();
    #pragma unroll
    for (int j = 0; j < 32; j += 8) {
        size_t idx = (size_t)(bx * 32 + ty + j) * R + by * 32 + tx;
        out[idx] = __float2half(tt[tx][ty + j]);
    }
}

// ---------------- fp16 GEMM (3-stage cp.async, 128x128x64, 2 CTA/SM) -------
#define STAGE_BYTES 32768
#define GEMM_STAGES 3
#define GEMM_SMEM   (GEMM_STAGES * STAGE_BYTES)

template<int MODE>   // 0: fp32+bias; 1: fp32+bias+res; 2: fp16 relu; 3: fp16
__global__ __launch_bounds__(256, 2) void gemm_f16(
    const __half* __restrict__ A, const __half* __restrict__ B,
    const float* __restrict__ bias, const float* __restrict__ res,
    float* __restrict__ C, __half* __restrict__ Oh, int M, int N, int K)
{
    extern __shared__ char smem[];
    const uint32_t sbase = smem_u32(smem);
    const int tid = threadIdx.x;
    const int wid = tid >> 5, lane = tid & 31;
    const int m0 = blockIdx.y * 128, n0 = blockIdx.x * 128;
    const int wm = (wid & 1) * 64;
    const int wn = (wid >> 1) * 32;

    float acc[4][4][4];
    #pragma unroll
    for (int a = 0; a < 4; a++)
        #pragma unroll
        for (int b = 0; b < 4; b++)
            #pragma unroll
            for (int c = 0; c < 4; c++) acc[a][b][c] = 0.f;

    const __half* Ab = A + (size_t)m0 * K;
    const __half* Bb = B + (size_t)n0 * K;
    const int row_l = tid >> 3, c_l = tid & 7;

    auto issue = [&](int i) {
        int k0 = i << 6;
        uint32_t st = sbase + (uint32_t)(i % GEMM_STAGES) * STAGE_BYTES;
        #pragma unroll
        for (int op = 0; op < 2; op++) {
            const __half* src = (op ? Bb : Ab) + k0;
            uint32_t dst = st + op * 16384;
            #pragma unroll
            for (int p = 0; p < 4; p++) {
                int row = row_l + p * 32;
                cp16(dst + SWZ128((uint32_t)(row * 128 + c_l * 16)),
                     src + (size_t)row * K + c_l * 8);
            }
        }
        asm volatile("cp.async.commit_group;" ::: "memory");
    };

    const int NC = K >> 6;
    issue(0); issue(1);
    for (int i = 0; i < NC; i++) {
        if (i + 1 < NC) { asm volatile("cp.async.wait_group 1;" ::: "memory"); }
        else            { asm volatile("cp.async.wait_group 0;" ::: "memory"); }
        __syncthreads();
        if (i + 2 < NC) issue(i + 2);

        uint32_t st = sbase + (uint32_t)(i % GEMM_STAGES) * STAGE_BYTES;
        uint32_t sA = st, sB = st + 16384;

        #pragma unroll
        for (int ks = 0; ks < 4; ks++) {
            uint32_t af[4][4];
            #pragma unroll
            for (int mi = 0; mi < 4; mi++) {
                int row = wm + mi * 16 + (lane & 15);
                int colb = ks * 32 + (lane >> 4) * 16;
                ldsm_x4(af[mi], sA + SWZ128((uint32_t)(row * 128 + colb)));
            }
            uint32_t bf[2][4];
            #pragma unroll
            for (int ni2 = 0; ni2 < 2; ni2++) {
                int row = wn + ni2 * 16 + ((lane & 16) >> 1) + (lane & 7);
                int colb = ks * 32 + (lane & 8) * 2;
                ldsm_x4(bf[ni2], sB + SWZ128((uint32_t)(row * 128 + colb)));
            }
            #pragma unroll
            for (int mi = 0; mi < 4; mi++)
                #pragma unroll
                for (int ni2 = 0; ni2 < 2; ni2++) {
                    mma_f16(acc[mi][2 * ni2],     af[mi], bf[ni2]);
                    mma_f16(acc[mi][2 * ni2 + 1], af[mi], bf[ni2] + 2);
                }
        }
    }

    #pragma unroll
    for (int mi = 0; mi < 4; mi++) {
        #pragma unroll
        for (int h = 0; h < 2; h++) {
            int row = m0 + wm + mi * 16 + (lane >> 2) + h * 8;
            #pragma unroll
            for (int ni = 0; ni < 4; ni++) {
                int col = n0 + wn + ni * 8 + (lane & 3) * 2;
                float2 bb = *reinterpret_cast<const float2*>(bias + col);
                float vx = acc[mi][ni][h * 2 + 0] + bb.x;
                float vy = acc[mi][ni][h * 2 + 1] + bb.y;
                if (MODE == 1) {
                    float2 rv = *reinterpret_cast<const float2*>(
                        res + (size_t)row * N + col);
                    vx += rv.x; vy += rv.y;
                }
                if (MODE == 2) { vx = fmaxf(vx, 0.f); vy = fmaxf(vy, 0.f); }
                if (MODE == 2 || MODE == 3) {
                    *reinterpret_cast<uint32_t*>(Oh + (size_t)row * N + col) =
                        h2u(__floats2half2_rn(vx, vy));
                } else {
                    *reinterpret_cast<float2*>(C + (size_t)row * N + col) =
                        make_float2(vx, vy);
                }
            }
        }
    }
}

// ---------------- fp16 tensor-core causal flash attention ------------------
// grid (SEQ/64, NH, BATCH), 128 threads (4 warps x 16 query rows), 4 CTA/SM.
// Two-stage KV double buffer (round-13 barrier scheme). Smaller barrier
// groups + 4 independent CTAs/SM interleave softmax and MMA phases.
#define ATTN_SMEM (2 * 16384)   // 2 stages x (K 8KB + V 8KB)

__global__ __launch_bounds__(128, 4) void attn_mma(
    const __half* __restrict__ qkv, __half* __restrict__ y)
{
    extern __shared__ char smem[];
    const uint32_t sb = smem_u32(smem);

    int qt = gridDim.x - 1 - blockIdx.x;   // heavy blocks first
    int h = blockIdx.y, b = blockIdx.z;
    int q0 = qt * 64;
    int tid = threadIdx.x, wid = tid >> 5, lane = tid & 31;
    const __half* base = qkv + (size_t)b * SEQ * 3 * DIM;
    const int r = lane >> 2, cb = (lane & 3) * 2;
    const __half2 QSC2 = __float2half2_rn(0.1803368801f);  // 0.125*log2(e)
    const uint32_t ONES[2] = {0x3C003C00u, 0x3C003C00u};   // half2(1,1) x2
    const __half NEGINF = __ushort_as_half(0xFC00u);

    // Q fragments (fp16 A-operand layout), softmax scale pre-folded
    uint32_t qf[4][4];
    #pragma unroll
    for (int ks = 0; ks < 4; ks++) {
        #pragma unroll
        for (int fr = 0; fr < 4; fr++) {
            int row = q0 + wid * 16 + r + (fr & 1) * 8;
            int col = ks * 16 + cb + (fr >> 1) * 8;
            __half2 v = *reinterpret_cast<const __half2*>(
                base + (size_t)row * 3 * DIM + h * HD + col);
            qf[ks][fr] = h2u(__hmul2(v, QSC2));
        }
    }

    auto issueKV = [&](int kb) {
        uint32_t stg = sb + (uint32_t)(kb & 1) * 16384;
        #pragma unroll
        for (int p = 0; p < 8; p++) {
            int idx = p * 128 + tid;              // 0..1023
            int op = idx >> 9, rem = idx & 511;
            int row = rem >> 3, c = rem & 7;
            const __half* src = base + (size_t)(kb * 64 + row) * 3 * DIM
                              + (op ? 2 * DIM : DIM) + h * HD + c * 8;
            cp16(stg + op * 8192 + SWZ128((uint32_t)(row * 128 + c * 16)), src);
        }
        asm volatile("cp.async.commit_group;" ::: "memory");
    };

    float m0 = -1e30f, m1 = -1e30f;
    float lacc[4] = {0.f, 0.f, 0.f, 0.f};
    float o[8][4];
    #pragma unroll
    for (int ni = 0; ni < 8; ni++)
        #pragma unroll
        for (int c = 0; c < 4; c++) o[ni][c] = 0.f;

    const int last = qt;
    issueKV(0);
    for (int kb = 0; kb <= last; kb++) {
        asm volatile("cp.async.wait_group 0;" ::: "memory");
        __syncthreads();   // buffer kb ready; all warps done with buffer kb-1
        if (kb < last) issueKV(kb + 1);   // overlaps with compute below

        uint32_t sK = sb + (uint32_t)(kb & 1) * 16384;
        uint32_t sV = sK + 8192;

        // S = Q K^T, fp16 accumulators (c[0]=row r, c[1]=row r+8)
        uint32_t s16[8][2];
        #pragma unroll
        for (int ni = 0; ni < 8; ni++) { s16[ni][0] = 0; s16[ni][1] = 0; }
        #pragma unroll
        for (int ks = 0; ks < 4; ks++) {
            #pragma unroll
            for (int ni2 = 0; ni2 < 4; ni2++) {
                int krow = ni2 * 16 + ((lane & 16) >> 1) + (lane & 7);
                int kcolb = ks * 32 + (lane & 8) * 2;
                uint32_t kf[4];
                ldsm_x4(kf, sK + SWZ128((uint32_t)(krow * 128 + kcolb)));
                mma_f16h(s16[2 * ni2],     qf[ks], kf);
                mma_f16h(s16[2 * ni2 + 1], qf[ks], kf + 2);
            }
        }

        // causal mask (diagonal tile only)
        if (kb == last) {
            int rg0 = q0 + wid * 16 + r, rg1 = rg0 + 8;
            int cgb = kb * 64;
            #pragma unroll
            for (int ni = 0; ni < 8; ni++) {
                int c0 = cgb + ni * 8 + cb;
                __half2 v0 = u2h(s16[ni][0]);
                __half2 v1 = u2h(s16[ni][1]);
                if (c0     > rg0) v0.x = NEGINF;
                if (c0 + 1 > rg0) v0.y = NEGINF;
                if (c0     > rg1) v1.x = NEGINF;
                if (c0 + 1 > rg1) v1.y = NEGINF;
                s16[ni][0] = h2u(v0);
                s16[ni][1] = h2u(v1);
            }
        }

        // row max via half2 SIMD + quad shuffle
        __half2 mx0 = u2h(s16[0][0]), mx1 = u2h(s16[0][1]);
        #pragma unroll
        for (int ni = 1; ni < 8; ni++) {
            mx0 = __hmax2(mx0, u2h(s16[ni][0]));
            mx1 = __hmax2(mx1, u2h(s16[ni][1]));
        }
        uint32_t x0 = h2u(mx0), x1 = h2u(mx1);
        x0 = h2u(__hmax2(u2h(x0), u2h(__shfl_xor_sync(0xffffffffu, x0, 1))));
        x0 = h2u(__hmax2(u2h(x0), u2h(__shfl_xor_sync(0xffffffffu, x0, 2))));
        x1 = h2u(__hmax2(u2h(x1), u2h(__shfl_xor_sync(0xffffffffu, x1, 1))));
        x1 = h2u(__hmax2(u2h(x1), u2h(__shfl_xor_sync(0xffffffffu, x1, 2))));
        float nm0 = fmaxf(__half2float(u2h(x0).x), __half2float(u2h(x0).y));
        float nm1 = fmaxf(__half2float(u2h(x1).x), __half2float(u2h(x1).y));
        nm0 = fmaxf(nm0, m0);
        nm1 = fmaxf(nm1, m1);

        // rescale only when some lane saw a new max (warp-uniform branch)
        bool changed = !__all_sync(0xffffffffu, (nm0 == m0) & (nm1 == m1));
        if (changed) {
            float sc0 = ex2(m0 - nm0), sc1 = ex2(m1 - nm1);
            #pragma unroll
            for (int ni = 0; ni < 8; ni++) {
                o[ni][0] *= sc0; o[ni][1] *= sc0;
                o[ni][2] *= sc1; o[ni][3] *= sc1;
            }
            lacc[0] *= sc0; lacc[2] *= sc1;
        }
        m0 = nm0; m1 = nm1;

        // P = exp2(S - m), pure half2 (regs already in A-fragment layout)
        __half2 nm0h = __float2half2_rn(nm0);
        __half2 nm1h = __float2half2_rn(nm1);
        uint32_t ph[4][4];
        #pragma unroll
        for (int t = 0; t < 4; t++) {
            ph[t][0] = h2u(h2exp2(__hsub2(u2h(s16[2 * t][0]),     nm0h)));
            ph[t][1] = h2u(h2exp2(__hsub2(u2h(s16[2 * t][1]),     nm1h)));
            ph[t][2] = h2u(h2exp2(__hsub2(u2h(s16[2 * t + 1][0]), nm0h)));
            ph[t][3] = h2u(h2exp2(__hsub2(u2h(s16[2 * t + 1][1]), nm1h)));
        }

        // O += P V ; l += P 1
        #pragma unroll
        for (int t = 0; t < 4; t++) {
            mma_f16(lacc, ph[t], ONES);
            #pragma unroll
            for (int ni2 = 0; ni2 < 4; ni2++) {
                int vrow = t * 16 + (lane & 15);
                int vcolb = ni2 * 32 + (lane & 16);
                uint32_t vf[4];
                ldsm_x4t(vf, sV + SWZ128((uint32_t)(vrow * 128 + vcolb)));
                mma_f16(o[2 * ni2],     ph[t], vf);
                mma_f16(o[2 * ni2 + 1], ph[t], vf + 2);
            }
        }
        __syncthreads();   // all warps done with buffer kb before next fill
    }

    // normalize + fp16 output
    float il0 = 1.0f / lacc[0], il1 = 1.0f / lacc[2];
    int row0 = b * SEQ + q0 + wid * 16 + r;
    #pragma unroll
    for (int ni = 0; ni < 8; ni++) {
        int col = h * HD + ni * 8 + cb;
        *reinterpret_cast<uint32_t*>(y + (size_t)row0 * DIM + col) =
            h2u(__floats2half2_rn(o[ni][0] * il0, o[ni][1] * il0));
        *reinterpret_cast<uint32_t*>(y + (size_t)(row0 + 8) * DIM + col) =
            h2u(__floats2half2_rn(o[ni][2] * il1, o[ni][3] * il1));
    }
}

// ---------------- launch ---------------------------------------------------
extern "C" void kernel_launch(void* const* d_in, const int* in_sizes, int n_in,
                              void* d_out, int out_size)
{
    const float* x      = (const float*)d_in[0];
    const float* ln1_g  = (const float*)d_in[1];
    const float* ln1_b  = (const float*)d_in[2];
    const float* ln2_g  = (const float*)d_in[3];
    const float* ln2_b  = (const float*)d_in[4];
    const float* W_qkv  = (const float*)d_in[5];
    const float* b_qkv  = (const float*)d_in[6];
    const float* W_proj = (const float*)d_in[7];
    const float* b_proj = (const float*)d_in[8];
    const float* W_fc   = (const float*)d_in[9];
    const float* b_fc   = (const float*)d_in[10];
    const float* W_out  = (const float*)d_in[11];
    const float* b_out  = (const float*)d_in[12];
    float* out = (float*)d_out;

    float *x1;
    __half *qkv, *h, *y, *act, *wq, *wp, *wf, *wo;
    cudaGetSymbolAddress((void**)&x1,  g_x1);
    cudaGetSymbolAddress((void**)&qkv, g_qkv);
    cudaGetSymbolAddress((void**)&h,   g_h);
    cudaGetSymbolAddress((void**)&y,   g_y);
    cudaGetSymbolAddress((void**)&act, g_act);
    cudaGetSymbolAddress((void**)&wq,  g_wq);
    cudaGetSymbolAddress((void**)&wp,  g_wp);
    cudaGetSymbolAddress((void**)&wf,  g_wf);
    cudaGetSymbolAddress((void**)&wo,  g_wo);

    cudaFuncSetAttribute(gemm_f16<1>,
        cudaFuncAttributeMaxDynamicSharedMemorySize, GEMM_SMEM);
    cudaFuncSetAttribute(gemm_f16<2>,
        cudaFuncAttributeMaxDynamicSharedMemorySize, GEMM_SMEM);
    cudaFuncSetAttribute(gemm_f16<3>,
        cudaFuncAttributeMaxDynamicSharedMemorySize, GEMM_SMEM);
    cudaFuncSetAttribute(attn_mma,
        cudaFuncAttributeMaxDynamicSharedMemorySize, ATTN_SMEM);

    // 0) weight transposes + LN1 fused in one launch
    prep_kernel<<<12288 + NTOK, 256>>>(W_qkv, W_proj, W_fc, W_out,
                                       wq, wp, wf, wo,
                                       x, ln1_g, ln1_b, h);

    // 1) qkv = h @ W_qkv + b_qkv (fp16 out)
    gemm_f16<3><<<dim3(3 * DIM / 128, NTOK / 128), 256, GEMM_SMEM>>>(
        h, wq, b_qkv, nullptr, nullptr, qkv, NTOK, 3 * DIM, DIM);

    // 2) attention -> y (fp16)
    attn_mma<<<dim3(SEQ / 64, NH, BATCH), 128, ATTN_SMEM>>>(qkv, y);

    // 3) x1 = x + y @ W_proj + b_proj
    gemm_f16<1><<<dim3(DIM / 128, NTOK / 128), 256, GEMM_SMEM>>>(
        y, wp, b_proj, x, x1, nullptr, NTOK, DIM, DIM);

    // 4) LN2 -> h (fp16)
    ln_kernel<<<NTOK, 256>>>(x1, ln2_g, ln2_b, h);

    // 5) act = relu(h @ W_fc + b_fc) (fp16)
    gemm_f16<2><<<dim3(4 * DIM / 128, NTOK / 128), 256, GEMM_SMEM>>>(
        h, wf, b_fc, nullptr, nullptr, act, NTOK, 4 * DIM, DIM);

    // 6) out = x1 + act @ W_out + b_out
    gemm_f16<1><<<dim3(DIM / 128, NTOK / 128), 256, GEMM_SMEM>>>(
        act, wo, b_out, x1, out, nullptr, NTOK, DIM, 4 * DIM);
}